// round 5
// baseline (speedup 1.0000x reference)
#include <cuda_runtime.h>
#include <cuda_bf16.h>
#include <math.h>

#define NB 16
#define NCDD 5
#define NHIS 50
#define NS 20
#define NT 41
#define NE 300
#define NF 256
#define NH 16
#define NDV 16
#define NQD 200
#define NSEQ 4000
#define NUROWS 21600
#define MID_BASE 17600
#define NCAT 4352
#define MVAL 164000
#define SCALE_F 0.057735026918962576f

// -------- static device scratch (no allocations) --------
__device__ float g_xu[NUROWS * NF];
__device__ float g_Wcat[NF * NCAT];
__device__ float g_bcat[NCAT];
__device__ float g_qxv[(size_t)NUROWS * NCAT];
__device__ float g_val[(size_t)MVAL * NF];
__device__ float g_kbuf[(size_t)MVAL * NQD];
__device__ float g_rep[(size_t)NSEQ * NF];

// -------- kernel 0: pack [Wq | Wv] -> Wcat[256 x 4352], bias --------
__global__ void prep_kernel(const float* __restrict__ Wq, const float* __restrict__ bq,
                            const float* __restrict__ Wv, const float* __restrict__ bv) {
    int idx = blockIdx.x * 256 + threadIdx.x;
    if (idx < NF * NCAT) {
        int f = idx / NCAT;
        int j = idx - f * NCAT;
        float w;
        if (j < NH * NF) {
            int h = j >> 8, g = j & 255;
            w = Wq[(h * 256 + f) * 256 + g];
        } else {
            int jj = j - NH * NF;
            int h = jj >> 4, d = jj & 15;
            w = Wv[(h * 256 + f) * 16 + d];
        }
        g_Wcat[idx] = w;
    }
    if (idx < NCAT) {
        if (idx < NH * NF) {
            int h = idx >> 8, g = idx & 255;
            g_bcat[idx] = bq[h * 256 + g];
        } else {
            g_bcat[idx] = bv[idx - NH * NF]; // bv folds through softmax (rows sum to 1)
        }
    }
}

// -------- kernel 1: conv1d(k=3, SAME) + ReLU over 21600 unique rows --------
// rows: [0,1600) cdd (bc,t 0..19); [1600,17600) his (bh, t=21+tt); [17600,21600) mid (t=20)
__global__ void __launch_bounds__(256) conv_kernel(const int* __restrict__ cand,
                                                   const int* __restrict__ clk,
                                                   const float* __restrict__ emb,
                                                   const float* __restrict__ cw,
                                                   const float* __restrict__ cb) {
    __shared__ float se[12 * 900];
    __shared__ int st[12][3];
    int row0 = blockIdx.x * 12;
    int tid = threadIdx.x;
    if (tid < 12) {
        int row = row0 + tid;
        int t0, t1, t2;
        if (row < 1600) {
            int bc = row / 20, t = row - bc * 20;
            const int* ct = cand + bc * 20;
            t0 = (t - 1 >= 0) ? ct[t - 1] : -1;   // -1 = zero pad
            t1 = ct[t];
            t2 = (t + 1 < 20) ? ct[t + 1] : 1;    // SEP token id 1
        } else if (row < MID_BASE) {
            int r2 = row - 1600;
            int bh = r2 / 20, tt = r2 - bh * 20;
            const int* ht = clk + bh * 20;
            t0 = (tt == 0) ? 1 : ht[tt - 1];
            t1 = ht[tt];
            t2 = (tt + 1 < 20) ? ht[tt + 1] : -1;
        } else {
            int nn = row - MID_BASE;
            int b = nn / 250, rr = nn - b * 250;
            int c = rr / 50, hh = rr - c * 50;
            t0 = cand[(b * 5 + c) * 20 + 19];
            t1 = 1;
            t2 = clk[(b * 50 + hh) * 20 + 0];
        }
        st[tid][0] = t0; st[tid][1] = t1; st[tid][2] = t2;
    }
    __syncthreads();
    for (int idx = tid; idx < 12 * 900; idx += 256) {
        int r = idx / 900;
        int rem = idx - r * 900;
        int w = rem / 300;
        int e = rem - w * 300;
        int tok = st[r][w];
        se[idx] = (tok < 0) ? 0.f : emb[(size_t)tok * NE + e];
    }
    __syncthreads();
    int f = tid;
    float cbf = cb[f];
    float acc[12];
#pragma unroll
    for (int r = 0; r < 12; ++r) acc[r] = cbf;
    for (int we = 0; we < 900; we += 4) {
        float w0 = cw[(we + 0) * 256 + f];
        float w1 = cw[(we + 1) * 256 + f];
        float w2 = cw[(we + 2) * 256 + f];
        float w3 = cw[(we + 3) * 256 + f];
#pragma unroll
        for (int r = 0; r < 12; ++r) {
            float4 a = *(const float4*)(se + r * 900 + we);
            acc[r] = fmaf(a.x, w0, acc[r]);
            acc[r] = fmaf(a.y, w1, acc[r]);
            acc[r] = fmaf(a.z, w2, acc[r]);
            acc[r] = fmaf(a.w, w3, acc[r]);
        }
    }
#pragma unroll
    for (int r = 0; r < 12; ++r)
        g_xu[(size_t)(row0 + r) * NF + f] = fmaxf(acc[r], 0.f);
}

// -------- tiled fp32 GEMM, K=256: C[MxN] = A[Mx256] @ B[256xN] + bias; ACT 0=none,1=tanh ----
template <int ACT>
__device__ __forceinline__ void gemm_body(const float* __restrict__ A,
                                          const float* __restrict__ Bm,
                                          const float* __restrict__ bias,
                                          float* __restrict__ C, int M, int N) {
    __shared__ float As[16][132];   // k-major
    __shared__ float Bs[16][68];
    int tid = threadIdx.x;
    int ty = tid >> 4, tx = tid & 15;
    int m0 = blockIdx.y * 128;
    int n0 = blockIdx.x * 64;

    float acc[8][4];
#pragma unroll
    for (int i = 0; i < 8; ++i)
#pragma unroll
        for (int j = 0; j < 4; ++j) acc[i][j] = 0.f;

    int arow = tid >> 2;
    int akq = (tid & 3) << 2;
    int brow = tid >> 4;
    int bcol = (tid & 15) << 2;

    for (int k0 = 0; k0 < 256; k0 += 16) {
#pragma unroll
        for (int g = 0; g < 2; ++g) {
            int m = m0 + arow + g * 64;
            float4 v = make_float4(0.f, 0.f, 0.f, 0.f);
            if (m < M) v = *(const float4*)(A + (size_t)m * 256 + k0 + akq);
            As[akq + 0][arow + g * 64] = v.x;
            As[akq + 1][arow + g * 64] = v.y;
            As[akq + 2][arow + g * 64] = v.z;
            As[akq + 3][arow + g * 64] = v.w;
        }
        {
            int n = n0 + bcol;
            float4 v = make_float4(0.f, 0.f, 0.f, 0.f);
            if (n + 3 < N) v = *(const float4*)(Bm + (size_t)(k0 + brow) * N + n);
            *(float4*)(&Bs[brow][bcol]) = v;
        }
        __syncthreads();
#pragma unroll
        for (int kk = 0; kk < 16; ++kk) {
            float4 a0 = *(const float4*)(&As[kk][ty * 8]);
            float4 a1 = *(const float4*)(&As[kk][ty * 8 + 4]);
            float4 b4 = *(const float4*)(&Bs[kk][tx << 2]);
            float av[8] = {a0.x, a0.y, a0.z, a0.w, a1.x, a1.y, a1.z, a1.w};
            float bb[4] = {b4.x, b4.y, b4.z, b4.w};
#pragma unroll
            for (int i = 0; i < 8; ++i)
#pragma unroll
                for (int j = 0; j < 4; ++j) acc[i][j] = fmaf(av[i], bb[j], acc[i][j]);
        }
        __syncthreads();
    }
#pragma unroll
    for (int i = 0; i < 8; ++i) {
        int m = m0 + ty * 8 + i;
        if (m >= M) continue;
#pragma unroll
        for (int j = 0; j < 4; ++j) {
            int n = n0 + (tx << 2) + j;
            if (n >= N) continue;
            float v = acc[i][j] + bias[n];
            if (ACT == 1) v = tanhf(v);
            C[(size_t)m * N + n] = v;
        }
    }
}

__global__ void __launch_bounds__(256) gemm_qxv_kernel() {
    gemm_body<0>(g_xu, g_Wcat, g_bcat, g_qxv, NUROWS, NCAT);
}
__global__ void __launch_bounds__(256) gemm_wordk_kernel(const float* __restrict__ Wk,
                                                         const float* __restrict__ bk) {
    gemm_body<1>(g_val, Wk, bk, g_kbuf, MVAL, NQD);
}

// -------- kernel 3: per (head, seq) self-attention --------
#define DOT4(A, Q, X) \
    A = fmaf(Q.x, X.x, A); A = fmaf(Q.y, X.y, A); A = fmaf(Q.z, X.z, A); A = fmaf(Q.w, X.w, A);

__global__ void __launch_bounds__(256) attn_kernel() {
    extern __shared__ float sm[];
    float* qs = sm;                    // 42*260
    float* xs = sm + 42 * 260;         // 42*260
    float* xvs = sm + 2 * 42 * 260;    // 41*16
    float* scm = xvs + 656;            // 41*44
    __shared__ int rows[41];

    int h = blockIdx.x;
    int n = blockIdx.y;
    int tid = threadIdx.x;

    if (tid < 41) {
        int b = n / 250, rr = n - b * 250;
        int c = rr / 50, hh = rr - c * 50;
        int t = tid, r;
        if (t < 20)       r = (b * 5 + c) * 20 + t;
        else if (t == 20) r = MID_BASE + n;
        else              r = 1600 + (b * 50 + hh) * 20 + (t - 21);
        rows[t] = r;
    }
    __syncthreads();

    for (int idx = tid; idx < 42 * 256; idx += 256) {
        int t = idx >> 8, f = idx & 255;
        float qv = 0.f, xv = 0.f;
        if (t < 41) {
            size_t rb = (size_t)rows[t];
            qv = g_qxv[rb * NCAT + h * 256 + f];
            xv = g_xu[rb * 256 + f];
        }
        qs[t * 260 + f] = qv;
        xs[t * 260 + f] = xv;
    }
    for (int idx = tid; idx < 656; idx += 256) {
        int t = idx >> 4;
        xvs[idx] = g_qxv[(size_t)rows[t] * NCAT + 4096 + h * 16 + (idx & 15)];
    }
    __syncthreads();

    if (tid < 196) {
        int ty = tid / 14, tx = tid - ty * 14;
        float acc[3][3];
#pragma unroll
        for (int i = 0; i < 3; ++i)
#pragma unroll
            for (int j = 0; j < 3; ++j) acc[i][j] = 0.f;
        const float* qp = qs + ty * 260;
        const float* xp = xs + tx * 260;
#pragma unroll 2
        for (int k = 0; k < 256; k += 4) {
            float4 q0 = *(const float4*)(qp + k);
            float4 q1 = *(const float4*)(qp + 14 * 260 + k);
            float4 q2 = *(const float4*)(qp + 28 * 260 + k);
            float4 x0 = *(const float4*)(xp + k);
            float4 x1 = *(const float4*)(xp + 14 * 260 + k);
            float4 x2 = *(const float4*)(xp + 28 * 260 + k);
            DOT4(acc[0][0], q0, x0); DOT4(acc[0][1], q0, x1); DOT4(acc[0][2], q0, x2);
            DOT4(acc[1][0], q1, x0); DOT4(acc[1][1], q1, x1); DOT4(acc[1][2], q1, x2);
            DOT4(acc[2][0], q2, x0); DOT4(acc[2][1], q2, x1); DOT4(acc[2][2], q2, x2);
        }
#pragma unroll
        for (int i = 0; i < 3; ++i)
#pragma unroll
            for (int j = 0; j < 3; ++j) {
                int t = ty + 14 * i, s = tx + 14 * j;
                if (t < 41 && s < 41) scm[t * 44 + s] = acc[i][j] * SCALE_F;
            }
    }
    __syncthreads();

    int warp = tid >> 5, lane = tid & 31;
    for (int t = warp; t < 41; t += 8) {
        float v0 = (lane < 41) ? scm[t * 44 + lane] : -1e30f;
        float v1 = (lane + 32 < 41) ? scm[t * 44 + lane + 32] : -1e30f;
        float m = fmaxf(v0, v1);
#pragma unroll
        for (int o = 16; o; o >>= 1) m = fmaxf(m, __shfl_xor_sync(0xffffffffu, m, o));
        float e0 = (lane < 41) ? __expf(v0 - m) : 0.f;
        float e1 = (lane + 32 < 41) ? __expf(v1 - m) : 0.f;
        float s = e0 + e1;
#pragma unroll
        for (int o = 16; o; o >>= 1) s += __shfl_xor_sync(0xffffffffu, s, o);
        float inv = 1.f / s;
        if (lane < 41) scm[t * 44 + lane] = e0 * inv;
        if (lane + 32 < 41) scm[t * 44 + lane + 32] = e1 * inv;
    }
    __syncthreads();

    if (tid < 656) {
        int t = tid >> 4, d = tid & 15;
        float a = 0.f;
#pragma unroll 8
        for (int s = 0; s < 41; ++s) a = fmaf(scm[t * 44 + s], xvs[s * 16 + d], a);
        g_val[((size_t)n * 41 + t) * 256 + h * 16 + d] = a;
    }
}

// -------- kernel 5: word attention per sequence --------
__global__ void __launch_bounds__(256) word_kernel(const float* __restrict__ qw) {
    __shared__ float sqw[200];
    __shared__ float sl[41];
    int n = blockIdx.x;
    int tid = threadIdx.x;
    if (tid < 200) sqw[tid] = qw[tid];
    __syncthreads();
    int warp = tid >> 5, lane = tid & 31;
    for (int t = warp; t < 41; t += 8) {
        const float* kr = g_kbuf + ((size_t)n * 41 + t) * 200;
        float s = 0.f;
        for (int e = lane; e < 200; e += 32) s = fmaf(kr[e], sqw[e], s);
#pragma unroll
        for (int o = 16; o; o >>= 1) s += __shfl_xor_sync(0xffffffffu, s, o);
        if (lane == 0) sl[t] = s * SCALE_F;
    }
    __syncthreads();
    if (tid < 32) {
        float v0 = (tid < 41) ? sl[tid] : -1e30f;
        float v1 = (tid + 32 < 41) ? sl[tid + 32] : -1e30f;
        float m = fmaxf(v0, v1);
#pragma unroll
        for (int o = 16; o; o >>= 1) m = fmaxf(m, __shfl_xor_sync(0xffffffffu, m, o));
        float e0 = (tid < 41) ? expf(v0 - m) : 0.f;
        float e1 = (tid + 32 < 41) ? expf(v1 - m) : 0.f;
        float s = e0 + e1;
#pragma unroll
        for (int o = 16; o; o >>= 1) s += __shfl_xor_sync(0xffffffffu, s, o);
        float inv = 1.f / s;
        if (tid < 41) sl[tid] = e0 * inv;
        if (tid + 32 < 41) sl[tid + 32] = e1 * inv;
    }
    __syncthreads();
    float acc = 0.f;
    const float* vr = g_val + (size_t)n * 41 * 256 + tid;
#pragma unroll 8
    for (int t = 0; t < 41; ++t) acc = fmaf(sl[t], vr[(size_t)t * 256], acc);
    g_rep[(size_t)n * 256 + tid] = acc;
}

// -------- kernel 6: mean over HIS, rank score, log-softmax over CDD --------
__global__ void __launch_bounds__(256) final_kernel(const float* __restrict__ Wl,
                                                    const float* __restrict__ blp,
                                                    float* __restrict__ out) {
    __shared__ float red[8];
    __shared__ float sc[5];
    int b = blockIdx.x;
    int tid = threadIdx.x;
    float wl = Wl[tid];
    for (int c = 0; c < 5; ++c) {
        const float* rp = g_rep + ((size_t)(b * 5 + c) * 50) * 256 + tid;
        float s = 0.f;
        for (int h = 0; h < 50; ++h) s += rp[(size_t)h * 256];
        s *= wl;
#pragma unroll
        for (int o = 16; o; o >>= 1) s += __shfl_xor_sync(0xffffffffu, s, o);
        if ((tid & 31) == 0) red[tid >> 5] = s;
        __syncthreads();
        if (tid < 8) {
            float v = red[tid];
#pragma unroll
            for (int o = 4; o; o >>= 1) v += __shfl_xor_sync(0xffu, v, o, 8);
            if (tid == 0) sc[c] = v * (1.f / 50.f) + blp[0];
        }
        __syncthreads();
    }
    if (tid == 0) {
        float m = sc[0];
        for (int c = 1; c < 5; ++c) m = fmaxf(m, sc[c]);
        float s = 0.f;
        for (int c = 0; c < 5; ++c) s += expf(sc[c] - m);
        float ls = logf(s);
        for (int c = 0; c < 5; ++c) out[b * 5 + c] = sc[c] - m - ls;
    }
}

// -------- host launcher --------
extern "C" void kernel_launch(void* const* d_in, const int* in_sizes, int n_in,
                              void* d_out, int out_size) {
    const int* cand = (const int*)d_in[0];
    const int* clk = (const int*)d_in[1];
    const float* emb = (const float*)d_in[2];
    const float* conv_w = (const float*)d_in[3];
    const float* conv_b = (const float*)d_in[4];
    const float* Wq = (const float*)d_in[5];
    const float* bq = (const float*)d_in[6];
    const float* Wv = (const float*)d_in[7];
    const float* bv = (const float*)d_in[8];
    const float* Wk = (const float*)d_in[9];
    const float* bk = (const float*)d_in[10];
    const float* qw = (const float*)d_in[11];
    const float* Wl = (const float*)d_in[12];
    const float* bl = (const float*)d_in[13];
    float* out = (float*)d_out;

    const int attn_smem = (2 * 42 * 260 + 656 + 41 * 44) * 4; // 97200 B
    cudaFuncSetAttribute(attn_kernel, cudaFuncAttributeMaxDynamicSharedMemorySize, attn_smem);

    prep_kernel<<<(NF * NCAT + 255) / 256, 256>>>(Wq, bq, Wv, bv);
    conv_kernel<<<NUROWS / 12, 256>>>(cand, clk, emb, conv_w, conv_b);
    gemm_qxv_kernel<<<dim3(NCAT / 64, (NUROWS + 127) / 128), 256>>>();
    attn_kernel<<<dim3(NH, NSEQ), 256, attn_smem>>>();
    gemm_wordk_kernel<<<dim3((NQD + 63) / 64, (MVAL + 127) / 128), 256>>>(Wk, bk);
    word_kernel<<<NSEQ, 256>>>(qw);
    final_kernel<<<NB, 256>>>(Wl, bl, out);
}

// round 6
// speedup vs baseline: 1.3249x; 1.3249x over previous
#include <cuda_runtime.h>
#include <cuda_bf16.h>
#include <math.h>

#define NB 16
#define NCDD 5
#define NHIS 50
#define NS 20
#define NT 41
#define NE 300
#define NF 256
#define NH 16
#define NDV 16
#define NQD 200
#define NSEQ 4000
#define NUROWS 21600
#define MID_BASE 17600
#define NCAT 4352
#define MVAL 164000
#define SCALE_F 0.057735026918962576f

// -------- static device scratch (no allocations) --------
__device__ float g_xu[NUROWS * NF];
__device__ float g_Wcat[NF * NCAT];
__device__ float g_bcat[NCAT];
__device__ float g_qxv[(size_t)NUROWS * NCAT];
__device__ float g_val[(size_t)MVAL * NF];
__device__ float g_kbuf[(size_t)MVAL * NQD];
__device__ float g_rep[(size_t)NSEQ * NF];

// -------- kernel 0: pack [Wq | Wv] -> Wcat[256 x 4352], bias --------
__global__ void prep_kernel(const float* __restrict__ Wq, const float* __restrict__ bq,
                            const float* __restrict__ Wv, const float* __restrict__ bv) {
    int idx = blockIdx.x * 256 + threadIdx.x;
    if (idx < NF * NCAT) {
        int f = idx / NCAT;
        int j = idx - f * NCAT;
        float w;
        if (j < NH * NF) {
            int h = j >> 8, g = j & 255;
            w = Wq[(h * 256 + f) * 256 + g];
        } else {
            int jj = j - NH * NF;
            int h = jj >> 4, d = jj & 15;
            w = Wv[(h * 256 + f) * 16 + d];
        }
        g_Wcat[idx] = w;
    }
    if (idx < NCAT) {
        if (idx < NH * NF) {
            int h = idx >> 8, g = idx & 255;
            g_bcat[idx] = bq[h * 256 + g];
        } else {
            g_bcat[idx] = bv[idx - NH * NF]; // bv folds through softmax (rows sum to 1)
        }
    }
}

// -------- kernel 1: conv1d(k=3, SAME) + ReLU over 21600 unique rows --------
__global__ void __launch_bounds__(256) conv_kernel(const int* __restrict__ cand,
                                                   const int* __restrict__ clk,
                                                   const float* __restrict__ emb,
                                                   const float* __restrict__ cw,
                                                   const float* __restrict__ cb) {
    __shared__ float se[12 * 900];
    __shared__ int st[12][3];
    int row0 = blockIdx.x * 12;
    int tid = threadIdx.x;
    if (tid < 12) {
        int row = row0 + tid;
        int t0, t1, t2;
        if (row < 1600) {
            int bc = row / 20, t = row - bc * 20;
            const int* ct = cand + bc * 20;
            t0 = (t - 1 >= 0) ? ct[t - 1] : -1;
            t1 = ct[t];
            t2 = (t + 1 < 20) ? ct[t + 1] : 1;
        } else if (row < MID_BASE) {
            int r2 = row - 1600;
            int bh = r2 / 20, tt = r2 - bh * 20;
            const int* ht = clk + bh * 20;
            t0 = (tt == 0) ? 1 : ht[tt - 1];
            t1 = ht[tt];
            t2 = (tt + 1 < 20) ? ht[tt + 1] : -1;
        } else {
            int nn = row - MID_BASE;
            int b = nn / 250, rr = nn - b * 250;
            int c = rr / 50, hh = rr - c * 50;
            t0 = cand[(b * 5 + c) * 20 + 19];
            t1 = 1;
            t2 = clk[(b * 50 + hh) * 20 + 0];
        }
        st[tid][0] = t0; st[tid][1] = t1; st[tid][2] = t2;
    }
    __syncthreads();
    for (int idx = tid; idx < 12 * 900; idx += 256) {
        int r = idx / 900;
        int rem = idx - r * 900;
        int w = rem / 300;
        int e = rem - w * 300;
        int tok = st[r][w];
        se[idx] = (tok < 0) ? 0.f : emb[(size_t)tok * NE + e];
    }
    __syncthreads();
    int f = tid;
    float cbf = cb[f];
    float acc[12];
#pragma unroll
    for (int r = 0; r < 12; ++r) acc[r] = cbf;
    for (int we = 0; we < 900; we += 4) {
        float w0 = cw[(we + 0) * 256 + f];
        float w1 = cw[(we + 1) * 256 + f];
        float w2 = cw[(we + 2) * 256 + f];
        float w3 = cw[(we + 3) * 256 + f];
#pragma unroll
        for (int r = 0; r < 12; ++r) {
            float4 a = *(const float4*)(se + r * 900 + we);
            acc[r] = fmaf(a.x, w0, acc[r]);
            acc[r] = fmaf(a.y, w1, acc[r]);
            acc[r] = fmaf(a.z, w2, acc[r]);
            acc[r] = fmaf(a.w, w3, acc[r]);
        }
    }
#pragma unroll
    for (int r = 0; r < 12; ++r)
        g_xu[(size_t)(row0 + r) * NF + f] = fmaxf(acc[r], 0.f);
}

// -------- tiled fp32 GEMM, K=256: C = A[Mx256] @ B[256xN] + bias; ACT 0=none,1=tanh ----
template <int ACT>
__device__ __forceinline__ void gemm_body(const float* __restrict__ A,
                                          const float* __restrict__ Bm,
                                          const float* __restrict__ bias,
                                          float* __restrict__ C, int M, int N) {
    __shared__ float As[16][132];
    __shared__ float Bs[16][68];
    int tid = threadIdx.x;
    int ty = tid >> 4, tx = tid & 15;
    int m0 = blockIdx.y * 128;
    int n0 = blockIdx.x * 64;

    float acc[8][4];
#pragma unroll
    for (int i = 0; i < 8; ++i)
#pragma unroll
        for (int j = 0; j < 4; ++j) acc[i][j] = 0.f;

    int arow = tid >> 2;
    int akq = (tid & 3) << 2;
    int brow = tid >> 4;
    int bcol = (tid & 15) << 2;

    for (int k0 = 0; k0 < 256; k0 += 16) {
#pragma unroll
        for (int g = 0; g < 2; ++g) {
            int m = m0 + arow + g * 64;
            float4 v = make_float4(0.f, 0.f, 0.f, 0.f);
            if (m < M) v = *(const float4*)(A + (size_t)m * 256 + k0 + akq);
            As[akq + 0][arow + g * 64] = v.x;
            As[akq + 1][arow + g * 64] = v.y;
            As[akq + 2][arow + g * 64] = v.z;
            As[akq + 3][arow + g * 64] = v.w;
        }
        {
            int n = n0 + bcol;
            float4 v = make_float4(0.f, 0.f, 0.f, 0.f);
            if (n + 3 < N) v = *(const float4*)(Bm + (size_t)(k0 + brow) * N + n);
            *(float4*)(&Bs[brow][bcol]) = v;
        }
        __syncthreads();
#pragma unroll
        for (int kk = 0; kk < 16; ++kk) {
            float4 a0 = *(const float4*)(&As[kk][ty * 8]);
            float4 a1 = *(const float4*)(&As[kk][ty * 8 + 4]);
            float4 b4 = *(const float4*)(&Bs[kk][tx << 2]);
            float av[8] = {a0.x, a0.y, a0.z, a0.w, a1.x, a1.y, a1.z, a1.w};
            float bb[4] = {b4.x, b4.y, b4.z, b4.w};
#pragma unroll
            for (int i = 0; i < 8; ++i)
#pragma unroll
                for (int j = 0; j < 4; ++j) acc[i][j] = fmaf(av[i], bb[j], acc[i][j]);
        }
        __syncthreads();
    }
#pragma unroll
    for (int i = 0; i < 8; ++i) {
        int m = m0 + ty * 8 + i;
        if (m >= M) continue;
#pragma unroll
        for (int j = 0; j < 4; ++j) {
            int n = n0 + (tx << 2) + j;
            if (n >= N) continue;
            float v = acc[i][j] + bias[n];
            if (ACT == 1) v = tanhf(v);
            C[(size_t)m * N + n] = v;
        }
    }
}

__global__ void __launch_bounds__(256) gemm_qxv_kernel() {
    gemm_body<0>(g_xu, g_Wcat, g_bcat, g_qxv, NUROWS, NCAT);
}
__global__ void __launch_bounds__(256) gemm_wordk_kernel(const float* __restrict__ Wk,
                                                         const float* __restrict__ bk) {
    gemm_body<1>(g_val, Wk, bk, g_kbuf, MVAL, NQD);
}

// -------- kernel 3: attention, block = (4 heads, 1 seq); 4 groups x 64 threads --------
#define DOT4(A, Q, X) \
    A = fmaf(Q.x, X.x, A); A = fmaf(Q.y, X.y, A); A = fmaf(Q.z, X.z, A); A = fmaf(Q.w, X.w, A);

// smem floats: xs 48*68=3264 | qs 4*3264=13056 | scm 4*41*44=7216 | xv 4*656=2624
#define ATTN_SMEM_FLOATS (3264 + 13056 + 7216 + 2624)

__global__ void __launch_bounds__(256, 2) attn_kernel() {
    extern __shared__ float sm[];
    float* xs = sm;                       // [48][68], chunk of 64 k
    float* qsA = sm + 3264;               // 4 x [48][68]
    float* scA = sm + 3264 + 13056;       // 4 x [41][44]
    float* xvA = sm + 3264 + 13056 + 7216;// 4 x [41][16]
    __shared__ int rows[41];

    int n = blockIdx.y;
    int hb = blockIdx.x;                  // head block 0..3
    int tid = threadIdx.x;
    int g = tid >> 6;                     // group 0..3
    int l = tid & 63;                     // lane within group
    int h = hb * 4 + g;

    float* qs = qsA + g * 3264;
    float* scm = scA + g * 1804;
    float* xvg = xvA + g * 656;

    if (tid < 41) {
        int b = n / 250, rr = n - b * 250;
        int c = rr / 50, hh = rr - c * 50;
        int t = tid, r;
        if (t < 20)       r = (b * 5 + c) * 20 + t;
        else if (t == 20) r = MID_BASE + n;
        else              r = 1600 + (b * 50 + hh) * 20 + (t - 21);
        rows[t] = r;
    }
    // zero pad rows 41..47 of xs and all qs (done once; loads only touch rows <41)
    for (int i = tid; i < 3264 + 13056; i += 256) {
        int off = (i < 3264) ? i : (i - 3264) % 3264;
        if (off >= 41 * 68) sm[i] = 0.f;
    }
    __syncthreads();

    // xv for this group's head (k-independent)
    for (int i = l; i < 656; i += 64) {
        int t = i >> 4, d = i & 15;
        xvg[i] = g_qxv[(size_t)rows[t] * NCAT + 4096 + h * 16 + d];
    }

    int ty = l >> 3, tx = l & 7;          // 8x8 thread grid, 6x6 tiles (stride 8)
    float acc[6][6];
#pragma unroll
    for (int i = 0; i < 6; ++i)
#pragma unroll
        for (int j = 0; j < 6; ++j) acc[i][j] = 0.f;

    for (int kc = 0; kc < 256; kc += 64) {
        __syncthreads();
        // stage x chunk (whole block) and q chunk (per group)
        for (int i = tid; i < 656; i += 256) {
            int t = i >> 4, kq = i & 15;
            *(float4*)(xs + t * 68 + kq * 4) =
                *(const float4*)(g_xu + (size_t)rows[t] * 256 + kc + kq * 4);
        }
        for (int i = l; i < 656; i += 64) {
            int t = i >> 4, kq = i & 15;
            *(float4*)(qs + t * 68 + kq * 4) =
                *(const float4*)(g_qxv + (size_t)rows[t] * NCAT + h * 256 + kc + kq * 4);
        }
        __syncthreads();
#pragma unroll 4
        for (int kq = 0; kq < 16; ++kq) {
            float4 qv[6], xv4[6];
#pragma unroll
            for (int r = 0; r < 6; ++r) qv[r] = *(const float4*)(qs + (ty + 8 * r) * 68 + kq * 4);
#pragma unroll
            for (int c = 0; c < 6; ++c) xv4[c] = *(const float4*)(xs + (tx + 8 * c) * 68 + kq * 4);
#pragma unroll
            for (int r = 0; r < 6; ++r)
#pragma unroll
                for (int c = 0; c < 6; ++c) { DOT4(acc[r][c], qv[r], xv4[c]); }
        }
    }
    // write scores
#pragma unroll
    for (int r = 0; r < 6; ++r) {
        int t = ty + 8 * r;
        if (t >= 41) continue;
#pragma unroll
        for (int c = 0; c < 6; ++c) {
            int s = tx + 8 * c;
            if (s < 41) scm[t * 44 + s] = acc[r][c] * SCALE_F;
        }
    }
    __syncthreads();

    // softmax per row (2 warps per group)
    {
        int w2 = l >> 5, lane = l & 31;
        for (int t = w2; t < 41; t += 2) {
            float v0 = (lane < 41) ? scm[t * 44 + lane] : -1e30f;
            float v1 = (lane + 32 < 41) ? scm[t * 44 + lane + 32] : -1e30f;
            float m = fmaxf(v0, v1);
#pragma unroll
            for (int o = 16; o; o >>= 1) m = fmaxf(m, __shfl_xor_sync(0xffffffffu, m, o));
            float e0 = (lane < 41) ? __expf(v0 - m) : 0.f;
            float e1 = (lane + 32 < 41) ? __expf(v1 - m) : 0.f;
            float s = e0 + e1;
#pragma unroll
            for (int o = 16; o; o >>= 1) s += __shfl_xor_sync(0xffffffffu, s, o);
            float inv = 1.f / s;
            if (lane < 41) scm[t * 44 + lane] = e0 * inv;
            if (lane + 32 < 41) scm[t * 44 + lane + 32] = e1 * inv;
        }
    }
    __syncthreads();

    // epilogue: out[t][d] = sum_s P[t][s] * xv[s][d]   (ALL 656 outputs)
    for (int i = l; i < 656; i += 64) {
        int t = i >> 4, d = i & 15;
        float a = 0.f;
#pragma unroll 8
        for (int s = 0; s < 41; ++s) a = fmaf(scm[t * 44 + s], xvg[s * 16 + d], a);
        g_val[((size_t)n * 41 + t) * 256 + h * 16 + d] = a;
    }
}

// -------- kernel 5: word attention per sequence --------
__global__ void __launch_bounds__(256) word_kernel(const float* __restrict__ qw) {
    __shared__ float sqw[200];
    __shared__ float sl[41];
    int n = blockIdx.x;
    int tid = threadIdx.x;
    if (tid < 200) sqw[tid] = qw[tid];
    __syncthreads();
    int warp = tid >> 5, lane = tid & 31;
    for (int t = warp; t < 41; t += 8) {
        const float* kr = g_kbuf + ((size_t)n * 41 + t) * 200;
        float s = 0.f;
        for (int e = lane; e < 200; e += 32) s = fmaf(kr[e], sqw[e], s);
#pragma unroll
        for (int o = 16; o; o >>= 1) s += __shfl_xor_sync(0xffffffffu, s, o);
        if (lane == 0) sl[t] = s * SCALE_F;
    }
    __syncthreads();
    if (tid < 32) {
        float v0 = (tid < 41) ? sl[tid] : -1e30f;
        float v1 = (tid + 32 < 41) ? sl[tid + 32] : -1e30f;
        float m = fmaxf(v0, v1);
#pragma unroll
        for (int o = 16; o; o >>= 1) m = fmaxf(m, __shfl_xor_sync(0xffffffffu, m, o));
        float e0 = (tid < 41) ? expf(v0 - m) : 0.f;
        float e1 = (tid + 32 < 41) ? expf(v1 - m) : 0.f;
        float s = e0 + e1;
#pragma unroll
        for (int o = 16; o; o >>= 1) s += __shfl_xor_sync(0xffffffffu, s, o);
        float inv = 1.f / s;
        if (tid < 41) sl[tid] = e0 * inv;
        if (tid + 32 < 41) sl[tid + 32] = e1 * inv;
    }
    __syncthreads();
    float acc = 0.f;
    const float* vr = g_val + (size_t)n * 41 * 256 + tid;
#pragma unroll 8
    for (int t = 0; t < 41; ++t) acc = fmaf(sl[t], vr[(size_t)t * 256], acc);
    g_rep[(size_t)n * 256 + tid] = acc;
}

// -------- kernel 6: mean over HIS, rank score, log-softmax over CDD --------
__global__ void __launch_bounds__(256) final_kernel(const float* __restrict__ Wl,
                                                    const float* __restrict__ blp,
                                                    float* __restrict__ out) {
    __shared__ float red[8];
    __shared__ float sc[5];
    int b = blockIdx.x;
    int tid = threadIdx.x;
    float wl = Wl[tid];
    for (int c = 0; c < 5; ++c) {
        const float* rp = g_rep + ((size_t)(b * 5 + c) * 50) * 256 + tid;
        float s = 0.f;
        for (int h = 0; h < 50; ++h) s += rp[(size_t)h * 256];
        s *= wl;
#pragma unroll
        for (int o = 16; o; o >>= 1) s += __shfl_xor_sync(0xffffffffu, s, o);
        if ((tid & 31) == 0) red[tid >> 5] = s;
        __syncthreads();
        if (tid < 8) {
            float v = red[tid];
#pragma unroll
            for (int o = 4; o; o >>= 1) v += __shfl_xor_sync(0xffu, v, o, 8);
            if (tid == 0) sc[c] = v * (1.f / 50.f) + blp[0];
        }
        __syncthreads();
    }
    if (tid == 0) {
        float m = sc[0];
        for (int c = 1; c < 5; ++c) m = fmaxf(m, sc[c]);
        float s = 0.f;
        for (int c = 0; c < 5; ++c) s += expf(sc[c] - m);
        float ls = logf(s);
        for (int c = 0; c < 5; ++c) out[b * 5 + c] = sc[c] - m - ls;
    }
}

// -------- host launcher --------
extern "C" void kernel_launch(void* const* d_in, const int* in_sizes, int n_in,
                              void* d_out, int out_size) {
    const int* cand = (const int*)d_in[0];
    const int* clk = (const int*)d_in[1];
    const float* emb = (const float*)d_in[2];
    const float* conv_w = (const float*)d_in[3];
    const float* conv_b = (const float*)d_in[4];
    const float* Wq = (const float*)d_in[5];
    const float* bq = (const float*)d_in[6];
    const float* Wv = (const float*)d_in[7];
    const float* bv = (const float*)d_in[8];
    const float* Wk = (const float*)d_in[9];
    const float* bk = (const float*)d_in[10];
    const float* qw = (const float*)d_in[11];
    const float* Wl = (const float*)d_in[12];
    const float* bl = (const float*)d_in[13];
    float* out = (float*)d_out;

    const int attn_smem = ATTN_SMEM_FLOATS * 4; // 104640 B
    cudaFuncSetAttribute(attn_kernel, cudaFuncAttributeMaxDynamicSharedMemorySize, attn_smem);

    prep_kernel<<<(NF * NCAT + 255) / 256, 256>>>(Wq, bq, Wv, bv);
    conv_kernel<<<NUROWS / 12, 256>>>(cand, clk, emb, conv_w, conv_b);
    gemm_qxv_kernel<<<dim3(NCAT / 64, (NUROWS + 127) / 128), 256>>>();
    attn_kernel<<<dim3(4, NSEQ), 256, attn_smem>>>();
    gemm_wordk_kernel<<<dim3((NQD + 63) / 64, (MVAL + 127) / 128), 256>>>(Wk, bk);
    word_kernel<<<NSEQ, 256>>>(qw);
    final_kernel<<<NB, 256>>>(Wl, bl, out);
}

// round 7
// speedup vs baseline: 1.4205x; 1.0721x over previous
#include <cuda_runtime.h>
#include <cuda_bf16.h>
#include <math.h>

#define NB 16
#define NCDD 5
#define NHIS 50
#define NS 20
#define NT 41
#define NE 300
#define NF 256
#define NH 16
#define NDV 16
#define NQD 200
#define NSEQ 4000
#define NUROWS 21600
#define MID_BASE 17600
#define NCAT 4352
#define MVAL 164000
#define SCALE_F 0.057735026918962576f

// -------- static device scratch (no allocations) --------
__device__ float g_xu[NUROWS * NF];
__device__ float g_Wcat[NF * NCAT];
__device__ float g_bcat[NCAT];
__device__ float g_qxv[(size_t)NUROWS * NCAT];
__device__ float g_val[(size_t)MVAL * NF];
__device__ float g_kbuf[(size_t)MVAL * NQD];
__device__ float g_rep[(size_t)NSEQ * NF];

// -------- kernel 0: pack [Wq | Wv] -> Wcat[256 x 4352], bias --------
__global__ void prep_kernel(const float* __restrict__ Wq, const float* __restrict__ bq,
                            const float* __restrict__ Wv, const float* __restrict__ bv) {
    int idx = blockIdx.x * 256 + threadIdx.x;
    if (idx < NF * NCAT) {
        int f = idx / NCAT;
        int j = idx - f * NCAT;
        float w;
        if (j < NH * NF) {
            int h = j >> 8, g = j & 255;
            w = Wq[(h * 256 + f) * 256 + g];
        } else {
            int jj = j - NH * NF;
            int h = jj >> 4, d = jj & 15;
            w = Wv[(h * 256 + f) * 16 + d];
        }
        g_Wcat[idx] = w;
    }
    if (idx < NCAT) {
        if (idx < NH * NF) {
            int h = idx >> 8, g = idx & 255;
            g_bcat[idx] = bq[h * 256 + g];
        } else {
            g_bcat[idx] = bv[idx - NH * NF]; // bv folds through softmax (rows sum to 1)
        }
    }
}

// -------- kernel 1: conv1d(k=3, SAME) + ReLU over 21600 unique rows --------
__global__ void __launch_bounds__(256) conv_kernel(const int* __restrict__ cand,
                                                   const int* __restrict__ clk,
                                                   const float* __restrict__ emb,
                                                   const float* __restrict__ cw,
                                                   const float* __restrict__ cb) {
    __shared__ float se[12 * 900];
    __shared__ int st[12][3];
    int row0 = blockIdx.x * 12;
    int tid = threadIdx.x;
    if (tid < 12) {
        int row = row0 + tid;
        int t0, t1, t2;
        if (row < 1600) {
            int bc = row / 20, t = row - bc * 20;
            const int* ct = cand + bc * 20;
            t0 = (t - 1 >= 0) ? ct[t - 1] : -1;
            t1 = ct[t];
            t2 = (t + 1 < 20) ? ct[t + 1] : 1;
        } else if (row < MID_BASE) {
            int r2 = row - 1600;
            int bh = r2 / 20, tt = r2 - bh * 20;
            const int* ht = clk + bh * 20;
            t0 = (tt == 0) ? 1 : ht[tt - 1];
            t1 = ht[tt];
            t2 = (tt + 1 < 20) ? ht[tt + 1] : -1;
        } else {
            int nn = row - MID_BASE;
            int b = nn / 250, rr = nn - b * 250;
            int c = rr / 50, hh = rr - c * 50;
            t0 = cand[(b * 5 + c) * 20 + 19];
            t1 = 1;
            t2 = clk[(b * 50 + hh) * 20 + 0];
        }
        st[tid][0] = t0; st[tid][1] = t1; st[tid][2] = t2;
    }
    __syncthreads();
    for (int idx = tid; idx < 12 * 900; idx += 256) {
        int r = idx / 900;
        int rem = idx - r * 900;
        int w = rem / 300;
        int e = rem - w * 300;
        int tok = st[r][w];
        se[idx] = (tok < 0) ? 0.f : emb[(size_t)tok * NE + e];
    }
    __syncthreads();
    int f = tid;
    float cbf = cb[f];
    float acc[12];
#pragma unroll
    for (int r = 0; r < 12; ++r) acc[r] = cbf;
    for (int we = 0; we < 900; we += 4) {
        float w0 = cw[(we + 0) * 256 + f];
        float w1 = cw[(we + 1) * 256 + f];
        float w2 = cw[(we + 2) * 256 + f];
        float w3 = cw[(we + 3) * 256 + f];
#pragma unroll
        for (int r = 0; r < 12; ++r) {
            float4 a = *(const float4*)(se + r * 900 + we);
            acc[r] = fmaf(a.x, w0, acc[r]);
            acc[r] = fmaf(a.y, w1, acc[r]);
            acc[r] = fmaf(a.z, w2, acc[r]);
            acc[r] = fmaf(a.w, w3, acc[r]);
        }
    }
#pragma unroll
    for (int r = 0; r < 12; ++r)
        g_xu[(size_t)(row0 + r) * NF + f] = fmaxf(acc[r], 0.f);
}

// -------- tiled fp32 GEMM, K=256: C = A[Mx256] @ B[256xN] + bias; ACT 0=none,1=tanh ----
template <int ACT>
__device__ __forceinline__ void gemm_body(const float* __restrict__ A,
                                          const float* __restrict__ Bm,
                                          const float* __restrict__ bias,
                                          float* __restrict__ C, int M, int N) {
    __shared__ float As[16][132];
    __shared__ float Bs[16][68];
    int tid = threadIdx.x;
    int ty = tid >> 4, tx = tid & 15;
    int m0 = blockIdx.y * 128;
    int n0 = blockIdx.x * 64;

    float acc[8][4];
#pragma unroll
    for (int i = 0; i < 8; ++i)
#pragma unroll
        for (int j = 0; j < 4; ++j) acc[i][j] = 0.f;

    int arow = tid >> 2;
    int akq = (tid & 3) << 2;
    int brow = tid >> 4;
    int bcol = (tid & 15) << 2;

    for (int k0 = 0; k0 < 256; k0 += 16) {
#pragma unroll
        for (int g = 0; g < 2; ++g) {
            int m = m0 + arow + g * 64;
            float4 v = make_float4(0.f, 0.f, 0.f, 0.f);
            if (m < M) v = *(const float4*)(A + (size_t)m * 256 + k0 + akq);
            As[akq + 0][arow + g * 64] = v.x;
            As[akq + 1][arow + g * 64] = v.y;
            As[akq + 2][arow + g * 64] = v.z;
            As[akq + 3][arow + g * 64] = v.w;
        }
        {
            int n = n0 + bcol;
            float4 v = make_float4(0.f, 0.f, 0.f, 0.f);
            if (n + 3 < N) v = *(const float4*)(Bm + (size_t)(k0 + brow) * N + n);
            *(float4*)(&Bs[brow][bcol]) = v;
        }
        __syncthreads();
#pragma unroll
        for (int kk = 0; kk < 16; ++kk) {
            float4 a0 = *(const float4*)(&As[kk][ty * 8]);
            float4 a1 = *(const float4*)(&As[kk][ty * 8 + 4]);
            float4 b4 = *(const float4*)(&Bs[kk][tx << 2]);
            float av[8] = {a0.x, a0.y, a0.z, a0.w, a1.x, a1.y, a1.z, a1.w};
            float bb[4] = {b4.x, b4.y, b4.z, b4.w};
#pragma unroll
            for (int i = 0; i < 8; ++i)
#pragma unroll
                for (int j = 0; j < 4; ++j) acc[i][j] = fmaf(av[i], bb[j], acc[i][j]);
        }
        __syncthreads();
    }
#pragma unroll
    for (int i = 0; i < 8; ++i) {
        int m = m0 + ty * 8 + i;
        if (m >= M) continue;
#pragma unroll
        for (int j = 0; j < 4; ++j) {
            int n = n0 + (tx << 2) + j;
            if (n >= N) continue;
            float v = acc[i][j] + bias[n];
            if (ACT == 1) v = tanhf(v);
            C[(size_t)m * N + n] = v;
        }
    }
}

__global__ void __launch_bounds__(256) gemm_qxv_kernel() {
    gemm_body<0>(g_xu, g_Wcat, g_bcat, g_qxv, NUROWS, NCAT);
}
__global__ void __launch_bounds__(256) gemm_wordk_kernel(const float* __restrict__ Wk,
                                                         const float* __restrict__ bk) {
    gemm_body<1>(g_val, Wk, bk, g_kbuf, MVAL, NQD);
}

// -------- kernel 3: attention, block = (4 heads, 1 seq); 4 groups x 64 threads --------
// k-chunk 32 -> smem 73.9KB -> 3 CTAs/SM (24 warps). Inner loop streams q (<=85 regs).
#define DOT4(A, Q, X) \
    A = fmaf(Q.x, X.x, A); A = fmaf(Q.y, X.y, A); A = fmaf(Q.z, X.z, A); A = fmaf(Q.w, X.w, A);

// smem floats: xs 48*36=1728 | qs 4*1728=6912 | scm 4*41*44=7216 | xv 4*656=2624
#define ATTN_SMEM_FLOATS (1728 + 6912 + 7216 + 2624)

__global__ void __launch_bounds__(256, 3) attn_kernel() {
    extern __shared__ float sm[];
    float* xs = sm;                          // [48][36], chunk of 32 k
    float* qsA = sm + 1728;                  // 4 x [48][36]
    float* scA = sm + 1728 + 6912;           // 4 x [41][44]
    float* xvA = sm + 1728 + 6912 + 7216;    // 4 x [41][16]
    __shared__ int rows[41];

    int n = blockIdx.y;
    int hb = blockIdx.x;                     // head block 0..3
    int tid = threadIdx.x;
    int g = tid >> 6;                        // group 0..3
    int l = tid & 63;                        // lane within group
    int h = hb * 4 + g;

    float* qs = qsA + g * 1728;
    float* scm = scA + g * 1804;
    float* xvg = xvA + g * 656;

    if (tid < 41) {
        int b = n / 250, rr = n - b * 250;
        int c = rr / 50, hh = rr - c * 50;
        int t = tid, r;
        if (t < 20)       r = (b * 5 + c) * 20 + t;
        else if (t == 20) r = MID_BASE + n;
        else              r = 1600 + (b * 50 + hh) * 20 + (t - 21);
        rows[t] = r;
    }
    // zero pad rows 41..47 once (chunks rewrite only rows < 41 at fixed offsets)
    if (tid < 252) xs[41 * 36 + tid] = 0.f;
    for (int i = l; i < 252; i += 64) qs[41 * 36 + i] = 0.f;
    __syncthreads();

    // xv for this group's head (k-independent)
    for (int i = l; i < 656; i += 64) {
        int t = i >> 4, d = i & 15;
        xvg[i] = g_qxv[(size_t)rows[t] * NCAT + 4096 + h * 16 + d];
    }

    int ty = l >> 3, tx = l & 7;             // 8x8 thread grid, 6x6 tiles (stride 8)
    float acc[6][6];
#pragma unroll
    for (int i = 0; i < 6; ++i)
#pragma unroll
        for (int j = 0; j < 6; ++j) acc[i][j] = 0.f;

    const float* xp0 = xs + tx * 36;
    const float* qp0 = qs + ty * 36;

    for (int kc = 0; kc < 256; kc += 32) {
        __syncthreads();
        // stage x chunk (whole block): 41 rows x 8 float4
        for (int i = tid; i < 328; i += 256) {
            int t = i >> 3, kq = i & 7;
            *(float4*)(xs + t * 36 + kq * 4) =
                *(const float4*)(g_xu + (size_t)rows[t] * 256 + kc + kq * 4);
        }
        // stage q chunk (per group)
        for (int i = l; i < 328; i += 64) {
            int t = i >> 3, kq = i & 7;
            *(float4*)(qs + t * 36 + kq * 4) =
                *(const float4*)(g_qxv + (size_t)rows[t] * NCAT + h * 256 + kc + kq * 4);
        }
        __syncthreads();
#pragma unroll 2
        for (int kq = 0; kq < 8; ++kq) {
            float4 xv4[6];
#pragma unroll
            for (int c = 0; c < 6; ++c) xv4[c] = *(const float4*)(xp0 + c * (8 * 36) + kq * 4);
#pragma unroll
            for (int r = 0; r < 6; ++r) {
                float4 qv = *(const float4*)(qp0 + r * (8 * 36) + kq * 4);
#pragma unroll
                for (int c = 0; c < 6; ++c) { DOT4(acc[r][c], qv, xv4[c]); }
            }
        }
    }
    // write scores
#pragma unroll
    for (int r = 0; r < 6; ++r) {
        int t = ty + 8 * r;
        if (t >= 41) continue;
#pragma unroll
        for (int c = 0; c < 6; ++c) {
            int s = tx + 8 * c;
            if (s < 41) scm[t * 44 + s] = acc[r][c] * SCALE_F;
        }
    }
    __syncthreads();

    // softmax per row (2 warps per group)
    {
        int w2 = l >> 5, lane = l & 31;
        for (int t = w2; t < 41; t += 2) {
            float v0 = (lane < 41) ? scm[t * 44 + lane] : -1e30f;
            float v1 = (lane + 32 < 41) ? scm[t * 44 + lane + 32] : -1e30f;
            float m = fmaxf(v0, v1);
#pragma unroll
            for (int o = 16; o; o >>= 1) m = fmaxf(m, __shfl_xor_sync(0xffffffffu, m, o));
            float e0 = (lane < 41) ? __expf(v0 - m) : 0.f;
            float e1 = (lane + 32 < 41) ? __expf(v1 - m) : 0.f;
            float s = e0 + e1;
#pragma unroll
            for (int o = 16; o; o >>= 1) s += __shfl_xor_sync(0xffffffffu, s, o);
            float inv = 1.f / s;
            if (lane < 41) scm[t * 44 + lane] = e0 * inv;
            if (lane + 32 < 41) scm[t * 44 + lane + 32] = e1 * inv;
        }
    }
    __syncthreads();

    // epilogue: out[t][d] = sum_s P[t][s] * xv[s][d]
    for (int i = l; i < 656; i += 64) {
        int t = i >> 4, d = i & 15;
        float a = 0.f;
#pragma unroll 8
        for (int s = 0; s < 41; ++s) a = fmaf(scm[t * 44 + s], xvg[s * 16 + d], a);
        g_val[((size_t)n * 41 + t) * 256 + h * 16 + d] = a;
    }
}

// -------- kernel 5: word attention per sequence --------
__global__ void __launch_bounds__(256) word_kernel(const float* __restrict__ qw) {
    __shared__ float sqw[200];
    __shared__ float sl[41];
    int n = blockIdx.x;
    int tid = threadIdx.x;
    if (tid < 200) sqw[tid] = qw[tid];
    __syncthreads();
    int warp = tid >> 5, lane = tid & 31;
    for (int t = warp; t < 41; t += 8) {
        const float* kr = g_kbuf + ((size_t)n * 41 + t) * 200;
        float s = 0.f;
        for (int e = lane; e < 200; e += 32) s = fmaf(kr[e], sqw[e], s);
#pragma unroll
        for (int o = 16; o; o >>= 1) s += __shfl_xor_sync(0xffffffffu, s, o);
        if (lane == 0) sl[t] = s * SCALE_F;
    }
    __syncthreads();
    if (tid < 32) {
        float v0 = (tid < 41) ? sl[tid] : -1e30f;
        float v1 = (tid + 32 < 41) ? sl[tid + 32] : -1e30f;
        float m = fmaxf(v0, v1);
#pragma unroll
        for (int o = 16; o; o >>= 1) m = fmaxf(m, __shfl_xor_sync(0xffffffffu, m, o));
        float e0 = (tid < 41) ? expf(v0 - m) : 0.f;
        float e1 = (tid + 32 < 41) ? expf(v1 - m) : 0.f;
        float s = e0 + e1;
#pragma unroll
        for (int o = 16; o; o >>= 1) s += __shfl_xor_sync(0xffffffffu, s, o);
        float inv = 1.f / s;
        if (tid < 41) sl[tid] = e0 * inv;
        if (tid + 32 < 41) sl[tid + 32] = e1 * inv;
    }
    __syncthreads();
    float acc = 0.f;
    const float* vr = g_val + (size_t)n * 41 * 256 + tid;
#pragma unroll 8
    for (int t = 0; t < 41; ++t) acc = fmaf(sl[t], vr[(size_t)t * 256], acc);
    g_rep[(size_t)n * 256 + tid] = acc;
}

// -------- kernel 6: mean over HIS, rank score, log-softmax over CDD --------
__global__ void __launch_bounds__(256) final_kernel(const float* __restrict__ Wl,
                                                    const float* __restrict__ blp,
                                                    float* __restrict__ out) {
    __shared__ float red[8];
    __shared__ float sc[5];
    int b = blockIdx.x;
    int tid = threadIdx.x;
    float wl = Wl[tid];
    for (int c = 0; c < 5; ++c) {
        const float* rp = g_rep + ((size_t)(b * 5 + c) * 50) * 256 + tid;
        float s = 0.f;
        for (int h = 0; h < 50; ++h) s += rp[(size_t)h * 256];
        s *= wl;
#pragma unroll
        for (int o = 16; o; o >>= 1) s += __shfl_xor_sync(0xffffffffu, s, o);
        if ((tid & 31) == 0) red[tid >> 5] = s;
        __syncthreads();
        if (tid < 8) {
            float v = red[tid];
#pragma unroll
            for (int o = 4; o; o >>= 1) v += __shfl_xor_sync(0xffu, v, o, 8);
            if (tid == 0) sc[c] = v * (1.f / 50.f) + blp[0];
        }
        __syncthreads();
    }
    if (tid == 0) {
        float m = sc[0];
        for (int c = 1; c < 5; ++c) m = fmaxf(m, sc[c]);
        float s = 0.f;
        for (int c = 0; c < 5; ++c) s += expf(sc[c] - m);
        float ls = logf(s);
        for (int c = 0; c < 5; ++c) out[b * 5 + c] = sc[c] - m - ls;
    }
}

// -------- host launcher --------
extern "C" void kernel_launch(void* const* d_in, const int* in_sizes, int n_in,
                              void* d_out, int out_size) {
    const int* cand = (const int*)d_in[0];
    const int* clk = (const int*)d_in[1];
    const float* emb = (const float*)d_in[2];
    const float* conv_w = (const float*)d_in[3];
    const float* conv_b = (const float*)d_in[4];
    const float* Wq = (const float*)d_in[5];
    const float* bq = (const float*)d_in[6];
    const float* Wv = (const float*)d_in[7];
    const float* bv = (const float*)d_in[8];
    const float* Wk = (const float*)d_in[9];
    const float* bk = (const float*)d_in[10];
    const float* qw = (const float*)d_in[11];
    const float* Wl = (const float*)d_in[12];
    const float* bl = (const float*)d_in[13];
    float* out = (float*)d_out;

    const int attn_smem = ATTN_SMEM_FLOATS * 4; // 73920 B -> 3 CTAs/SM
    cudaFuncSetAttribute(attn_kernel, cudaFuncAttributeMaxDynamicSharedMemorySize, attn_smem);

    prep_kernel<<<(NF * NCAT + 255) / 256, 256>>>(Wq, bq, Wv, bv);
    conv_kernel<<<NUROWS / 12, 256>>>(cand, clk, emb, conv_w, conv_b);
    gemm_qxv_kernel<<<dim3(NCAT / 64, (NUROWS + 127) / 128), 256>>>();
    attn_kernel<<<dim3(4, NSEQ), 256, attn_smem>>>();
    gemm_wordk_kernel<<<dim3((NQD + 63) / 64, (MVAL + 127) / 128), 256>>>(Wk, bk);
    word_kernel<<<NSEQ, 256>>>(qw);
    final_kernel<<<NB, 256>>>(Wl, bl, out);
}

// round 8
// speedup vs baseline: 2.0521x; 1.4447x over previous
#include <cuda_runtime.h>
#include <cuda_bf16.h>
#include <math.h>
#include <stdint.h>

#define NB 16
#define NCDD 5
#define NHIS 50
#define NS 20
#define NT 41
#define NE 300
#define NF 256
#define NH 16
#define NDV 16
#define NQD 200
#define NSEQ 4000
#define NUROWS 21600
#define MID_BASE 17600
#define NCAT 4352
#define MVAL 164000
#define SCALE_F 0.057735026918962576f

// -------- static device scratch (no allocations) --------
__device__ float g_xu[NUROWS * NF];
__device__ float g_Wcat[NF * NCAT];
__device__ float g_bcat[NCAT];
__device__ float g_qxv[(size_t)NUROWS * NCAT];
__device__ float g_val[(size_t)MVAL * NF];
__device__ float g_kbuf[(size_t)MVAL * NQD];
__device__ float g_rep[(size_t)NSEQ * NF];

// -------- kernel 0: pack [Wq | Wv] -> Wcat[256 x 4352], bias --------
__global__ void prep_kernel(const float* __restrict__ Wq, const float* __restrict__ bq,
                            const float* __restrict__ Wv, const float* __restrict__ bv) {
    int idx = blockIdx.x * 256 + threadIdx.x;
    if (idx < NF * NCAT) {
        int f = idx / NCAT;
        int j = idx - f * NCAT;
        float w;
        if (j < NH * NF) {
            int h = j >> 8, g = j & 255;
            w = Wq[(h * 256 + f) * 256 + g];
        } else {
            int jj = j - NH * NF;
            int h = jj >> 4, d = jj & 15;
            w = Wv[(h * 256 + f) * 16 + d];
        }
        g_Wcat[idx] = w;
    }
    if (idx < NCAT) {
        if (idx < NH * NF) {
            int h = idx >> 8, g = idx & 255;
            g_bcat[idx] = bq[h * 256 + g];
        } else {
            g_bcat[idx] = bv[idx - NH * NF]; // bv folds through softmax (rows sum to 1)
        }
    }
}

// -------- kernel 1: conv1d(k=3, SAME) + ReLU over 21600 unique rows --------
__global__ void __launch_bounds__(256) conv_kernel(const int* __restrict__ cand,
                                                   const int* __restrict__ clk,
                                                   const float* __restrict__ emb,
                                                   const float* __restrict__ cw,
                                                   const float* __restrict__ cb) {
    __shared__ float se[12 * 900];
    __shared__ int st[12][3];
    int row0 = blockIdx.x * 12;
    int tid = threadIdx.x;
    if (tid < 12) {
        int row = row0 + tid;
        int t0, t1, t2;
        if (row < 1600) {
            int bc = row / 20, t = row - bc * 20;
            const int* ct = cand + bc * 20;
            t0 = (t - 1 >= 0) ? ct[t - 1] : -1;
            t1 = ct[t];
            t2 = (t + 1 < 20) ? ct[t + 1] : 1;
        } else if (row < MID_BASE) {
            int r2 = row - 1600;
            int bh = r2 / 20, tt = r2 - bh * 20;
            const int* ht = clk + bh * 20;
            t0 = (tt == 0) ? 1 : ht[tt - 1];
            t1 = ht[tt];
            t2 = (tt + 1 < 20) ? ht[tt + 1] : -1;
        } else {
            int nn = row - MID_BASE;
            int b = nn / 250, rr = nn - b * 250;
            int c = rr / 50, hh = rr - c * 50;
            t0 = cand[(b * 5 + c) * 20 + 19];
            t1 = 1;
            t2 = clk[(b * 50 + hh) * 20 + 0];
        }
        st[tid][0] = t0; st[tid][1] = t1; st[tid][2] = t2;
    }
    __syncthreads();
    for (int idx = tid; idx < 12 * 900; idx += 256) {
        int r = idx / 900;
        int rem = idx - r * 900;
        int w = rem / 300;
        int e = rem - w * 300;
        int tok = st[r][w];
        se[idx] = (tok < 0) ? 0.f : emb[(size_t)tok * NE + e];
    }
    __syncthreads();
    int f = tid;
    float cbf = cb[f];
    float acc[12];
#pragma unroll
    for (int r = 0; r < 12; ++r) acc[r] = cbf;
    for (int we = 0; we < 900; we += 4) {
        float w0 = cw[(we + 0) * 256 + f];
        float w1 = cw[(we + 1) * 256 + f];
        float w2 = cw[(we + 2) * 256 + f];
        float w3 = cw[(we + 3) * 256 + f];
#pragma unroll
        for (int r = 0; r < 12; ++r) {
            float4 a = *(const float4*)(se + r * 900 + we);
            acc[r] = fmaf(a.x, w0, acc[r]);
            acc[r] = fmaf(a.y, w1, acc[r]);
            acc[r] = fmaf(a.z, w2, acc[r]);
            acc[r] = fmaf(a.w, w3, acc[r]);
        }
    }
#pragma unroll
    for (int r = 0; r < 12; ++r)
        g_xu[(size_t)(row0 + r) * NF + f] = fmaxf(acc[r], 0.f);
}

// -------- tiled fp32 GEMM, K=256: C = A[Mx256] @ B[256xN] + bias; ACT 0=none,1=tanh ----
template <int ACT>
__device__ __forceinline__ void gemm_body(const float* __restrict__ A,
                                          const float* __restrict__ Bm,
                                          const float* __restrict__ bias,
                                          float* __restrict__ C, int M, int N) {
    __shared__ float As[16][132];
    __shared__ float Bs[16][68];
    int tid = threadIdx.x;
    int ty = tid >> 4, tx = tid & 15;
    int m0 = blockIdx.y * 128;
    int n0 = blockIdx.x * 64;

    float acc[8][4];
#pragma unroll
    for (int i = 0; i < 8; ++i)
#pragma unroll
        for (int j = 0; j < 4; ++j) acc[i][j] = 0.f;

    int arow = tid >> 2;
    int akq = (tid & 3) << 2;
    int brow = tid >> 4;
    int bcol = (tid & 15) << 2;

    for (int k0 = 0; k0 < 256; k0 += 16) {
#pragma unroll
        for (int g = 0; g < 2; ++g) {
            int m = m0 + arow + g * 64;
            float4 v = make_float4(0.f, 0.f, 0.f, 0.f);
            if (m < M) v = *(const float4*)(A + (size_t)m * 256 + k0 + akq);
            As[akq + 0][arow + g * 64] = v.x;
            As[akq + 1][arow + g * 64] = v.y;
            As[akq + 2][arow + g * 64] = v.z;
            As[akq + 3][arow + g * 64] = v.w;
        }
        {
            int n = n0 + bcol;
            float4 v = make_float4(0.f, 0.f, 0.f, 0.f);
            if (n + 3 < N) v = *(const float4*)(Bm + (size_t)(k0 + brow) * N + n);
            *(float4*)(&Bs[brow][bcol]) = v;
        }
        __syncthreads();
#pragma unroll
        for (int kk = 0; kk < 16; ++kk) {
            float4 a0 = *(const float4*)(&As[kk][ty * 8]);
            float4 a1 = *(const float4*)(&As[kk][ty * 8 + 4]);
            float4 b4 = *(const float4*)(&Bs[kk][tx << 2]);
            float av[8] = {a0.x, a0.y, a0.z, a0.w, a1.x, a1.y, a1.z, a1.w};
            float bb[4] = {b4.x, b4.y, b4.z, b4.w};
#pragma unroll
            for (int i = 0; i < 8; ++i)
#pragma unroll
                for (int j = 0; j < 4; ++j) acc[i][j] = fmaf(av[i], bb[j], acc[i][j]);
        }
        __syncthreads();
    }
#pragma unroll
    for (int i = 0; i < 8; ++i) {
        int m = m0 + ty * 8 + i;
        if (m >= M) continue;
#pragma unroll
        for (int j = 0; j < 4; ++j) {
            int n = n0 + (tx << 2) + j;
            if (n >= N) continue;
            float v = acc[i][j] + bias[n];
            if (ACT == 1) v = tanhf(v);
            C[(size_t)m * N + n] = v;
        }
    }
}

__global__ void __launch_bounds__(256) gemm_qxv_kernel() {
    gemm_body<0>(g_xu, g_Wcat, g_bcat, g_qxv, NUROWS, NCAT);
}
__global__ void __launch_bounds__(256) gemm_wordk_kernel(const float* __restrict__ Wk,
                                                         const float* __restrict__ bk) {
    gemm_body<1>(g_val, Wk, bk, g_kbuf, MVAL, NQD);
}

// -------- kernel 3: attention, block = (4 heads, 1 seq); scores via bf16 mma.sync --------
// smem bytes: xb 48*72 bf16 = 6912 | qb 4x6912 = 27648 | scm 4*1804*4 = 28864 | xv 4*656*4 = 10496
// total 73920 B -> 3 CTAs/SM
#define ATTN_SMEM_BYTES 73920

__global__ void __launch_bounds__(256, 3) attn_kernel() {
    extern __shared__ float sm[];
    __nv_bfloat16* xb = (__nv_bfloat16*)sm;                    // [48][72] bf16 (k-chunk 64)
    __nv_bfloat16* qbA = (__nv_bfloat16*)(sm + 1728);          // 4 x [48][72] bf16
    float* scA = sm + 1728 + 6912;                             // 4 x [41][44]
    float* xvA = sm + 1728 + 6912 + 7216;                      // 4 x [41][16]
    __shared__ int rows[41];

    int n = blockIdx.y;
    int hb = blockIdx.x;
    int tid = threadIdx.x;
    int g = tid >> 6;                  // group 0..3 (one head each, 2 warps)
    int l = tid & 63;
    int w = l >> 5;                    // warp within group
    int lane = l & 31;
    int h = hb * 4 + g;

    __nv_bfloat16* qb = qbA + g * 3456;
    float* scm = scA + g * 1804;
    float* xvg = xvA + g * 656;

    uint32_t xb_u = (uint32_t)__cvta_generic_to_shared(xb);
    uint32_t qb_u = (uint32_t)__cvta_generic_to_shared(qb);

    if (tid < 41) {
        int b = n / 250, rr = n - b * 250;
        int c = rr / 50, hh = rr - c * 50;
        int t = tid, r;
        if (t < 20)       r = (b * 5 + c) * 20 + t;
        else if (t == 20) r = MID_BASE + n;
        else              r = 1600 + (b * 50 + hh) * 20 + (t - 21);
        rows[t] = r;
    }
    __syncthreads();

    // xv for this group's head (fp32, float4 loads)
    for (int i = l; i < 164; i += 64) {
        int t = i >> 2, qd = i & 3;
        *(float4*)(xvg + t * 16 + qd * 4) =
            *(const float4*)(g_qxv + (size_t)rows[t] * NCAT + 4096 + h * 16 + qd * 4);
    }

    float acc[3][3][4];
#pragma unroll
    for (int i = 0; i < 3; ++i)
#pragma unroll
        for (int j = 0; j < 3; ++j)
#pragma unroll
            for (int e = 0; e < 4; ++e) acc[i][j][e] = 0.f;

    for (int kc = 0; kc < 256; kc += 64) {
        __syncthreads();
        // stage x chunk (whole block): 41 rows x 16 float4 -> bf16
        for (int i = tid; i < 656; i += 256) {
            int t = i >> 4, kq = i & 15;
            float4 v = *(const float4*)(g_xu + (size_t)rows[t] * 256 + kc + kq * 4);
            __nv_bfloat162 p0 = __floats2bfloat162_rn(v.x, v.y);
            __nv_bfloat162 p1 = __floats2bfloat162_rn(v.z, v.w);
            uint2 u;
            u.x = *(uint32_t*)&p0;
            u.y = *(uint32_t*)&p1;
            *(uint2*)(xb + t * 72 + kq * 4) = u;
        }
        // stage q chunk (per group) -> bf16
        for (int i = l; i < 656; i += 64) {
            int t = i >> 4, kq = i & 15;
            float4 v = *(const float4*)(g_qxv + (size_t)rows[t] * NCAT + h * 256 + kc + kq * 4);
            __nv_bfloat162 p0 = __floats2bfloat162_rn(v.x, v.y);
            __nv_bfloat162 p1 = __floats2bfloat162_rn(v.z, v.w);
            uint2 u;
            u.x = *(uint32_t*)&p0;
            u.y = *(uint32_t*)&p1;
            *(uint2*)(qb + t * 72 + kq * 4) = u;
        }
        __syncthreads();
#pragma unroll
        for (int ks = 0; ks < 4; ++ks) {
            uint32_t a[3][4], b[3][2];
#pragma unroll
            for (int i = 0; i < 3; ++i) {
                uint32_t addr = qb_u +
                    (uint32_t)(((i * 16 + (lane & 15)) * 72 + ks * 16 + (lane >> 4) * 8) * 2);
                asm volatile("ldmatrix.sync.aligned.m8n8.x4.shared.b16 {%0,%1,%2,%3}, [%4];"
                    : "=r"(a[i][0]), "=r"(a[i][1]), "=r"(a[i][2]), "=r"(a[i][3]) : "r"(addr));
            }
#pragma unroll
            for (int j = 0; j < 3; ++j) {
                int nr = w * 24 + j * 8 + (lane & 7);
                uint32_t addr = xb_u +
                    (uint32_t)((nr * 72 + ks * 16 + ((lane >> 3) & 1) * 8) * 2);
                asm volatile("ldmatrix.sync.aligned.m8n8.x2.shared.b16 {%0,%1}, [%2];"
                    : "=r"(b[j][0]), "=r"(b[j][1]) : "r"(addr));
            }
#pragma unroll
            for (int i = 0; i < 3; ++i)
#pragma unroll
                for (int j = 0; j < 3; ++j)
                    asm volatile(
                        "mma.sync.aligned.m16n8k16.row.col.f32.bf16.bf16.f32 "
                        "{%0,%1,%2,%3}, {%4,%5,%6,%7}, {%8,%9}, {%0,%1,%2,%3};"
                        : "+f"(acc[i][j][0]), "+f"(acc[i][j][1]),
                          "+f"(acc[i][j][2]), "+f"(acc[i][j][3])
                        : "r"(a[i][0]), "r"(a[i][1]), "r"(a[i][2]), "r"(a[i][3]),
                          "r"(b[j][0]), "r"(b[j][1]));
        }
    }

    // write scores (predicated to 41x41)
    {
        int gid = lane >> 2, t4 = lane & 3;
#pragma unroll
        for (int i = 0; i < 3; ++i) {
#pragma unroll
            for (int j = 0; j < 3; ++j) {
                int c0 = w * 24 + j * 8 + t4 * 2;
                int r0 = i * 16 + gid;
                if (r0 < 41) {
                    if (c0 < 41) scm[r0 * 44 + c0] = acc[i][j][0] * SCALE_F;
                    if (c0 + 1 < 41) scm[r0 * 44 + c0 + 1] = acc[i][j][1] * SCALE_F;
                }
                int r1 = r0 + 8;
                if (r1 < 41) {
                    if (c0 < 41) scm[r1 * 44 + c0] = acc[i][j][2] * SCALE_F;
                    if (c0 + 1 < 41) scm[r1 * 44 + c0 + 1] = acc[i][j][3] * SCALE_F;
                }
            }
        }
    }
    __syncthreads();

    // softmax per row (2 warps per group)
    for (int t = w; t < 41; t += 2) {
        float v0 = (lane < 41) ? scm[t * 44 + lane] : -1e30f;
        float v1 = (lane + 32 < 41) ? scm[t * 44 + lane + 32] : -1e30f;
        float m = fmaxf(v0, v1);
#pragma unroll
        for (int o = 16; o; o >>= 1) m = fmaxf(m, __shfl_xor_sync(0xffffffffu, m, o));
        float e0 = (lane < 41) ? __expf(v0 - m) : 0.f;
        float e1 = (lane + 32 < 41) ? __expf(v1 - m) : 0.f;
        float s = e0 + e1;
#pragma unroll
        for (int o = 16; o; o >>= 1) s += __shfl_xor_sync(0xffffffffu, s, o);
        float inv = 1.f / s;
        if (lane < 41) scm[t * 44 + lane] = e0 * inv;
        if (lane + 32 < 41) scm[t * 44 + lane + 32] = e1 * inv;
    }
    __syncthreads();

    // epilogue: out[t][d] = sum_s P[t][s] * xv[s][d]
    for (int i = l; i < 656; i += 64) {
        int t = i >> 4, d = i & 15;
        float a = 0.f;
#pragma unroll 8
        for (int s = 0; s < 41; ++s) a = fmaf(scm[t * 44 + s], xvg[s * 16 + d], a);
        g_val[((size_t)n * 41 + t) * 256 + h * 16 + d] = a;
    }
}

// -------- kernel 5: word attention per sequence --------
__global__ void __launch_bounds__(256) word_kernel(const float* __restrict__ qw) {
    __shared__ float sqw[200];
    __shared__ float sl[41];
    int n = blockIdx.x;
    int tid = threadIdx.x;
    if (tid < 200) sqw[tid] = qw[tid];
    __syncthreads();
    int warp = tid >> 5, lane = tid & 31;
    for (int t = warp; t < 41; t += 8) {
        const float* kr = g_kbuf + ((size_t)n * 41 + t) * 200;
        float s = 0.f;
        for (int e = lane; e < 200; e += 32) s = fmaf(kr[e], sqw[e], s);
#pragma unroll
        for (int o = 16; o; o >>= 1) s += __shfl_xor_sync(0xffffffffu, s, o);
        if (lane == 0) sl[t] = s * SCALE_F;
    }
    __syncthreads();
    if (tid < 32) {
        float v0 = (tid < 41) ? sl[tid] : -1e30f;
        float v1 = (tid + 32 < 41) ? sl[tid + 32] : -1e30f;
        float m = fmaxf(v0, v1);
#pragma unroll
        for (int o = 16; o; o >>= 1) m = fmaxf(m, __shfl_xor_sync(0xffffffffu, m, o));
        float e0 = (tid < 41) ? expf(v0 - m) : 0.f;
        float e1 = (tid + 32 < 41) ? expf(v1 - m) : 0.f;
        float s = e0 + e1;
#pragma unroll
        for (int o = 16; o; o >>= 1) s += __shfl_xor_sync(0xffffffffu, s, o);
        float inv = 1.f / s;
        if (tid < 41) sl[tid] = e0 * inv;
        if (tid + 32 < 41) sl[tid + 32] = e1 * inv;
    }
    __syncthreads();
    float acc = 0.f;
    const float* vr = g_val + (size_t)n * 41 * 256 + tid;
#pragma unroll 8
    for (int t = 0; t < 41; ++t) acc = fmaf(sl[t], vr[(size_t)t * 256], acc);
    g_rep[(size_t)n * 256 + tid] = acc;
}

// -------- kernel 6: mean over HIS, rank score, log-softmax over CDD --------
__global__ void __launch_bounds__(256) final_kernel(const float* __restrict__ Wl,
                                                    const float* __restrict__ blp,
                                                    float* __restrict__ out) {
    __shared__ float red[8];
    __shared__ float sc[5];
    int b = blockIdx.x;
    int tid = threadIdx.x;
    float wl = Wl[tid];
    for (int c = 0; c < 5; ++c) {
        const float* rp = g_rep + ((size_t)(b * 5 + c) * 50) * 256 + tid;
        float s = 0.f;
        for (int h = 0; h < 50; ++h) s += rp[(size_t)h * 256];
        s *= wl;
#pragma unroll
        for (int o = 16; o; o >>= 1) s += __shfl_xor_sync(0xffffffffu, s, o);
        if ((tid & 31) == 0) red[tid >> 5] = s;
        __syncthreads();
        if (tid < 8) {
            float v = red[tid];
#pragma unroll
            for (int o = 4; o; o >>= 1) v += __shfl_xor_sync(0xffu, v, o, 8);
            if (tid == 0) sc[c] = v * (1.f / 50.f) + blp[0];
        }
        __syncthreads();
    }
    if (tid == 0) {
        float m = sc[0];
        for (int c = 1; c < 5; ++c) m = fmaxf(m, sc[c]);
        float s = 0.f;
        for (int c = 0; c < 5; ++c) s += expf(sc[c] - m);
        float ls = logf(s);
        for (int c = 0; c < 5; ++c) out[b * 5 + c] = sc[c] - m - ls;
    }
}

// -------- host launcher --------
extern "C" void kernel_launch(void* const* d_in, const int* in_sizes, int n_in,
                              void* d_out, int out_size) {
    const int* cand = (const int*)d_in[0];
    const int* clk = (const int*)d_in[1];
    const float* emb = (const float*)d_in[2];
    const float* conv_w = (const float*)d_in[3];
    const float* conv_b = (const float*)d_in[4];
    const float* Wq = (const float*)d_in[5];
    const float* bq = (const float*)d_in[6];
    const float* Wv = (const float*)d_in[7];
    const float* bv = (const float*)d_in[8];
    const float* Wk = (const float*)d_in[9];
    const float* bk = (const float*)d_in[10];
    const float* qw = (const float*)d_in[11];
    const float* Wl = (const float*)d_in[12];
    const float* bl = (const float*)d_in[13];
    float* out = (float*)d_out;

    cudaFuncSetAttribute(attn_kernel, cudaFuncAttributeMaxDynamicSharedMemorySize,
                         ATTN_SMEM_BYTES);

    prep_kernel<<<(NF * NCAT + 255) / 256, 256>>>(Wq, bq, Wv, bv);
    conv_kernel<<<NUROWS / 12, 256>>>(cand, clk, emb, conv_w, conv_b);
    gemm_qxv_kernel<<<dim3(NCAT / 64, (NUROWS + 127) / 128), 256>>>();
    attn_kernel<<<dim3(4, NSEQ), 256, ATTN_SMEM_BYTES>>>();
    gemm_wordk_kernel<<<dim3((NQD + 63) / 64, (MVAL + 127) / 128), 256>>>(Wk, bk);
    word_kernel<<<NSEQ, 256>>>(qw);
    final_kernel<<<NB, 256>>>(Wl, bl, out);
}

// round 9
// speedup vs baseline: 3.0655x; 1.4938x over previous
#include <cuda_runtime.h>
#include <cuda_bf16.h>
#include <math.h>
#include <stdint.h>

#define NB 16
#define NCDD 5
#define NHIS 50
#define NS 20
#define NT 41
#define NE 300
#define NF 256
#define NH 16
#define NDV 16
#define NQD 200
#define NSEQ 4000
#define NUROWS 21600
#define MID_BASE 17600
#define MVAL 164000
#define SCALE_F 0.057735026918962576f

// -------- static device scratch (no allocations) --------
__device__ __nv_bfloat16 g_xub[NUROWS * NF];                 // conv out, bf16
__device__ __nv_bfloat16 g_WcatTb[4352 * 256];               // [n][k] = [Wq|Wv] transposed
__device__ float g_bcat[4352];
__device__ __nv_bfloat16 g_WkTb[200 * 256];                  // [n][k] = Wk^T
__device__ __nv_bfloat16 g_qb[(size_t)NUROWS * 4096];        // q, bf16
__device__ float g_xv[(size_t)NUROWS * 256];                 // xv, fp32
__device__ float g_val[(size_t)MVAL * NF];
__device__ __nv_bfloat16 g_valb[(size_t)MVAL * NF];
__device__ float g_kbuf[(size_t)MVAL * NQD];
__device__ float g_rep[(size_t)NSEQ * NF];

// -------- kernel 0: pack transposed bf16 weights + bias --------
__global__ void prep_kernel(const float* __restrict__ Wq, const float* __restrict__ bq,
                            const float* __restrict__ Wv, const float* __restrict__ bv,
                            const float* __restrict__ Wk) {
    int idx = blockIdx.x * 256 + threadIdx.x;
    if (idx < 4352 * 256) {
        int nn = idx >> 8, k = idx & 255;
        float w;
        if (nn < 4096) {
            int h = nn >> 8, g = nn & 255;
            w = Wq[(h * 256 + k) * 256 + g];
        } else {
            int jj = nn - 4096;
            int h = jj >> 4, d = jj & 15;
            w = Wv[(h * 256 + k) * 16 + d];
        }
        g_WcatTb[idx] = __float2bfloat16(w);
    }
    if (idx < 200 * 256) {
        int nn = idx >> 8, k = idx & 255;
        g_WkTb[idx] = __float2bfloat16(Wk[k * 200 + nn]);
    }
    if (idx < 4352) {
        if (idx < 4096) {
            int h = idx >> 8, g = idx & 255;
            g_bcat[idx] = bq[h * 256 + g];
        } else {
            g_bcat[idx] = bv[idx - 4096]; // bv folds through softmax (rows sum to 1)
        }
    }
}

// -------- kernel 1: conv1d(k=3, SAME) + ReLU over 21600 unique rows, bf16 out --------
__global__ void __launch_bounds__(256) conv_kernel(const int* __restrict__ cand,
                                                   const int* __restrict__ clk,
                                                   const float* __restrict__ emb,
                                                   const float* __restrict__ cw,
                                                   const float* __restrict__ cb) {
    __shared__ float se[12 * 900];
    __shared__ int st[12][3];
    int row0 = blockIdx.x * 12;
    int tid = threadIdx.x;
    if (tid < 12) {
        int row = row0 + tid;
        int t0, t1, t2;
        if (row < 1600) {
            int bc = row / 20, t = row - bc * 20;
            const int* ct = cand + bc * 20;
            t0 = (t - 1 >= 0) ? ct[t - 1] : -1;
            t1 = ct[t];
            t2 = (t + 1 < 20) ? ct[t + 1] : 1;
        } else if (row < MID_BASE) {
            int r2 = row - 1600;
            int bh = r2 / 20, tt = r2 - bh * 20;
            const int* ht = clk + bh * 20;
            t0 = (tt == 0) ? 1 : ht[tt - 1];
            t1 = ht[tt];
            t2 = (tt + 1 < 20) ? ht[tt + 1] : -1;
        } else {
            int nn = row - MID_BASE;
            int b = nn / 250, rr = nn - b * 250;
            int c = rr / 50, hh = rr - c * 50;
            t0 = cand[(b * 5 + c) * 20 + 19];
            t1 = 1;
            t2 = clk[(b * 50 + hh) * 20 + 0];
        }
        st[tid][0] = t0; st[tid][1] = t1; st[tid][2] = t2;
    }
    __syncthreads();
    for (int idx = tid; idx < 12 * 900; idx += 256) {
        int r = idx / 900;
        int rem = idx - r * 900;
        int w = rem / 300;
        int e = rem - w * 300;
        int tok = st[r][w];
        se[idx] = (tok < 0) ? 0.f : emb[(size_t)tok * NE + e];
    }
    __syncthreads();
    int f = tid;
    float cbf = cb[f];
    float acc[12];
#pragma unroll
    for (int r = 0; r < 12; ++r) acc[r] = cbf;
    for (int we = 0; we < 900; we += 4) {
        float w0 = cw[(we + 0) * 256 + f];
        float w1 = cw[(we + 1) * 256 + f];
        float w2 = cw[(we + 2) * 256 + f];
        float w3 = cw[(we + 3) * 256 + f];
#pragma unroll
        for (int r = 0; r < 12; ++r) {
            float4 a = *(const float4*)(se + r * 900 + we);
            acc[r] = fmaf(a.x, w0, acc[r]);
            acc[r] = fmaf(a.y, w1, acc[r]);
            acc[r] = fmaf(a.z, w2, acc[r]);
            acc[r] = fmaf(a.w, w3, acc[r]);
        }
    }
#pragma unroll
    for (int r = 0; r < 12; ++r)
        g_xub[(size_t)(row0 + r) * NF + f] = __float2bfloat16(fmaxf(acc[r], 0.f));
}

// -------- bf16 tensor-core GEMM, K=256: C = A @ B^T_storage + bias --------
// A: [M][256] bf16 row-major; Bt: [N][256] bf16 (n-major);
// MODE 0: n<4096 -> g_qb bf16; n>=4096 -> g_xv fp32.  MODE 1: tanh -> g_kbuf fp32 (N=200).
template <int MODE>
__global__ void __launch_bounds__(256, 2) gemm_mma_kernel(const __nv_bfloat16* __restrict__ Ag,
                                                          const __nv_bfloat16* __restrict__ Bt,
                                                          const float* __restrict__ bias,
                                                          int M, int N) {
    __shared__ __nv_bfloat16 As[128 * 56];
    __shared__ __nv_bfloat16 Bs[128 * 56];
    int tid = threadIdx.x;
    int w = tid >> 5, lane = tid & 31;
    int wm = w >> 2, wn = w & 3;           // 2x4 warp grid -> 64m x 32n per warp
    int m0 = blockIdx.y * 128;
    int n0 = blockIdx.x * 128;

    uint32_t As_u = (uint32_t)__cvta_generic_to_shared(As);
    uint32_t Bs_u = (uint32_t)__cvta_generic_to_shared(Bs);

    float acc[4][4][4];
#pragma unroll
    for (int i = 0; i < 4; ++i)
#pragma unroll
        for (int j = 0; j < 4; ++j)
#pragma unroll
            for (int e = 0; e < 4; ++e) acc[i][j][e] = 0.f;

    for (int kc = 0; kc < 256; kc += 32) {
        __syncthreads();
        for (int i = tid; i < 1024; i += 256) {
            int r = (i >> 2) & 127;
            int kq = i & 3;
            uint4 v = make_uint4(0, 0, 0, 0);
            if (i < 512) {
                int m = m0 + r;
                if (m < M) v = *(const uint4*)(Ag + (size_t)m * 256 + kc + kq * 8);
                *(uint4*)(As + r * 56 + kq * 8) = v;
            } else {
                int nn = n0 + r;
                if (nn < N) v = *(const uint4*)(Bt + (size_t)nn * 256 + kc + kq * 8);
                *(uint4*)(Bs + r * 56 + kq * 8) = v;
            }
        }
        __syncthreads();
#pragma unroll
        for (int ks = 0; ks < 2; ++ks) {
            uint32_t a[4][4], b[4][2];
#pragma unroll
            for (int i = 0; i < 4; ++i) {
                uint32_t addr = As_u +
                    (uint32_t)(((wm * 64 + i * 16 + (lane & 15)) * 56 + ks * 16 + (lane >> 4) * 8) * 2);
                asm volatile("ldmatrix.sync.aligned.m8n8.x4.shared.b16 {%0,%1,%2,%3}, [%4];"
                    : "=r"(a[i][0]), "=r"(a[i][1]), "=r"(a[i][2]), "=r"(a[i][3]) : "r"(addr));
            }
#pragma unroll
            for (int j = 0; j < 4; ++j) {
                int nr = wn * 32 + j * 8 + (lane & 7);
                uint32_t addr = Bs_u +
                    (uint32_t)((nr * 56 + ks * 16 + ((lane >> 3) & 1) * 8) * 2);
                asm volatile("ldmatrix.sync.aligned.m8n8.x2.shared.b16 {%0,%1}, [%2];"
                    : "=r"(b[j][0]), "=r"(b[j][1]) : "r"(addr));
            }
#pragma unroll
            for (int i = 0; i < 4; ++i)
#pragma unroll
                for (int j = 0; j < 4; ++j)
                    asm volatile(
                        "mma.sync.aligned.m16n8k16.row.col.f32.bf16.bf16.f32 "
                        "{%0,%1,%2,%3}, {%4,%5,%6,%7}, {%8,%9}, {%0,%1,%2,%3};"
                        : "+f"(acc[i][j][0]), "+f"(acc[i][j][1]),
                          "+f"(acc[i][j][2]), "+f"(acc[i][j][3])
                        : "r"(a[i][0]), "r"(a[i][1]), "r"(a[i][2]), "r"(a[i][3]),
                          "r"(b[j][0]), "r"(b[j][1]));
        }
    }

    int gid = lane >> 2;
#pragma unroll
    for (int i = 0; i < 4; ++i) {
#pragma unroll
        for (int j = 0; j < 4; ++j) {
            int c0 = n0 + wn * 32 + j * 8 + (lane & 3) * 2;
            float b0 = 0.f, b1 = 0.f;
            if (MODE == 0 || c0 + 1 < N) { b0 = bias[c0]; b1 = bias[c0 + 1]; }
            else if (c0 < N) b0 = bias[c0];
#pragma unroll
            for (int half = 0; half < 2; ++half) {
                int m = m0 + wm * 64 + i * 16 + gid + half * 8;
                if (m >= M) continue;
                float v0 = acc[i][j][half * 2 + 0] + b0;
                float v1 = acc[i][j][half * 2 + 1] + b1;
                if (MODE == 0) {
                    if (c0 < 4096) {
                        __nv_bfloat162 p = __floats2bfloat162_rn(v0, v1);
                        *(uint32_t*)(g_qb + (size_t)m * 4096 + c0) = *(uint32_t*)&p;
                    } else {
                        *(float2*)(g_xv + (size_t)m * 256 + (c0 - 4096)) =
                            make_float2(v0, v1);
                    }
                } else {
                    if (c0 < N) g_kbuf[(size_t)m * NQD + c0] = tanhf(v0);
                    if (c0 + 1 < N) g_kbuf[(size_t)m * NQD + c0 + 1] = tanhf(v1);
                }
            }
        }
    }
}

// -------- kernel 3: attention, block = (4 heads, 1 seq); scores via bf16 mma.sync --------
// smem bytes: xb 48*72*2=6912 | qb 4x6912=27648 | scm 4*1804*4=28864 | xv 4*656*4=10496 = 73920
#define ATTN_SMEM_BYTES 73920

__global__ void __launch_bounds__(256, 3) attn_kernel() {
    extern __shared__ float sm[];
    __nv_bfloat16* xb = (__nv_bfloat16*)sm;
    __nv_bfloat16* qbA = (__nv_bfloat16*)(sm + 1728);
    float* scA = sm + 1728 + 6912;
    float* xvA = sm + 1728 + 6912 + 7216;
    __shared__ int rows[41];

    int n = blockIdx.y;
    int hb = blockIdx.x;
    int tid = threadIdx.x;
    int g = tid >> 6;
    int l = tid & 63;
    int w = l >> 5;
    int lane = l & 31;
    int h = hb * 4 + g;

    __nv_bfloat16* qb = qbA + g * 3456;
    float* scm = scA + g * 1804;
    float* xvg = xvA + g * 656;

    uint32_t xb_u = (uint32_t)__cvta_generic_to_shared(xb);
    uint32_t qb_u = (uint32_t)__cvta_generic_to_shared(qb);

    if (tid < 41) {
        int b = n / 250, rr = n - b * 250;
        int c = rr / 50, hh = rr - c * 50;
        int t = tid, r;
        if (t < 20)       r = (b * 5 + c) * 20 + t;
        else if (t == 20) r = MID_BASE + n;
        else              r = 1600 + (b * 50 + hh) * 20 + (t - 21);
        rows[t] = r;
    }
    __syncthreads();

    for (int i = l; i < 164; i += 64) {
        int t = i >> 2, qd = i & 3;
        *(float4*)(xvg + t * 16 + qd * 4) =
            *(const float4*)(g_xv + (size_t)rows[t] * 256 + h * 16 + qd * 4);
    }

    float acc[3][3][4];
#pragma unroll
    for (int i = 0; i < 3; ++i)
#pragma unroll
        for (int j = 0; j < 3; ++j)
#pragma unroll
            for (int e = 0; e < 4; ++e) acc[i][j][e] = 0.f;

    for (int kc = 0; kc < 256; kc += 64) {
        __syncthreads();
        // stage x chunk (whole block): bf16 direct copies
        for (int i = tid; i < 656; i += 256) {
            int t = i >> 4, kq = i & 15;
            *(uint2*)(xb + t * 72 + kq * 4) =
                *(const uint2*)(g_xub + (size_t)rows[t] * 256 + kc + kq * 4);
        }
        // stage q chunk (per group)
        for (int i = l; i < 656; i += 64) {
            int t = i >> 4, kq = i & 15;
            *(uint2*)(qb + t * 72 + kq * 4) =
                *(const uint2*)(g_qb + (size_t)rows[t] * 4096 + h * 256 + kc + kq * 4);
        }
        __syncthreads();
#pragma unroll
        for (int ks = 0; ks < 4; ++ks) {
            uint32_t a[3][4], b[3][2];
#pragma unroll
            for (int i = 0; i < 3; ++i) {
                uint32_t addr = qb_u +
                    (uint32_t)(((i * 16 + (lane & 15)) * 72 + ks * 16 + (lane >> 4) * 8) * 2);
                asm volatile("ldmatrix.sync.aligned.m8n8.x4.shared.b16 {%0,%1,%2,%3}, [%4];"
                    : "=r"(a[i][0]), "=r"(a[i][1]), "=r"(a[i][2]), "=r"(a[i][3]) : "r"(addr));
            }
#pragma unroll
            for (int j = 0; j < 3; ++j) {
                int nr = w * 24 + j * 8 + (lane & 7);
                uint32_t addr = xb_u +
                    (uint32_t)((nr * 72 + ks * 16 + ((lane >> 3) & 1) * 8) * 2);
                asm volatile("ldmatrix.sync.aligned.m8n8.x2.shared.b16 {%0,%1}, [%2];"
                    : "=r"(b[j][0]), "=r"(b[j][1]) : "r"(addr));
            }
#pragma unroll
            for (int i = 0; i < 3; ++i)
#pragma unroll
                for (int j = 0; j < 3; ++j)
                    asm volatile(
                        "mma.sync.aligned.m16n8k16.row.col.f32.bf16.bf16.f32 "
                        "{%0,%1,%2,%3}, {%4,%5,%6,%7}, {%8,%9}, {%0,%1,%2,%3};"
                        : "+f"(acc[i][j][0]), "+f"(acc[i][j][1]),
                          "+f"(acc[i][j][2]), "+f"(acc[i][j][3])
                        : "r"(a[i][0]), "r"(a[i][1]), "r"(a[i][2]), "r"(a[i][3]),
                          "r"(b[j][0]), "r"(b[j][1]));
        }
    }

    {
        int gid = lane >> 2, t4 = lane & 3;
#pragma unroll
        for (int i = 0; i < 3; ++i) {
#pragma unroll
            for (int j = 0; j < 3; ++j) {
                int c0 = w * 24 + j * 8 + t4 * 2;
                int r0 = i * 16 + gid;
                if (r0 < 41) {
                    if (c0 < 41) scm[r0 * 44 + c0] = acc[i][j][0] * SCALE_F;
                    if (c0 + 1 < 41) scm[r0 * 44 + c0 + 1] = acc[i][j][1] * SCALE_F;
                }
                int r1 = r0 + 8;
                if (r1 < 41) {
                    if (c0 < 41) scm[r1 * 44 + c0] = acc[i][j][2] * SCALE_F;
                    if (c0 + 1 < 41) scm[r1 * 44 + c0 + 1] = acc[i][j][3] * SCALE_F;
                }
            }
        }
    }
    __syncthreads();

    for (int t = w; t < 41; t += 2) {
        float v0 = (lane < 41) ? scm[t * 44 + lane] : -1e30f;
        float v1 = (lane + 32 < 41) ? scm[t * 44 + lane + 32] : -1e30f;
        float m = fmaxf(v0, v1);
#pragma unroll
        for (int o = 16; o; o >>= 1) m = fmaxf(m, __shfl_xor_sync(0xffffffffu, m, o));
        float e0 = (lane < 41) ? __expf(v0 - m) : 0.f;
        float e1 = (lane + 32 < 41) ? __expf(v1 - m) : 0.f;
        float s = e0 + e1;
#pragma unroll
        for (int o = 16; o; o >>= 1) s += __shfl_xor_sync(0xffffffffu, s, o);
        float inv = 1.f / s;
        if (lane < 41) scm[t * 44 + lane] = e0 * inv;
        if (lane + 32 < 41) scm[t * 44 + lane + 32] = e1 * inv;
    }
    __syncthreads();

    for (int i = l; i < 656; i += 64) {
        int t = i >> 4, d = i & 15;
        float a = 0.f;
#pragma unroll 8
        for (int s = 0; s < 41; ++s) a = fmaf(scm[t * 44 + s], xvg[s * 16 + d], a);
        size_t o = ((size_t)n * 41 + t) * 256 + h * 16 + d;
        g_val[o] = a;
        g_valb[o] = __float2bfloat16(a);
    }
}

// -------- kernel 5: word attention per sequence --------
__global__ void __launch_bounds__(256) word_kernel(const float* __restrict__ qw) {
    __shared__ float sqw[200];
    __shared__ float sl[41];
    int n = blockIdx.x;
    int tid = threadIdx.x;
    if (tid < 200) sqw[tid] = qw[tid];
    __syncthreads();
    int warp = tid >> 5, lane = tid & 31;
    for (int t = warp; t < 41; t += 8) {
        const float* kr = g_kbuf + ((size_t)n * 41 + t) * 200;
        float s = 0.f;
        for (int e = lane; e < 200; e += 32) s = fmaf(kr[e], sqw[e], s);
#pragma unroll
        for (int o = 16; o; o >>= 1) s += __shfl_xor_sync(0xffffffffu, s, o);
        if (lane == 0) sl[t] = s * SCALE_F;
    }
    __syncthreads();
    if (tid < 32) {
        float v0 = (tid < 41) ? sl[tid] : -1e30f;
        float v1 = (tid + 32 < 41) ? sl[tid + 32] : -1e30f;
        float m = fmaxf(v0, v1);
#pragma unroll
        for (int o = 16; o; o >>= 1) m = fmaxf(m, __shfl_xor_sync(0xffffffffu, m, o));
        float e0 = (tid < 41) ? expf(v0 - m) : 0.f;
        float e1 = (tid + 32 < 41) ? expf(v1 - m) : 0.f;
        float s = e0 + e1;
#pragma unroll
        for (int o = 16; o; o >>= 1) s += __shfl_xor_sync(0xffffffffu, s, o);
        float inv = 1.f / s;
        if (tid < 41) sl[tid] = e0 * inv;
        if (tid + 32 < 41) sl[tid + 32] = e1 * inv;
    }
    __syncthreads();
    float acc = 0.f;
    const float* vr = g_val + (size_t)n * 41 * 256 + tid;
#pragma unroll 8
    for (int t = 0; t < 41; ++t) acc = fmaf(sl[t], vr[(size_t)t * 256], acc);
    g_rep[(size_t)n * 256 + tid] = acc;
}

// -------- kernel 6: mean over HIS, rank score, log-softmax over CDD --------
__global__ void __launch_bounds__(256) final_kernel(const float* __restrict__ Wl,
                                                    const float* __restrict__ blp,
                                                    float* __restrict__ out) {
    __shared__ float red[8];
    __shared__ float sc[5];
    int b = blockIdx.x;
    int tid = threadIdx.x;
    float wl = Wl[tid];
    for (int c = 0; c < 5; ++c) {
        const float* rp = g_rep + ((size_t)(b * 5 + c) * 50) * 256 + tid;
        float s = 0.f;
        for (int h = 0; h < 50; ++h) s += rp[(size_t)h * 256];
        s *= wl;
#pragma unroll
        for (int o = 16; o; o >>= 1) s += __shfl_xor_sync(0xffffffffu, s, o);
        if ((tid & 31) == 0) red[tid >> 5] = s;
        __syncthreads();
        if (tid < 8) {
            float v = red[tid];
#pragma unroll
            for (int o = 4; o; o >>= 1) v += __shfl_xor_sync(0xffu, v, o, 8);
            if (tid == 0) sc[c] = v * (1.f / 50.f) + blp[0];
        }
        __syncthreads();
    }
    if (tid == 0) {
        float m = sc[0];
        for (int c = 1; c < 5; ++c) m = fmaxf(m, sc[c]);
        float s = 0.f;
        for (int c = 0; c < 5; ++c) s += expf(sc[c] - m);
        float ls = logf(s);
        for (int c = 0; c < 5; ++c) out[b * 5 + c] = sc[c] - m - ls;
    }
}

// -------- host launcher --------
extern "C" void kernel_launch(void* const* d_in, const int* in_sizes, int n_in,
                              void* d_out, int out_size) {
    const int* cand = (const int*)d_in[0];
    const int* clk = (const int*)d_in[1];
    const float* emb = (const float*)d_in[2];
    const float* conv_w = (const float*)d_in[3];
    const float* conv_b = (const float*)d_in[4];
    const float* Wq = (const float*)d_in[5];
    const float* bq = (const float*)d_in[6];
    const float* Wv = (const float*)d_in[7];
    const float* bv = (const float*)d_in[8];
    const float* Wk = (const float*)d_in[9];
    const float* bk = (const float*)d_in[10];
    const float* qw = (const float*)d_in[11];
    const float* Wl = (const float*)d_in[12];
    const float* bl = (const float*)d_in[13];
    float* out = (float*)d_out;

    cudaFuncSetAttribute(attn_kernel, cudaFuncAttributeMaxDynamicSharedMemorySize,
                         ATTN_SMEM_BYTES);

    // device symbol addresses for GEMM operands
    static const __nv_bfloat16* h_xub = nullptr;
    static const __nv_bfloat16* h_WcatTb = nullptr;
    static const __nv_bfloat16* h_WkTb = nullptr;
    static const __nv_bfloat16* h_valb = nullptr;
    static const float* h_bcat = nullptr;
    if (!h_xub) {
        void* p;
        cudaGetSymbolAddress(&p, g_xub);    h_xub = (const __nv_bfloat16*)p;
        cudaGetSymbolAddress(&p, g_WcatTb); h_WcatTb = (const __nv_bfloat16*)p;
        cudaGetSymbolAddress(&p, g_WkTb);   h_WkTb = (const __nv_bfloat16*)p;
        cudaGetSymbolAddress(&p, g_valb);   h_valb = (const __nv_bfloat16*)p;
        cudaGetSymbolAddress(&p, g_bcat);   h_bcat = (const float*)p;
    }

    prep_kernel<<<4352, 256>>>(Wq, bq, Wv, bv, Wk);
    conv_kernel<<<NUROWS / 12, 256>>>(cand, clk, emb, conv_w, conv_b);
    gemm_mma_kernel<0><<<dim3(34, (NUROWS + 127) / 128), 256>>>(h_xub, h_WcatTb, h_bcat,
                                                                NUROWS, 4352);
    attn_kernel<<<dim3(4, NSEQ), 256, ATTN_SMEM_BYTES>>>();
    gemm_mma_kernel<1><<<dim3(2, (MVAL + 127) / 128), 256>>>(h_valb, h_WkTb, bk,
                                                             MVAL, NQD);
    word_kernel<<<NSEQ, 256>>>(qw);
    final_kernel<<<NB, 256>>>(Wl, bl, out);
}

// round 10
// speedup vs baseline: 3.6376x; 1.1866x over previous
#include <cuda_runtime.h>
#include <cuda_bf16.h>
#include <math.h>
#include <stdint.h>

#define NB 16
#define NCDD 5
#define NHIS 50
#define NS 20
#define NT 41
#define NE 300
#define NF 256
#define NH 16
#define NDV 16
#define NQD 200
#define NSEQ 4000
#define NUROWS 21600
#define MID_BASE 17600
#define MVAL 164000
#define SCALE_F 0.057735026918962576f

// -------- static device scratch (no allocations) --------
__device__ __nv_bfloat16 g_xub[NUROWS * NF];
__device__ __nv_bfloat16 g_WcatTb[4352 * 256];
__device__ float g_bcat[4352];
__device__ __nv_bfloat16 g_WkTb[200 * 256];
__device__ __nv_bfloat16 g_qb[(size_t)NUROWS * 4096];
__device__ float g_xv[(size_t)NUROWS * 256];
__device__ float g_val[(size_t)MVAL * NF];
__device__ __nv_bfloat16 g_valb[(size_t)MVAL * NF];
__device__ float g_kbuf[(size_t)MVAL * NQD];
__device__ float g_rep[(size_t)NSEQ * NF];

// -------- kernel 0: pack transposed bf16 weights + bias --------
__global__ void prep_kernel(const float* __restrict__ Wq, const float* __restrict__ bq,
                            const float* __restrict__ Wv, const float* __restrict__ bv,
                            const float* __restrict__ Wk) {
    int idx = blockIdx.x * 256 + threadIdx.x;
    if (idx < 4352 * 256) {
        int nn = idx >> 8, k = idx & 255;
        float w;
        if (nn < 4096) {
            int h = nn >> 8, g = nn & 255;
            w = Wq[(h * 256 + k) * 256 + g];
        } else {
            int jj = nn - 4096;
            int h = jj >> 4, d = jj & 15;
            w = Wv[(h * 256 + k) * 16 + d];
        }
        g_WcatTb[idx] = __float2bfloat16(w);
    }
    if (idx < 200 * 256) {
        int nn = idx >> 8, k = idx & 255;
        g_WkTb[idx] = __float2bfloat16(Wk[k * 200 + nn]);
    }
    if (idx < 4352) {
        if (idx < 4096) {
            int h = idx >> 8, g = idx & 255;
            g_bcat[idx] = bq[h * 256 + g];
        } else {
            g_bcat[idx] = bv[idx - 4096]; // bv folds through softmax (rows sum to 1)
        }
    }
}

// -------- kernel 1: conv1d(k=3, SAME) + ReLU over 21600 unique rows, bf16 out --------
__global__ void __launch_bounds__(256) conv_kernel(const int* __restrict__ cand,
                                                   const int* __restrict__ clk,
                                                   const float* __restrict__ emb,
                                                   const float* __restrict__ cw,
                                                   const float* __restrict__ cb) {
    __shared__ float se[12 * 900];
    __shared__ int st[12][3];
    int row0 = blockIdx.x * 12;
    int tid = threadIdx.x;
    if (tid < 12) {
        int row = row0 + tid;
        int t0, t1, t2;
        if (row < 1600) {
            int bc = row / 20, t = row - bc * 20;
            const int* ct = cand + bc * 20;
            t0 = (t - 1 >= 0) ? ct[t - 1] : -1;
            t1 = ct[t];
            t2 = (t + 1 < 20) ? ct[t + 1] : 1;
        } else if (row < MID_BASE) {
            int r2 = row - 1600;
            int bh = r2 / 20, tt = r2 - bh * 20;
            const int* ht = clk + bh * 20;
            t0 = (tt == 0) ? 1 : ht[tt - 1];
            t1 = ht[tt];
            t2 = (tt + 1 < 20) ? ht[tt + 1] : -1;
        } else {
            int nn = row - MID_BASE;
            int b = nn / 250, rr = nn - b * 250;
            int c = rr / 50, hh = rr - c * 50;
            t0 = cand[(b * 5 + c) * 20 + 19];
            t1 = 1;
            t2 = clk[(b * 50 + hh) * 20 + 0];
        }
        st[tid][0] = t0; st[tid][1] = t1; st[tid][2] = t2;
    }
    __syncthreads();
    for (int idx = tid; idx < 12 * 900; idx += 256) {
        int r = idx / 900;
        int rem = idx - r * 900;
        int w = rem / 300;
        int e = rem - w * 300;
        int tok = st[r][w];
        se[idx] = (tok < 0) ? 0.f : emb[(size_t)tok * NE + e];
    }
    __syncthreads();
    int f = tid;
    float cbf = cb[f];
    float acc[12];
#pragma unroll
    for (int r = 0; r < 12; ++r) acc[r] = cbf;
    for (int we = 0; we < 900; we += 4) {
        float w0 = cw[(we + 0) * 256 + f];
        float w1 = cw[(we + 1) * 256 + f];
        float w2 = cw[(we + 2) * 256 + f];
        float w3 = cw[(we + 3) * 256 + f];
#pragma unroll
        for (int r = 0; r < 12; ++r) {
            float4 a = *(const float4*)(se + r * 900 + we);
            acc[r] = fmaf(a.x, w0, acc[r]);
            acc[r] = fmaf(a.y, w1, acc[r]);
            acc[r] = fmaf(a.z, w2, acc[r]);
            acc[r] = fmaf(a.w, w3, acc[r]);
        }
    }
#pragma unroll
    for (int r = 0; r < 12; ++r)
        g_xub[(size_t)(row0 + r) * NF + f] = __float2bfloat16(fmaxf(acc[r], 0.f));
}

// -------- bf16 tensor-core GEMM, K=256, register-prefetch double buffered --------
// MODE 0: n<4096 -> g_qb bf16; n>=4096 -> g_xv fp32.  MODE 1: tanh -> g_kbuf fp32.
template <int MODE>
__global__ void __launch_bounds__(256, 2) gemm_mma_kernel(const __nv_bfloat16* __restrict__ Ag,
                                                          const __nv_bfloat16* __restrict__ Bt,
                                                          const float* __restrict__ bias,
                                                          int M, int N) {
    __shared__ __nv_bfloat16 As[128 * 56];
    __shared__ __nv_bfloat16 Bs[128 * 56];
    int tid = threadIdx.x;
    int w = tid >> 5, lane = tid & 31;
    int wm = w >> 2, wn = w & 3;
    int m0 = blockIdx.y * 128;
    int n0 = blockIdx.x * 128;

    uint32_t As_u = (uint32_t)__cvta_generic_to_shared(As);
    uint32_t Bs_u = (uint32_t)__cvta_generic_to_shared(Bs);

    float acc[4][4][4];
#pragma unroll
    for (int i = 0; i < 4; ++i)
#pragma unroll
        for (int j = 0; j < 4; ++j)
#pragma unroll
            for (int e = 0; e < 4; ++e) acc[i][j][e] = 0.f;

    uint4 pre[4];
#pragma unroll
    for (int j = 0; j < 4; ++j) {
        int i = tid + j * 256;
        int r = (i >> 2) & 127;
        int kq = i & 3;
        uint4 v = make_uint4(0, 0, 0, 0);
        if (i < 512) {
            int m = m0 + r;
            if (m < M) v = *(const uint4*)(Ag + (size_t)m * 256 + kq * 8);
        } else {
            int nn = n0 + r;
            if (nn < N) v = *(const uint4*)(Bt + (size_t)nn * 256 + kq * 8);
        }
        pre[j] = v;
    }

    for (int kc = 0; kc < 256; kc += 32) {
        __syncthreads();
#pragma unroll
        for (int j = 0; j < 4; ++j) {
            int i = tid + j * 256;
            int r = (i >> 2) & 127;
            int kq = i & 3;
            if (i < 512) *(uint4*)(As + r * 56 + kq * 8) = pre[j];
            else         *(uint4*)(Bs + r * 56 + kq * 8) = pre[j];
        }
        __syncthreads();
        if (kc + 32 < 256) {
            int kn = kc + 32;
#pragma unroll
            for (int j = 0; j < 4; ++j) {
                int i = tid + j * 256;
                int r = (i >> 2) & 127;
                int kq = i & 3;
                uint4 v = make_uint4(0, 0, 0, 0);
                if (i < 512) {
                    int m = m0 + r;
                    if (m < M) v = *(const uint4*)(Ag + (size_t)m * 256 + kn + kq * 8);
                } else {
                    int nn = n0 + r;
                    if (nn < N) v = *(const uint4*)(Bt + (size_t)nn * 256 + kn + kq * 8);
                }
                pre[j] = v;
            }
        }
#pragma unroll
        for (int ks = 0; ks < 2; ++ks) {
            uint32_t a[4][4], b[4][2];
#pragma unroll
            for (int i = 0; i < 4; ++i) {
                uint32_t addr = As_u +
                    (uint32_t)(((wm * 64 + i * 16 + (lane & 15)) * 56 + ks * 16 + (lane >> 4) * 8) * 2);
                asm volatile("ldmatrix.sync.aligned.m8n8.x4.shared.b16 {%0,%1,%2,%3}, [%4];"
                    : "=r"(a[i][0]), "=r"(a[i][1]), "=r"(a[i][2]), "=r"(a[i][3]) : "r"(addr));
            }
#pragma unroll
            for (int j = 0; j < 4; ++j) {
                int nr = wn * 32 + j * 8 + (lane & 7);
                uint32_t addr = Bs_u +
                    (uint32_t)((nr * 56 + ks * 16 + ((lane >> 3) & 1) * 8) * 2);
                asm volatile("ldmatrix.sync.aligned.m8n8.x2.shared.b16 {%0,%1}, [%2];"
                    : "=r"(b[j][0]), "=r"(b[j][1]) : "r"(addr));
            }
#pragma unroll
            for (int i = 0; i < 4; ++i)
#pragma unroll
                for (int j = 0; j < 4; ++j)
                    asm volatile(
                        "mma.sync.aligned.m16n8k16.row.col.f32.bf16.bf16.f32 "
                        "{%0,%1,%2,%3}, {%4,%5,%6,%7}, {%8,%9}, {%0,%1,%2,%3};"
                        : "+f"(acc[i][j][0]), "+f"(acc[i][j][1]),
                          "+f"(acc[i][j][2]), "+f"(acc[i][j][3])
                        : "r"(a[i][0]), "r"(a[i][1]), "r"(a[i][2]), "r"(a[i][3]),
                          "r"(b[j][0]), "r"(b[j][1]));
        }
    }

    int gid = lane >> 2;
#pragma unroll
    for (int i = 0; i < 4; ++i) {
#pragma unroll
        for (int j = 0; j < 4; ++j) {
            int c0 = n0 + wn * 32 + j * 8 + (lane & 3) * 2;
            float b0 = 0.f, b1 = 0.f;
            if (MODE == 0 || c0 + 1 < N) { b0 = bias[c0]; b1 = bias[c0 + 1]; }
            else if (c0 < N) b0 = bias[c0];
#pragma unroll
            for (int half = 0; half < 2; ++half) {
                int m = m0 + wm * 64 + i * 16 + gid + half * 8;
                if (m >= M) continue;
                float v0 = acc[i][j][half * 2 + 0] + b0;
                float v1 = acc[i][j][half * 2 + 1] + b1;
                if (MODE == 0) {
                    if (c0 < 4096) {
                        __nv_bfloat162 p = __floats2bfloat162_rn(v0, v1);
                        *(uint32_t*)(g_qb + (size_t)m * 4096 + c0) = *(uint32_t*)&p;
                    } else {
                        *(float2*)(g_xv + (size_t)m * 256 + (c0 - 4096)) =
                            make_float2(v0, v1);
                    }
                } else {
                    if (c0 < N) g_kbuf[(size_t)m * NQD + c0] = tanhf(v0);
                    if (c0 + 1 < N) g_kbuf[(size_t)m * NQD + c0 + 1] = tanhf(v1);
                }
            }
        }
    }
}

// -------- kernel 3: attention, block = (4 heads, 1 seq); scores via bf16 mma.sync --------
#define ATTN_SMEM_BYTES 73920

__global__ void __launch_bounds__(256, 3) attn_kernel() {
    extern __shared__ float sm[];
    __nv_bfloat16* xb = (__nv_bfloat16*)sm;
    __nv_bfloat16* qbA = (__nv_bfloat16*)(sm + 1728);
    float* scA = sm + 1728 + 6912;
    float* xvA = sm + 1728 + 6912 + 7216;
    __shared__ int rows[41];

    int n = blockIdx.y;
    int hb = blockIdx.x;
    int tid = threadIdx.x;
    int g = tid >> 6;
    int l = tid & 63;
    int w = l >> 5;
    int lane = l & 31;
    int h = hb * 4 + g;

    __nv_bfloat16* qb = qbA + g * 3456;
    float* scm = scA + g * 1804;
    float* xvg = xvA + g * 656;

    uint32_t xb_u = (uint32_t)__cvta_generic_to_shared(xb);
    uint32_t qb_u = (uint32_t)__cvta_generic_to_shared(qb);

    if (tid < 41) {
        int b = n / 250, rr = n - b * 250;
        int c = rr / 50, hh = rr - c * 50;
        int t = tid, r;
        if (t < 20)       r = (b * 5 + c) * 20 + t;
        else if (t == 20) r = MID_BASE + n;
        else              r = 1600 + (b * 50 + hh) * 20 + (t - 21);
        rows[t] = r;
    }
    __syncthreads();

    for (int i = l; i < 164; i += 64) {
        int t = i >> 2, qd = i & 3;
        *(float4*)(xvg + t * 16 + qd * 4) =
            *(const float4*)(g_xv + (size_t)rows[t] * 256 + h * 16 + qd * 4);
    }

    float acc[3][3][4];
#pragma unroll
    for (int i = 0; i < 3; ++i)
#pragma unroll
        for (int j = 0; j < 3; ++j)
#pragma unroll
            for (int e = 0; e < 4; ++e) acc[i][j][e] = 0.f;

    for (int kc = 0; kc < 256; kc += 64) {
        __syncthreads();
        // stage x chunk (whole block): 41 rows x 8 uint4
        for (int i = tid; i < 328; i += 256) {
            int t = i >> 3, kq = i & 7;
            *(uint4*)(xb + t * 72 + kq * 8) =
                *(const uint4*)(g_xub + (size_t)rows[t] * 256 + kc + kq * 8);
        }
        // stage q chunk (per group)
        for (int i = l; i < 328; i += 64) {
            int t = i >> 3, kq = i & 7;
            *(uint4*)(qb + t * 72 + kq * 8) =
                *(const uint4*)(g_qb + (size_t)rows[t] * 4096 + h * 256 + kc + kq * 8);
        }
        __syncthreads();
#pragma unroll
        for (int ks = 0; ks < 4; ++ks) {
            uint32_t a[3][4], b[3][2];
#pragma unroll
            for (int i = 0; i < 3; ++i) {
                uint32_t addr = qb_u +
                    (uint32_t)(((i * 16 + (lane & 15)) * 72 + ks * 16 + (lane >> 4) * 8) * 2);
                asm volatile("ldmatrix.sync.aligned.m8n8.x4.shared.b16 {%0,%1,%2,%3}, [%4];"
                    : "=r"(a[i][0]), "=r"(a[i][1]), "=r"(a[i][2]), "=r"(a[i][3]) : "r"(addr));
            }
#pragma unroll
            for (int j = 0; j < 3; ++j) {
                int nr = w * 24 + j * 8 + (lane & 7);
                uint32_t addr = xb_u +
                    (uint32_t)((nr * 72 + ks * 16 + ((lane >> 3) & 1) * 8) * 2);
                asm volatile("ldmatrix.sync.aligned.m8n8.x2.shared.b16 {%0,%1}, [%2];"
                    : "=r"(b[j][0]), "=r"(b[j][1]) : "r"(addr));
            }
#pragma unroll
            for (int i = 0; i < 3; ++i)
#pragma unroll
                for (int j = 0; j < 3; ++j)
                    asm volatile(
                        "mma.sync.aligned.m16n8k16.row.col.f32.bf16.bf16.f32 "
                        "{%0,%1,%2,%3}, {%4,%5,%6,%7}, {%8,%9}, {%0,%1,%2,%3};"
                        : "+f"(acc[i][j][0]), "+f"(acc[i][j][1]),
                          "+f"(acc[i][j][2]), "+f"(acc[i][j][3])
                        : "r"(a[i][0]), "r"(a[i][1]), "r"(a[i][2]), "r"(a[i][3]),
                          "r"(b[j][0]), "r"(b[j][1]));
        }
    }

    // write scores (vectorized pairs; c0+1<41 except c0=40)
    {
        int gid = lane >> 2, t4 = lane & 3;
#pragma unroll
        for (int i = 0; i < 3; ++i) {
#pragma unroll
            for (int j = 0; j < 3; ++j) {
                int c0 = w * 24 + j * 8 + t4 * 2;
                int r0 = i * 16 + gid;
                int r1 = r0 + 8;
                if (c0 + 1 < 41) {
                    if (r0 < 41) *(float2*)(scm + r0 * 44 + c0) =
                        make_float2(acc[i][j][0] * SCALE_F, acc[i][j][1] * SCALE_F);
                    if (r1 < 41) *(float2*)(scm + r1 * 44 + c0) =
                        make_float2(acc[i][j][2] * SCALE_F, acc[i][j][3] * SCALE_F);
                } else if (c0 < 41) {
                    if (r0 < 41) scm[r0 * 44 + c0] = acc[i][j][0] * SCALE_F;
                    if (r1 < 41) scm[r1 * 44 + c0] = acc[i][j][2] * SCALE_F;
                }
            }
        }
    }
    __syncthreads();

    for (int t = w; t < 41; t += 2) {
        float v0 = (lane < 41) ? scm[t * 44 + lane] : -1e30f;
        float v1 = (lane + 32 < 41) ? scm[t * 44 + lane + 32] : -1e30f;
        float m = fmaxf(v0, v1);
#pragma unroll
        for (int o = 16; o; o >>= 1) m = fmaxf(m, __shfl_xor_sync(0xffffffffu, m, o));
        float e0 = (lane < 41) ? __expf(v0 - m) : 0.f;
        float e1 = (lane + 32 < 41) ? __expf(v1 - m) : 0.f;
        float s = e0 + e1;
#pragma unroll
        for (int o = 16; o; o >>= 1) s += __shfl_xor_sync(0xffffffffu, s, o);
        float inv = 1.f / s;
        if (lane < 41) scm[t * 44 + lane] = e0 * inv;
        if (lane + 32 < 41) scm[t * 44 + lane + 32] = e1 * inv;
    }
    __syncthreads();

    // epilogue: work item = (t, d-quad); 164 items per group
    for (int i = l; i < 164; i += 64) {
        int t = i >> 2, dq = (i & 3) * 4;
        const float* pr = scm + t * 44;
        float ax = 0.f, ay = 0.f, az = 0.f, aw = 0.f;
#pragma unroll 8
        for (int s = 0; s < 41; ++s) {
            float p = pr[s];
            float4 xv4 = *(const float4*)(xvg + s * 16 + dq);
            ax = fmaf(p, xv4.x, ax);
            ay = fmaf(p, xv4.y, ay);
            az = fmaf(p, xv4.z, az);
            aw = fmaf(p, xv4.w, aw);
        }
        size_t o = ((size_t)n * 41 + t) * 256 + h * 16 + dq;
        *(float4*)(g_val + o) = make_float4(ax, ay, az, aw);
        __nv_bfloat162 p0 = __floats2bfloat162_rn(ax, ay);
        __nv_bfloat162 p1 = __floats2bfloat162_rn(az, aw);
        *(uint2*)(g_valb + o) = make_uint2(*(uint32_t*)&p0, *(uint32_t*)&p1);
    }
}

// -------- kernel 5: word attention per sequence --------
__global__ void __launch_bounds__(256) word_kernel(const float* __restrict__ qw) {
    __shared__ float sqw[200];
    __shared__ float sl[41];
    int n = blockIdx.x;
    int tid = threadIdx.x;
    if (tid < 200) sqw[tid] = qw[tid];
    __syncthreads();
    int warp = tid >> 5, lane = tid & 31;
    for (int t = warp; t < 41; t += 8) {
        const float* kr = g_kbuf + ((size_t)n * 41 + t) * 200;
        float s = 0.f;
        for (int e = lane; e < 200; e += 32) s = fmaf(kr[e], sqw[e], s);
#pragma unroll
        for (int o = 16; o; o >>= 1) s += __shfl_xor_sync(0xffffffffu, s, o);
        if (lane == 0) sl[t] = s * SCALE_F;
    }
    __syncthreads();
    if (tid < 32) {
        float v0 = (tid < 41) ? sl[tid] : -1e30f;
        float v1 = (tid + 32 < 41) ? sl[tid + 32] : -1e30f;
        float m = fmaxf(v0, v1);
#pragma unroll
        for (int o = 16; o; o >>= 1) m = fmaxf(m, __shfl_xor_sync(0xffffffffu, m, o));
        float e0 = (tid < 41) ? expf(v0 - m) : 0.f;
        float e1 = (tid + 32 < 41) ? expf(v1 - m) : 0.f;
        float s = e0 + e1;
#pragma unroll
        for (int o = 16; o; o >>= 1) s += __shfl_xor_sync(0xffffffffu, s, o);
        float inv = 1.f / s;
        if (tid < 41) sl[tid] = e0 * inv;
        if (tid + 32 < 41) sl[tid + 32] = e1 * inv;
    }
    __syncthreads();
    float acc = 0.f;
    const float* vr = g_val + (size_t)n * 41 * 256 + tid;
#pragma unroll 8
    for (int t = 0; t < 41; ++t) acc = fmaf(sl[t], vr[(size_t)t * 256], acc);
    g_rep[(size_t)n * 256 + tid] = acc;
}

// -------- kernel 6: mean over HIS, rank score, log-softmax over CDD --------
__global__ void __launch_bounds__(256) final_kernel(const float* __restrict__ Wl,
                                                    const float* __restrict__ blp,
                                                    float* __restrict__ out) {
    __shared__ float red[8];
    __shared__ float sc[5];
    int b = blockIdx.x;
    int tid = threadIdx.x;
    float wl = Wl[tid];
    for (int c = 0; c < 5; ++c) {
        const float* rp = g_rep + ((size_t)(b * 5 + c) * 50) * 256 + tid;
        float s = 0.f;
        for (int h = 0; h < 50; ++h) s += rp[(size_t)h * 256];
        s *= wl;
#pragma unroll
        for (int o = 16; o; o >>= 1) s += __shfl_xor_sync(0xffffffffu, s, o);
        if ((tid & 31) == 0) red[tid >> 5] = s;
        __syncthreads();
        if (tid < 8) {
            float v = red[tid];
#pragma unroll
            for (int o = 4; o; o >>= 1) v += __shfl_xor_sync(0xffu, v, o, 8);
            if (tid == 0) sc[c] = v * (1.f / 50.f) + blp[0];
        }
        __syncthreads();
    }
    if (tid == 0) {
        float m = sc[0];
        for (int c = 1; c < 5; ++c) m = fmaxf(m, sc[c]);
        float s = 0.f;
        for (int c = 0; c < 5; ++c) s += expf(sc[c] - m);
        float ls = logf(s);
        for (int c = 0; c < 5; ++c) out[b * 5 + c] = sc[c] - m - ls;
    }
}

// -------- host launcher --------
extern "C" void kernel_launch(void* const* d_in, const int* in_sizes, int n_in,
                              void* d_out, int out_size) {
    const int* cand = (const int*)d_in[0];
    const int* clk = (const int*)d_in[1];
    const float* emb = (const float*)d_in[2];
    const float* conv_w = (const float*)d_in[3];
    const float* conv_b = (const float*)d_in[4];
    const float* Wq = (const float*)d_in[5];
    const float* bq = (const float*)d_in[6];
    const float* Wv = (const float*)d_in[7];
    const float* bv = (const float*)d_in[8];
    const float* Wk = (const float*)d_in[9];
    const float* bk = (const float*)d_in[10];
    const float* qw = (const float*)d_in[11];
    const float* Wl = (const float*)d_in[12];
    const float* bl = (const float*)d_in[13];
    float* out = (float*)d_out;

    cudaFuncSetAttribute(attn_kernel, cudaFuncAttributeMaxDynamicSharedMemorySize,
                         ATTN_SMEM_BYTES);

    static const __nv_bfloat16* h_xub = nullptr;
    static const __nv_bfloat16* h_WcatTb = nullptr;
    static const __nv_bfloat16* h_WkTb = nullptr;
    static const __nv_bfloat16* h_valb = nullptr;
    static const float* h_bcat = nullptr;
    if (!h_xub) {
        void* p;
        cudaGetSymbolAddress(&p, g_xub);    h_xub = (const __nv_bfloat16*)p;
        cudaGetSymbolAddress(&p, g_WcatTb); h_WcatTb = (const __nv_bfloat16*)p;
        cudaGetSymbolAddress(&p, g_WkTb);   h_WkTb = (const __nv_bfloat16*)p;
        cudaGetSymbolAddress(&p, g_valb);   h_valb = (const __nv_bfloat16*)p;
        cudaGetSymbolAddress(&p, g_bcat);   h_bcat = (const float*)p;
    }

    prep_kernel<<<4352, 256>>>(Wq, bq, Wv, bv, Wk);
    conv_kernel<<<NUROWS / 12, 256>>>(cand, clk, emb, conv_w, conv_b);
    gemm_mma_kernel<0><<<dim3(34, (NUROWS + 127) / 128), 256>>>(h_xub, h_WcatTb, h_bcat,
                                                                NUROWS, 4352);
    attn_kernel<<<dim3(4, NSEQ), 256, ATTN_SMEM_BYTES>>>();
    gemm_mma_kernel<1><<<dim3(2, (MVAL + 127) / 128), 256>>>(h_valb, h_WkTb, bk,
                                                             MVAL, NQD);
    word_kernel<<<NSEQ, 256>>>(qw);
    final_kernel<<<NB, 256>>>(Wl, bl, out);
}

// round 11
// speedup vs baseline: 3.9778x; 1.0935x over previous
#include <cuda_runtime.h>
#include <cuda_bf16.h>
#include <cuda_fp16.h>
#include <math.h>
#include <stdint.h>

#define NB 16
#define NCDD 5
#define NHIS 50
#define NS 20
#define NT 41
#define NE 300
#define NF 256
#define NH 16
#define NDV 16
#define NQD 200
#define NSEQ 4000
#define NUROWS 21600
#define MID_BASE 17600
#define MVAL 164000
#define SCALE_F 0.057735026918962576f

// -------- static device scratch (no allocations) --------
__device__ __nv_bfloat16 g_xub[NUROWS * NF];
__device__ __nv_bfloat16 g_WcatTb[4352 * 256];
__device__ float g_bcat[4352];
__device__ __nv_bfloat16 g_WkTb[200 * 256];
__device__ __nv_bfloat16 g_qb[(size_t)NUROWS * 4096];
__device__ float g_xv[(size_t)NUROWS * 256];
__device__ float g_val[(size_t)MVAL * NF];
__device__ __nv_bfloat16 g_valb[(size_t)MVAL * NF];
__device__ float g_kbuf[(size_t)MVAL * NQD];
__device__ float g_rep[(size_t)NSEQ * NF];

// -------- kernel 0: pack transposed bf16 weights + bias --------
__global__ void prep_kernel(const float* __restrict__ Wq, const float* __restrict__ bq,
                            const float* __restrict__ Wv, const float* __restrict__ bv,
                            const float* __restrict__ Wk) {
    int idx = blockIdx.x * 256 + threadIdx.x;
    if (idx < 4352 * 256) {
        int nn = idx >> 8, k = idx & 255;
        float w;
        if (nn < 4096) {
            int h = nn >> 8, g = nn & 255;
            w = Wq[(h * 256 + k) * 256 + g];
        } else {
            int jj = nn - 4096;
            int h = jj >> 4, d = jj & 15;
            w = Wv[(h * 256 + k) * 16 + d];
        }
        g_WcatTb[idx] = __float2bfloat16(w);
    }
    if (idx < 200 * 256) {
        int nn = idx >> 8, k = idx & 255;
        g_WkTb[idx] = __float2bfloat16(Wk[k * 200 + nn]);
    }
    if (idx < 4352) {
        if (idx < 4096) {
            int h = idx >> 8, g = idx & 255;
            g_bcat[idx] = bq[h * 256 + g];
        } else {
            g_bcat[idx] = bv[idx - 4096]; // bv folds through softmax (rows sum to 1)
        }
    }
}

// -------- kernel 1: conv1d(k=3, SAME) + ReLU over 21600 unique rows, bf16 out --------
__global__ void __launch_bounds__(256) conv_kernel(const int* __restrict__ cand,
                                                   const int* __restrict__ clk,
                                                   const float* __restrict__ emb,
                                                   const float* __restrict__ cw,
                                                   const float* __restrict__ cb) {
    __shared__ float se[12 * 900];
    __shared__ int st[12][3];
    int row0 = blockIdx.x * 12;
    int tid = threadIdx.x;
    if (tid < 12) {
        int row = row0 + tid;
        int t0, t1, t2;
        if (row < 1600) {
            int bc = row / 20, t = row - bc * 20;
            const int* ct = cand + bc * 20;
            t0 = (t - 1 >= 0) ? ct[t - 1] : -1;
            t1 = ct[t];
            t2 = (t + 1 < 20) ? ct[t + 1] : 1;
        } else if (row < MID_BASE) {
            int r2 = row - 1600;
            int bh = r2 / 20, tt = r2 - bh * 20;
            const int* ht = clk + bh * 20;
            t0 = (tt == 0) ? 1 : ht[tt - 1];
            t1 = ht[tt];
            t2 = (tt + 1 < 20) ? ht[tt + 1] : -1;
        } else {
            int nn = row - MID_BASE;
            int b = nn / 250, rr = nn - b * 250;
            int c = rr / 50, hh = rr - c * 50;
            t0 = cand[(b * 5 + c) * 20 + 19];
            t1 = 1;
            t2 = clk[(b * 50 + hh) * 20 + 0];
        }
        st[tid][0] = t0; st[tid][1] = t1; st[tid][2] = t2;
    }
    __syncthreads();
    for (int idx = tid; idx < 12 * 900; idx += 256) {
        int r = idx / 900;
        int rem = idx - r * 900;
        int w = rem / 300;
        int e = rem - w * 300;
        int tok = st[r][w];
        se[idx] = (tok < 0) ? 0.f : emb[(size_t)tok * NE + e];
    }
    __syncthreads();
    int f = tid;
    float cbf = cb[f];
    float acc[12];
#pragma unroll
    for (int r = 0; r < 12; ++r) acc[r] = cbf;
    for (int we = 0; we < 900; we += 4) {
        float w0 = cw[(we + 0) * 256 + f];
        float w1 = cw[(we + 1) * 256 + f];
        float w2 = cw[(we + 2) * 256 + f];
        float w3 = cw[(we + 3) * 256 + f];
#pragma unroll
        for (int r = 0; r < 12; ++r) {
            float4 a = *(const float4*)(se + r * 900 + we);
            acc[r] = fmaf(a.x, w0, acc[r]);
            acc[r] = fmaf(a.y, w1, acc[r]);
            acc[r] = fmaf(a.z, w2, acc[r]);
            acc[r] = fmaf(a.w, w3, acc[r]);
        }
    }
#pragma unroll
    for (int r = 0; r < 12; ++r)
        g_xub[(size_t)(row0 + r) * NF + f] = __float2bfloat16(fmaxf(acc[r], 0.f));
}

// -------- bf16 tensor-core GEMM, K=256, register-prefetch double buffered --------
template <int MODE>
__global__ void __launch_bounds__(256, 2) gemm_mma_kernel(const __nv_bfloat16* __restrict__ Ag,
                                                          const __nv_bfloat16* __restrict__ Bt,
                                                          const float* __restrict__ bias,
                                                          int M, int N) {
    __shared__ __nv_bfloat16 As[128 * 56];
    __shared__ __nv_bfloat16 Bs[128 * 56];
    int tid = threadIdx.x;
    int w = tid >> 5, lane = tid & 31;
    int wm = w >> 2, wn = w & 3;
    int m0 = blockIdx.y * 128;
    int n0 = blockIdx.x * 128;

    uint32_t As_u = (uint32_t)__cvta_generic_to_shared(As);
    uint32_t Bs_u = (uint32_t)__cvta_generic_to_shared(Bs);

    float acc[4][4][4];
#pragma unroll
    for (int i = 0; i < 4; ++i)
#pragma unroll
        for (int j = 0; j < 4; ++j)
#pragma unroll
            for (int e = 0; e < 4; ++e) acc[i][j][e] = 0.f;

    uint4 pre[4];
#pragma unroll
    for (int j = 0; j < 4; ++j) {
        int i = tid + j * 256;
        int r = (i >> 2) & 127;
        int kq = i & 3;
        uint4 v = make_uint4(0, 0, 0, 0);
        if (i < 512) {
            int m = m0 + r;
            if (m < M) v = *(const uint4*)(Ag + (size_t)m * 256 + kq * 8);
        } else {
            int nn = n0 + r;
            if (nn < N) v = *(const uint4*)(Bt + (size_t)nn * 256 + kq * 8);
        }
        pre[j] = v;
    }

    for (int kc = 0; kc < 256; kc += 32) {
        __syncthreads();
#pragma unroll
        for (int j = 0; j < 4; ++j) {
            int i = tid + j * 256;
            int r = (i >> 2) & 127;
            int kq = i & 3;
            if (i < 512) *(uint4*)(As + r * 56 + kq * 8) = pre[j];
            else         *(uint4*)(Bs + r * 56 + kq * 8) = pre[j];
        }
        __syncthreads();
        if (kc + 32 < 256) {
            int kn = kc + 32;
#pragma unroll
            for (int j = 0; j < 4; ++j) {
                int i = tid + j * 256;
                int r = (i >> 2) & 127;
                int kq = i & 3;
                uint4 v = make_uint4(0, 0, 0, 0);
                if (i < 512) {
                    int m = m0 + r;
                    if (m < M) v = *(const uint4*)(Ag + (size_t)m * 256 + kn + kq * 8);
                } else {
                    int nn = n0 + r;
                    if (nn < N) v = *(const uint4*)(Bt + (size_t)nn * 256 + kn + kq * 8);
                }
                pre[j] = v;
            }
        }
#pragma unroll
        for (int ks = 0; ks < 2; ++ks) {
            uint32_t a[4][4], b[4][2];
#pragma unroll
            for (int i = 0; i < 4; ++i) {
                uint32_t addr = As_u +
                    (uint32_t)(((wm * 64 + i * 16 + (lane & 15)) * 56 + ks * 16 + (lane >> 4) * 8) * 2);
                asm volatile("ldmatrix.sync.aligned.m8n8.x4.shared.b16 {%0,%1,%2,%3}, [%4];"
                    : "=r"(a[i][0]), "=r"(a[i][1]), "=r"(a[i][2]), "=r"(a[i][3]) : "r"(addr));
            }
#pragma unroll
            for (int j = 0; j < 4; ++j) {
                int nr = wn * 32 + j * 8 + (lane & 7);
                uint32_t addr = Bs_u +
                    (uint32_t)((nr * 56 + ks * 16 + ((lane >> 3) & 1) * 8) * 2);
                asm volatile("ldmatrix.sync.aligned.m8n8.x2.shared.b16 {%0,%1}, [%2];"
                    : "=r"(b[j][0]), "=r"(b[j][1]) : "r"(addr));
            }
#pragma unroll
            for (int i = 0; i < 4; ++i)
#pragma unroll
                for (int j = 0; j < 4; ++j)
                    asm volatile(
                        "mma.sync.aligned.m16n8k16.row.col.f32.bf16.bf16.f32 "
                        "{%0,%1,%2,%3}, {%4,%5,%6,%7}, {%8,%9}, {%0,%1,%2,%3};"
                        : "+f"(acc[i][j][0]), "+f"(acc[i][j][1]),
                          "+f"(acc[i][j][2]), "+f"(acc[i][j][3])
                        : "r"(a[i][0]), "r"(a[i][1]), "r"(a[i][2]), "r"(a[i][3]),
                          "r"(b[j][0]), "r"(b[j][1]));
        }
    }

    int gid = lane >> 2;
#pragma unroll
    for (int i = 0; i < 4; ++i) {
#pragma unroll
        for (int j = 0; j < 4; ++j) {
            int c0 = n0 + wn * 32 + j * 8 + (lane & 3) * 2;
            float b0 = 0.f, b1 = 0.f;
            if (MODE == 0 || c0 + 1 < N) { b0 = bias[c0]; b1 = bias[c0 + 1]; }
            else if (c0 < N) b0 = bias[c0];
#pragma unroll
            for (int half_ = 0; half_ < 2; ++half_) {
                int m = m0 + wm * 64 + i * 16 + gid + half_ * 8;
                if (m >= M) continue;
                float v0 = acc[i][j][half_ * 2 + 0] + b0;
                float v1 = acc[i][j][half_ * 2 + 1] + b1;
                if (MODE == 0) {
                    if (c0 < 4096) {
                        __nv_bfloat162 p = __floats2bfloat162_rn(v0, v1);
                        *(uint32_t*)(g_qb + (size_t)m * 4096 + c0) = *(uint32_t*)&p;
                    } else {
                        *(float2*)(g_xv + (size_t)m * 256 + (c0 - 4096)) =
                            make_float2(v0, v1);
                    }
                } else {
                    if (c0 < N) g_kbuf[(size_t)m * NQD + c0] = tanhf(v0);
                    if (c0 + 1 < N) g_kbuf[(size_t)m * NQD + c0 + 1] = tanhf(v1);
                }
            }
        }
    }
}

// -------- kernel 3: attention; scores bf16 mma, epilogue fp16 mma --------
// smem: xb 6912 | qbA 4x6912=27648 (reused as P fp16 48x56) | scm 4x7216=28864 | xvT 4x1792=7168
#define ATTN_SMEM_BYTES 70592

__global__ void __launch_bounds__(256, 3) attn_kernel() {
    extern __shared__ float sm[];
    __nv_bfloat16* xb = (__nv_bfloat16*)sm;
    __nv_bfloat16* qbA = (__nv_bfloat16*)(sm + 1728);
    float* scA = sm + 8640;
    half* xvTA = (half*)(sm + 15856);
    __shared__ int rows[41];

    int n = blockIdx.y;
    int hb = blockIdx.x;
    int tid = threadIdx.x;
    int g = tid >> 6;
    int l = tid & 63;
    int w = l >> 5;
    int lane = l & 31;
    int h = hb * 4 + g;

    __nv_bfloat16* qb = qbA + g * 3456;
    float* scm = scA + g * 1804;
    half* xvT = xvTA + g * 896;          // [16][56] fp16, transposed xv

    uint32_t xb_u = (uint32_t)__cvta_generic_to_shared(xb);
    uint32_t qb_u = (uint32_t)__cvta_generic_to_shared(qb);
    uint32_t xvT_u = (uint32_t)__cvta_generic_to_shared(xvT);

    if (tid < 41) {
        int b = n / 250, rr = n - b * 250;
        int c = rr / 50, hh = rr - c * 50;
        int t = tid, r;
        if (t < 20)       r = (b * 5 + c) * 20 + t;
        else if (t == 20) r = MID_BASE + n;
        else              r = 1600 + (b * 50 + hh) * 20 + (t - 21);
        rows[t] = r;
    }
    __syncthreads();

    // stage xv transposed fp16 [d][s]; zero pad s in [41,56)
    for (int i = l; i < 240; i += 64) {
        int d = i / 15, s = 41 + i % 15;
        xvT[d * 56 + s] = __float2half(0.f);
    }
    for (int i = l; i < 164; i += 64) {
        int s = i >> 2, dq = (i & 3) * 4;
        float4 v = *(const float4*)(g_xv + (size_t)rows[s] * 256 + h * 16 + dq);
        xvT[(dq + 0) * 56 + s] = __float2half(v.x);
        xvT[(dq + 1) * 56 + s] = __float2half(v.y);
        xvT[(dq + 2) * 56 + s] = __float2half(v.z);
        xvT[(dq + 3) * 56 + s] = __float2half(v.w);
    }

    float acc[3][3][4];
#pragma unroll
    for (int i = 0; i < 3; ++i)
#pragma unroll
        for (int j = 0; j < 3; ++j)
#pragma unroll
            for (int e = 0; e < 4; ++e) acc[i][j][e] = 0.f;

    for (int kc = 0; kc < 256; kc += 64) {
        __syncthreads();
        for (int i = tid; i < 328; i += 256) {
            int t = i >> 3, kq = i & 7;
            *(uint4*)(xb + t * 72 + kq * 8) =
                *(const uint4*)(g_xub + (size_t)rows[t] * 256 + kc + kq * 8);
        }
        for (int i = l; i < 328; i += 64) {
            int t = i >> 3, kq = i & 7;
            *(uint4*)(qb + t * 72 + kq * 8) =
                *(const uint4*)(g_qb + (size_t)rows[t] * 4096 + h * 256 + kc + kq * 8);
        }
        __syncthreads();
#pragma unroll
        for (int ks = 0; ks < 4; ++ks) {
            uint32_t a[3][4], b[3][2];
#pragma unroll
            for (int i = 0; i < 3; ++i) {
                uint32_t addr = qb_u +
                    (uint32_t)(((i * 16 + (lane & 15)) * 72 + ks * 16 + (lane >> 4) * 8) * 2);
                asm volatile("ldmatrix.sync.aligned.m8n8.x4.shared.b16 {%0,%1,%2,%3}, [%4];"
                    : "=r"(a[i][0]), "=r"(a[i][1]), "=r"(a[i][2]), "=r"(a[i][3]) : "r"(addr));
            }
#pragma unroll
            for (int j = 0; j < 3; ++j) {
                int nr = w * 24 + j * 8 + (lane & 7);
                uint32_t addr = xb_u +
                    (uint32_t)((nr * 72 + ks * 16 + ((lane >> 3) & 1) * 8) * 2);
                asm volatile("ldmatrix.sync.aligned.m8n8.x2.shared.b16 {%0,%1}, [%2];"
                    : "=r"(b[j][0]), "=r"(b[j][1]) : "r"(addr));
            }
#pragma unroll
            for (int i = 0; i < 3; ++i)
#pragma unroll
                for (int j = 0; j < 3; ++j)
                    asm volatile(
                        "mma.sync.aligned.m16n8k16.row.col.f32.bf16.bf16.f32 "
                        "{%0,%1,%2,%3}, {%4,%5,%6,%7}, {%8,%9}, {%0,%1,%2,%3};"
                        : "+f"(acc[i][j][0]), "+f"(acc[i][j][1]),
                          "+f"(acc[i][j][2]), "+f"(acc[i][j][3])
                        : "r"(a[i][0]), "r"(a[i][1]), "r"(a[i][2]), "r"(a[i][3]),
                          "r"(b[j][0]), "r"(b[j][1]));
        }
    }

    // write scores to scm fp32
    {
        int gid = lane >> 2, t4 = lane & 3;
#pragma unroll
        for (int i = 0; i < 3; ++i) {
#pragma unroll
            for (int j = 0; j < 3; ++j) {
                int c0 = w * 24 + j * 8 + t4 * 2;
                int r0 = i * 16 + gid;
                int r1 = r0 + 8;
                if (c0 + 1 < 41) {
                    if (r0 < 41) *(float2*)(scm + r0 * 44 + c0) =
                        make_float2(acc[i][j][0] * SCALE_F, acc[i][j][1] * SCALE_F);
                    if (r1 < 41) *(float2*)(scm + r1 * 44 + c0) =
                        make_float2(acc[i][j][2] * SCALE_F, acc[i][j][3] * SCALE_F);
                } else if (c0 < 41) {
                    if (r0 < 41) scm[r0 * 44 + c0] = acc[i][j][0] * SCALE_F;
                    if (r1 < 41) scm[r1 * 44 + c0] = acc[i][j][2] * SCALE_F;
                }
            }
        }
    }
    __syncthreads();

    // softmax per row; write normalized P as fp16 into qb region (48x56)
    half* Pb = (half*)qb;
    for (int t = w; t < 41; t += 2) {
        float v0 = (lane < 41) ? scm[t * 44 + lane] : -1e30f;
        float v1 = (lane + 32 < 41) ? scm[t * 44 + lane + 32] : -1e30f;
        float m = fmaxf(v0, v1);
#pragma unroll
        for (int o = 16; o; o >>= 1) m = fmaxf(m, __shfl_xor_sync(0xffffffffu, m, o));
        float e0 = (lane < 41) ? __expf(v0 - m) : 0.f;
        float e1 = (lane + 32 < 41) ? __expf(v1 - m) : 0.f;
        float s = e0 + e1;
#pragma unroll
        for (int o = 16; o; o >>= 1) s += __shfl_xor_sync(0xffffffffu, s, o);
        float inv = 1.f / s;
        Pb[t * 56 + lane] = __float2half(e0 * inv);
        int s1 = lane + 32;
        if (s1 < 56) Pb[t * 56 + s1] = __float2half((s1 < 41) ? e1 * inv : 0.f);
    }
    __syncthreads();

    // epilogue mma: out[48x16] = P[48x48] @ xv[48x16]; warp0 m-tiles {0,1}, warp1 {2}
    {
        uint32_t Pb_u = qb_u;
        int nMt = (w == 0) ? 2 : 1;
        int mBase = (w == 0) ? 0 : 2;
        float ea[2][2][4];
#pragma unroll
        for (int i = 0; i < 2; ++i)
#pragma unroll
            for (int j = 0; j < 2; ++j)
#pragma unroll
                for (int e = 0; e < 4; ++e) ea[i][j][e] = 0.f;
#pragma unroll
        for (int ks = 0; ks < 3; ++ks) {
            uint32_t bf[2][2];
#pragma unroll
            for (int j = 0; j < 2; ++j) {
                uint32_t addr = xvT_u +
                    (uint32_t)(((j * 8 + (lane & 7)) * 56 + ks * 16 + ((lane >> 3) & 1) * 8) * 2);
                asm volatile("ldmatrix.sync.aligned.m8n8.x2.shared.b16 {%0,%1}, [%2];"
                    : "=r"(bf[j][0]), "=r"(bf[j][1]) : "r"(addr));
            }
#pragma unroll
            for (int im = 0; im < 2; ++im) {
                if (im >= nMt) break;
                int mt = mBase + im;
                uint32_t af[4];
                uint32_t addr = Pb_u +
                    (uint32_t)(((mt * 16 + (lane & 15)) * 56 + ks * 16 + (lane >> 4) * 8) * 2);
                asm volatile("ldmatrix.sync.aligned.m8n8.x4.shared.b16 {%0,%1,%2,%3}, [%4];"
                    : "=r"(af[0]), "=r"(af[1]), "=r"(af[2]), "=r"(af[3]) : "r"(addr));
#pragma unroll
                for (int j = 0; j < 2; ++j)
                    asm volatile(
                        "mma.sync.aligned.m16n8k16.row.col.f32.f16.f16.f32 "
                        "{%0,%1,%2,%3}, {%4,%5,%6,%7}, {%8,%9}, {%0,%1,%2,%3};"
                        : "+f"(ea[im][j][0]), "+f"(ea[im][j][1]),
                          "+f"(ea[im][j][2]), "+f"(ea[im][j][3])
                        : "r"(af[0]), "r"(af[1]), "r"(af[2]), "r"(af[3]),
                          "r"(bf[j][0]), "r"(bf[j][1]));
            }
        }
        int gid = lane >> 2;
#pragma unroll
        for (int im = 0; im < 2; ++im) {
            if (im >= nMt) break;
            int mt = mBase + im;
#pragma unroll
            for (int j = 0; j < 2; ++j) {
                int c0 = j * 8 + (lane & 3) * 2;
#pragma unroll
                for (int hf = 0; hf < 2; ++hf) {
                    int t = mt * 16 + gid + hf * 8;
                    if (t < 41) {
                        float v0 = ea[im][j][hf * 2 + 0];
                        float v1 = ea[im][j][hf * 2 + 1];
                        size_t o = ((size_t)n * 41 + t) * 256 + h * 16 + c0;
                        *(float2*)(g_val + o) = make_float2(v0, v1);
                        __nv_bfloat162 pp = __floats2bfloat162_rn(v0, v1);
                        *(uint32_t*)(g_valb + o) = *(uint32_t*)&pp;
                    }
                }
            }
        }
    }
}

// -------- kernel 5: word attention per sequence --------
__global__ void __launch_bounds__(256) word_kernel(const float* __restrict__ qw) {
    __shared__ float sqw[200];
    __shared__ float sl[41];
    int n = blockIdx.x;
    int tid = threadIdx.x;
    if (tid < 200) sqw[tid] = qw[tid];
    __syncthreads();
    int warp = tid >> 5, lane = tid & 31;
    for (int t = warp; t < 41; t += 8) {
        const float* kr = g_kbuf + ((size_t)n * 41 + t) * 200;
        float s = 0.f;
        for (int e = lane; e < 200; e += 32) s = fmaf(kr[e], sqw[e], s);
#pragma unroll
        for (int o = 16; o; o >>= 1) s += __shfl_xor_sync(0xffffffffu, s, o);
        if (lane == 0) sl[t] = s * SCALE_F;
    }
    __syncthreads();
    if (tid < 32) {
        float v0 = (tid < 41) ? sl[tid] : -1e30f;
        float v1 = (tid + 32 < 41) ? sl[tid + 32] : -1e30f;
        float m = fmaxf(v0, v1);
#pragma unroll
        for (int o = 16; o; o >>= 1) m = fmaxf(m, __shfl_xor_sync(0xffffffffu, m, o));
        float e0 = (tid < 41) ? expf(v0 - m) : 0.f;
        float e1 = (tid + 32 < 41) ? expf(v1 - m) : 0.f;
        float s = e0 + e1;
#pragma unroll
        for (int o = 16; o; o >>= 1) s += __shfl_xor_sync(0xffffffffu, s, o);
        float inv = 1.f / s;
        if (tid < 41) sl[tid] = e0 * inv;
        if (tid + 32 < 41) sl[tid + 32] = e1 * inv;
    }
    __syncthreads();
    float acc = 0.f;
    const float* vr = g_val + (size_t)n * 41 * 256 + tid;
#pragma unroll 8
    for (int t = 0; t < 41; ++t) acc = fmaf(sl[t], vr[(size_t)t * 256], acc);
    g_rep[(size_t)n * 256 + tid] = acc;
}

// -------- kernel 6: mean over HIS, rank score, log-softmax over CDD --------
__global__ void __launch_bounds__(256) final_kernel(const float* __restrict__ Wl,
                                                    const float* __restrict__ blp,
                                                    float* __restrict__ out) {
    __shared__ float red[8];
    __shared__ float sc[5];
    int b = blockIdx.x;
    int tid = threadIdx.x;
    float wl = Wl[tid];
    for (int c = 0; c < 5; ++c) {
        const float* rp = g_rep + ((size_t)(b * 5 + c) * 50) * 256 + tid;
        float s = 0.f;
        for (int h = 0; h < 50; ++h) s += rp[(size_t)h * 256];
        s *= wl;
#pragma unroll
        for (int o = 16; o; o >>= 1) s += __shfl_xor_sync(0xffffffffu, s, o);
        if ((tid & 31) == 0) red[tid >> 5] = s;
        __syncthreads();
        if (tid < 8) {
            float v = red[tid];
#pragma unroll
            for (int o = 4; o; o >>= 1) v += __shfl_xor_sync(0xffu, v, o, 8);
            if (tid == 0) sc[c] = v * (1.f / 50.f) + blp[0];
        }
        __syncthreads();
    }
    if (tid == 0) {
        float m = sc[0];
        for (int c = 1; c < 5; ++c) m = fmaxf(m, sc[c]);
        float s = 0.f;
        for (int c = 0; c < 5; ++c) s += expf(sc[c] - m);
        float ls = logf(s);
        for (int c = 0; c < 5; ++c) out[b * 5 + c] = sc[c] - m - ls;
    }
}

// -------- host launcher --------
extern "C" void kernel_launch(void* const* d_in, const int* in_sizes, int n_in,
                              void* d_out, int out_size) {
    const int* cand = (const int*)d_in[0];
    const int* clk = (const int*)d_in[1];
    const float* emb = (const float*)d_in[2];
    const float* conv_w = (const float*)d_in[3];
    const float* conv_b = (const float*)d_in[4];
    const float* Wq = (const float*)d_in[5];
    const float* bq = (const float*)d_in[6];
    const float* Wv = (const float*)d_in[7];
    const float* bv = (const float*)d_in[8];
    const float* Wk = (const float*)d_in[9];
    const float* bk = (const float*)d_in[10];
    const float* qw = (const float*)d_in[11];
    const float* Wl = (const float*)d_in[12];
    const float* bl = (const float*)d_in[13];
    float* out = (float*)d_out;

    cudaFuncSetAttribute(attn_kernel, cudaFuncAttributeMaxDynamicSharedMemorySize,
                         ATTN_SMEM_BYTES);

    static const __nv_bfloat16* h_xub = nullptr;
    static const __nv_bfloat16* h_WcatTb = nullptr;
    static const __nv_bfloat16* h_WkTb = nullptr;
    static const __nv_bfloat16* h_valb = nullptr;
    static const float* h_bcat = nullptr;
    if (!h_xub) {
        void* p;
        cudaGetSymbolAddress(&p, g_xub);    h_xub = (const __nv_bfloat16*)p;
        cudaGetSymbolAddress(&p, g_WcatTb); h_WcatTb = (const __nv_bfloat16*)p;
        cudaGetSymbolAddress(&p, g_WkTb);   h_WkTb = (const __nv_bfloat16*)p;
        cudaGetSymbolAddress(&p, g_valb);   h_valb = (const __nv_bfloat16*)p;
        cudaGetSymbolAddress(&p, g_bcat);   h_bcat = (const float*)p;
    }

    prep_kernel<<<4352, 256>>>(Wq, bq, Wv, bv, Wk);
    conv_kernel<<<NUROWS / 12, 256>>>(cand, clk, emb, conv_w, conv_b);
    gemm_mma_kernel<0><<<dim3(34, (NUROWS + 127) / 128), 256>>>(h_xub, h_WcatTb, h_bcat,
                                                                NUROWS, 4352);
    attn_kernel<<<dim3(4, NSEQ), 256, ATTN_SMEM_BYTES>>>();
    gemm_mma_kernel<1><<<dim3(2, (MVAL + 127) / 128), 256>>>(h_valb, h_WkTb, bk,
                                                             MVAL, NQD);
    word_kernel<<<NSEQ, 256>>>(qw);
    final_kernel<<<NB, 256>>>(Wl, bl, out);
}

// round 12
// speedup vs baseline: 5.5871x; 1.4046x over previous
#include <cuda_runtime.h>
#include <cuda_bf16.h>
#include <cuda_fp16.h>
#include <math.h>
#include <stdint.h>

#define NB 16
#define NCDD 5
#define NHIS 50
#define NS 20
#define NT 41
#define NE 300
#define NF 256
#define NH 16
#define NDV 16
#define NQD 200
#define NSEQ 4000
#define NUROWS 21600
#define MID_BASE 17600
#define MVAL 164000
#define SCALE_F 0.057735026918962576f
#define CONV_K 928

// -------- static device scratch (no allocations) --------
__device__ __nv_bfloat16 g_xub[NUROWS * NF];
__device__ __nv_bfloat16 g_WcatTb[4352 * 256];
__device__ float g_bcat[4352];
__device__ __nv_bfloat16 g_WkTb[200 * 256];
__device__ __nv_bfloat16 g_cwb[256 * CONV_K];
__device__ __nv_bfloat16 g_qb[(size_t)NUROWS * 4096];
__device__ float g_xv[(size_t)NUROWS * 256];
__device__ __nv_bfloat16 g_valb[(size_t)MVAL * NF];
__device__ float g_kbuf[(size_t)MVAL * NQD];
__device__ float g_rep[(size_t)NSEQ * NF];

// -------- kernel 0: pack transposed bf16 weights + bias --------
__global__ void prep_kernel(const float* __restrict__ Wq, const float* __restrict__ bq,
                            const float* __restrict__ Wv, const float* __restrict__ bv,
                            const float* __restrict__ Wk, const float* __restrict__ cw) {
    int idx = blockIdx.x * 256 + threadIdx.x;
    if (idx < 4352 * 256) {
        int nn = idx >> 8, k = idx & 255;
        float w;
        if (nn < 4096) {
            int h = nn >> 8, g = nn & 255;
            w = Wq[(h * 256 + k) * 256 + g];
        } else {
            int jj = nn - 4096;
            int h = jj >> 4, d = jj & 15;
            w = Wv[(h * 256 + k) * 16 + d];
        }
        g_WcatTb[idx] = __float2bfloat16(w);
    }
    if (idx < 200 * 256) {
        int nn = idx >> 8, k = idx & 255;
        g_WkTb[idx] = __float2bfloat16(Wk[k * 200 + nn]);
    }
    if (idx < 256 * CONV_K) {
        int f = idx / CONV_K, k = idx - f * CONV_K;
        g_cwb[idx] = __float2bfloat16(k < 900 ? cw[k * 256 + f] : 0.f);
    }
    if (idx < 4352) {
        if (idx < 4096) {
            int h = idx >> 8, g = idx & 255;
            g_bcat[idx] = bq[h * 256 + g];
        } else {
            g_bcat[idx] = bv[idx - 4096]; // bv folds through softmax (rows sum to 1)
        }
    }
}

// -------- kernel 1: conv as bf16 mma GEMM over im2col rows --------
__global__ void __launch_bounds__(256, 2) conv_mma_kernel(const int* __restrict__ cand,
                                                          const int* __restrict__ clk,
                                                          const float* __restrict__ emb,
                                                          const float* __restrict__ cb) {
    __shared__ __nv_bfloat16 As[128 * 40];
    __shared__ __nv_bfloat16 Bs[128 * 40];
    __shared__ int st[128][3];
    int tid = threadIdx.x;
    int w = tid >> 5, lane = tid & 31;
    int wm = w >> 2, wn = w & 3;
    int m0 = blockIdx.y * 128;
    int n0 = blockIdx.x * 128;

    if (tid < 128) {
        int row = m0 + tid;
        int t0 = -1, t1 = -1, t2 = -1;
        if (row < NUROWS) {
            if (row < 1600) {
                int bc = row / 20, t = row - bc * 20;
                const int* ct = cand + bc * 20;
                t0 = (t - 1 >= 0) ? ct[t - 1] : -1;
                t1 = ct[t];
                t2 = (t + 1 < 20) ? ct[t + 1] : 1;
            } else if (row < MID_BASE) {
                int r2 = row - 1600;
                int bh = r2 / 20, tt = r2 - bh * 20;
                const int* ht = clk + bh * 20;
                t0 = (tt == 0) ? 1 : ht[tt - 1];
                t1 = ht[tt];
                t2 = (tt + 1 < 20) ? ht[tt + 1] : -1;
            } else {
                int nn = row - MID_BASE;
                int b = nn / 250, rr = nn - b * 250;
                int c = rr / 50, hh = rr - c * 50;
                t0 = cand[(b * 5 + c) * 20 + 19];
                t1 = 1;
                t2 = clk[(b * 50 + hh) * 20 + 0];
            }
        }
        st[tid][0] = t0; st[tid][1] = t1; st[tid][2] = t2;
    }

    uint32_t As_u = (uint32_t)__cvta_generic_to_shared(As);
    uint32_t Bs_u = (uint32_t)__cvta_generic_to_shared(Bs);

    float acc[4][4][4];
#pragma unroll
    for (int i = 0; i < 4; ++i)
#pragma unroll
        for (int j = 0; j < 4; ++j)
#pragma unroll
            for (int e = 0; e < 4; ++e) acc[i][j][e] = 0.f;

    for (int kc = 0; kc < CONV_K; kc += 32) {
        __syncthreads();
        // A: 128 rows x 8 quads of 4 k (quads never cross tap boundary: 300 % 4 == 0)
#pragma unroll
        for (int j = 0; j < 4; ++j) {
            int i = tid + j * 256;
            int r = i >> 3, q = i & 7;
            int k0 = kc + q * 4;
            uint2 u = make_uint2(0, 0);
            if (k0 < 900) {
                int tap = k0 / 300;
                int e0 = k0 - tap * 300;
                int tok = st[r][tap];
                if (tok >= 0) {
                    float4 v = *(const float4*)(emb + (size_t)tok * 300 + e0);
                    __nv_bfloat162 p0 = __floats2bfloat162_rn(v.x, v.y);
                    __nv_bfloat162 p1 = __floats2bfloat162_rn(v.z, v.w);
                    u.x = *(uint32_t*)&p0;
                    u.y = *(uint32_t*)&p1;
                }
            }
            *(uint2*)(As + r * 40 + q * 4) = u;
        }
#pragma unroll
        for (int j = 0; j < 2; ++j) {
            int i = tid + j * 256;
            int r = i >> 2, kq = i & 3;
            *(uint4*)(Bs + r * 40 + kq * 8) =
                *(const uint4*)(g_cwb + (size_t)(n0 + r) * CONV_K + kc + kq * 8);
        }
        __syncthreads();
#pragma unroll
        for (int ks = 0; ks < 2; ++ks) {
            uint32_t a[4][4], b[4][2];
#pragma unroll
            for (int i = 0; i < 4; ++i) {
                uint32_t addr = As_u +
                    (uint32_t)(((wm * 64 + i * 16 + (lane & 15)) * 40 + ks * 16 + (lane >> 4) * 8) * 2);
                asm volatile("ldmatrix.sync.aligned.m8n8.x4.shared.b16 {%0,%1,%2,%3}, [%4];"
                    : "=r"(a[i][0]), "=r"(a[i][1]), "=r"(a[i][2]), "=r"(a[i][3]) : "r"(addr));
            }
#pragma unroll
            for (int j = 0; j < 4; ++j) {
                int nr = wn * 32 + j * 8 + (lane & 7);
                uint32_t addr = Bs_u +
                    (uint32_t)((nr * 40 + ks * 16 + ((lane >> 3) & 1) * 8) * 2);
                asm volatile("ldmatrix.sync.aligned.m8n8.x2.shared.b16 {%0,%1}, [%2];"
                    : "=r"(b[j][0]), "=r"(b[j][1]) : "r"(addr));
            }
#pragma unroll
            for (int i = 0; i < 4; ++i)
#pragma unroll
                for (int j = 0; j < 4; ++j)
                    asm volatile(
                        "mma.sync.aligned.m16n8k16.row.col.f32.bf16.bf16.f32 "
                        "{%0,%1,%2,%3}, {%4,%5,%6,%7}, {%8,%9}, {%0,%1,%2,%3};"
                        : "+f"(acc[i][j][0]), "+f"(acc[i][j][1]),
                          "+f"(acc[i][j][2]), "+f"(acc[i][j][3])
                        : "r"(a[i][0]), "r"(a[i][1]), "r"(a[i][2]), "r"(a[i][3]),
                          "r"(b[j][0]), "r"(b[j][1]));
        }
    }

    int gid = lane >> 2;
#pragma unroll
    for (int i = 0; i < 4; ++i) {
#pragma unroll
        for (int j = 0; j < 4; ++j) {
            int c0 = n0 + wn * 32 + j * 8 + (lane & 3) * 2;
            float b0 = cb[c0], b1 = cb[c0 + 1];
#pragma unroll
            for (int hf = 0; hf < 2; ++hf) {
                int m = m0 + wm * 64 + i * 16 + gid + hf * 8;
                if (m >= NUROWS) continue;
                float v0 = fmaxf(acc[i][j][hf * 2 + 0] + b0, 0.f);
                float v1 = fmaxf(acc[i][j][hf * 2 + 1] + b1, 0.f);
                __nv_bfloat162 p = __floats2bfloat162_rn(v0, v1);
                *(uint32_t*)(g_xub + (size_t)m * 256 + c0) = *(uint32_t*)&p;
            }
        }
    }
}

// -------- bf16 tensor-core GEMM, K=256, register-prefetch double buffered --------
template <int MODE>
__global__ void __launch_bounds__(256, 2) gemm_mma_kernel(const __nv_bfloat16* __restrict__ Ag,
                                                          const __nv_bfloat16* __restrict__ Bt,
                                                          const float* __restrict__ bias,
                                                          int M, int N) {
    __shared__ __nv_bfloat16 As[128 * 56];
    __shared__ __nv_bfloat16 Bs[128 * 56];
    int tid = threadIdx.x;
    int w = tid >> 5, lane = tid & 31;
    int wm = w >> 2, wn = w & 3;
    int m0 = blockIdx.y * 128;
    int n0 = blockIdx.x * 128;

    uint32_t As_u = (uint32_t)__cvta_generic_to_shared(As);
    uint32_t Bs_u = (uint32_t)__cvta_generic_to_shared(Bs);

    float acc[4][4][4];
#pragma unroll
    for (int i = 0; i < 4; ++i)
#pragma unroll
        for (int j = 0; j < 4; ++j)
#pragma unroll
            for (int e = 0; e < 4; ++e) acc[i][j][e] = 0.f;

    uint4 pre[4];
#pragma unroll
    for (int j = 0; j < 4; ++j) {
        int i = tid + j * 256;
        int r = (i >> 2) & 127;
        int kq = i & 3;
        uint4 v = make_uint4(0, 0, 0, 0);
        if (i < 512) {
            int m = m0 + r;
            if (m < M) v = *(const uint4*)(Ag + (size_t)m * 256 + kq * 8);
        } else {
            int nn = n0 + r;
            if (nn < N) v = *(const uint4*)(Bt + (size_t)nn * 256 + kq * 8);
        }
        pre[j] = v;
    }

    for (int kc = 0; kc < 256; kc += 32) {
        __syncthreads();
#pragma unroll
        for (int j = 0; j < 4; ++j) {
            int i = tid + j * 256;
            int r = (i >> 2) & 127;
            int kq = i & 3;
            if (i < 512) *(uint4*)(As + r * 56 + kq * 8) = pre[j];
            else         *(uint4*)(Bs + r * 56 + kq * 8) = pre[j];
        }
        __syncthreads();
        if (kc + 32 < 256) {
            int kn = kc + 32;
#pragma unroll
            for (int j = 0; j < 4; ++j) {
                int i = tid + j * 256;
                int r = (i >> 2) & 127;
                int kq = i & 3;
                uint4 v = make_uint4(0, 0, 0, 0);
                if (i < 512) {
                    int m = m0 + r;
                    if (m < M) v = *(const uint4*)(Ag + (size_t)m * 256 + kn + kq * 8);
                } else {
                    int nn = n0 + r;
                    if (nn < N) v = *(const uint4*)(Bt + (size_t)nn * 256 + kn + kq * 8);
                }
                pre[j] = v;
            }
        }
#pragma unroll
        for (int ks = 0; ks < 2; ++ks) {
            uint32_t a[4][4], b[4][2];
#pragma unroll
            for (int i = 0; i < 4; ++i) {
                uint32_t addr = As_u +
                    (uint32_t)(((wm * 64 + i * 16 + (lane & 15)) * 56 + ks * 16 + (lane >> 4) * 8) * 2);
                asm volatile("ldmatrix.sync.aligned.m8n8.x4.shared.b16 {%0,%1,%2,%3}, [%4];"
                    : "=r"(a[i][0]), "=r"(a[i][1]), "=r"(a[i][2]), "=r"(a[i][3]) : "r"(addr));
            }
#pragma unroll
            for (int j = 0; j < 4; ++j) {
                int nr = wn * 32 + j * 8 + (lane & 7);
                uint32_t addr = Bs_u +
                    (uint32_t)((nr * 56 + ks * 16 + ((lane >> 3) & 1) * 8) * 2);
                asm volatile("ldmatrix.sync.aligned.m8n8.x2.shared.b16 {%0,%1}, [%2];"
                    : "=r"(b[j][0]), "=r"(b[j][1]) : "r"(addr));
            }
#pragma unroll
            for (int i = 0; i < 4; ++i)
#pragma unroll
                for (int j = 0; j < 4; ++j)
                    asm volatile(
                        "mma.sync.aligned.m16n8k16.row.col.f32.bf16.bf16.f32 "
                        "{%0,%1,%2,%3}, {%4,%5,%6,%7}, {%8,%9}, {%0,%1,%2,%3};"
                        : "+f"(acc[i][j][0]), "+f"(acc[i][j][1]),
                          "+f"(acc[i][j][2]), "+f"(acc[i][j][3])
                        : "r"(a[i][0]), "r"(a[i][1]), "r"(a[i][2]), "r"(a[i][3]),
                          "r"(b[j][0]), "r"(b[j][1]));
        }
    }

    int gid = lane >> 2;
#pragma unroll
    for (int i = 0; i < 4; ++i) {
#pragma unroll
        for (int j = 0; j < 4; ++j) {
            int c0 = n0 + wn * 32 + j * 8 + (lane & 3) * 2;
            float b0 = 0.f, b1 = 0.f;
            if (MODE == 0 || c0 + 1 < N) { b0 = bias[c0]; b1 = bias[c0 + 1]; }
            else if (c0 < N) b0 = bias[c0];
#pragma unroll
            for (int hf = 0; hf < 2; ++hf) {
                int m = m0 + wm * 64 + i * 16 + gid + hf * 8;
                if (m >= M) continue;
                float v0 = acc[i][j][hf * 2 + 0] + b0;
                float v1 = acc[i][j][hf * 2 + 1] + b1;
                if (MODE == 0) {
                    if (c0 < 4096) {
                        __nv_bfloat162 p = __floats2bfloat162_rn(v0, v1);
                        *(uint32_t*)(g_qb + (size_t)m * 4096 + c0) = *(uint32_t*)&p;
                    } else {
                        *(float2*)(g_xv + (size_t)m * 256 + (c0 - 4096)) =
                            make_float2(v0, v1);
                    }
                } else {
                    if (c0 < N) g_kbuf[(size_t)m * NQD + c0] = tanhf(v0);
                    if (c0 + 1 < N) g_kbuf[(size_t)m * NQD + c0 + 1] = tanhf(v1);
                }
            }
        }
    }
}

// -------- kernel 3: attention; deferred-normalization softmax, fp16 mma epilogue --------
#define ATTN_SMEM_BYTES 70592

__global__ void __launch_bounds__(256, 3) attn_kernel() {
    extern __shared__ float sm[];
    __nv_bfloat16* xb = (__nv_bfloat16*)sm;
    __nv_bfloat16* qbA = (__nv_bfloat16*)(sm + 1728);
    float* scA = sm + 8640;
    half* xvTA = (half*)(sm + 15856);
    __shared__ int rows[41];
    __shared__ float sinv[4][48];

    int n = blockIdx.y;
    int hb = blockIdx.x;
    int tid = threadIdx.x;
    int g = tid >> 6;
    int l = tid & 63;
    int w = l >> 5;
    int lane = l & 31;
    int h = hb * 4 + g;

    __nv_bfloat16* qb = qbA + g * 3456;
    float* scm = scA + g * 1804;
    half* xvT = xvTA + g * 896;

    uint32_t xb_u = (uint32_t)__cvta_generic_to_shared(xb);
    uint32_t qb_u = (uint32_t)__cvta_generic_to_shared(qb);
    uint32_t xvT_u = (uint32_t)__cvta_generic_to_shared(xvT);

    if (tid < 41) {
        int b = n / 250, rr = n - b * 250;
        int c = rr / 50, hh = rr - c * 50;
        int t = tid, r;
        if (t < 20)       r = (b * 5 + c) * 20 + t;
        else if (t == 20) r = MID_BASE + n;
        else              r = 1600 + (b * 50 + hh) * 20 + (t - 21);
        rows[t] = r;
    }
    __syncthreads();

    // stage xv transposed fp16 [d][s]; zero pad s in [41,56)
    for (int i = l; i < 240; i += 64) {
        int d = i / 15, s = 41 + i % 15;
        xvT[d * 56 + s] = __float2half(0.f);
    }
    for (int i = l; i < 164; i += 64) {
        int s = i >> 2, dq = (i & 3) * 4;
        float4 v = *(const float4*)(g_xv + (size_t)rows[s] * 256 + h * 16 + dq);
        xvT[(dq + 0) * 56 + s] = __float2half(v.x);
        xvT[(dq + 1) * 56 + s] = __float2half(v.y);
        xvT[(dq + 2) * 56 + s] = __float2half(v.z);
        xvT[(dq + 3) * 56 + s] = __float2half(v.w);
    }

    float acc[3][3][4];
#pragma unroll
    for (int i = 0; i < 3; ++i)
#pragma unroll
        for (int j = 0; j < 3; ++j)
#pragma unroll
            for (int e = 0; e < 4; ++e) acc[i][j][e] = 0.f;

    for (int kc = 0; kc < 256; kc += 64) {
        __syncthreads();
        for (int i = tid; i < 328; i += 256) {
            int t = i >> 3, kq = i & 7;
            *(uint4*)(xb + t * 72 + kq * 8) =
                *(const uint4*)(g_xub + (size_t)rows[t] * 256 + kc + kq * 8);
        }
        for (int i = l; i < 328; i += 64) {
            int t = i >> 3, kq = i & 7;
            *(uint4*)(qb + t * 72 + kq * 8) =
                *(const uint4*)(g_qb + (size_t)rows[t] * 4096 + h * 256 + kc + kq * 8);
        }
        __syncthreads();
#pragma unroll
        for (int ks = 0; ks < 4; ++ks) {
            uint32_t a[3][4], b[3][2];
#pragma unroll
            for (int i = 0; i < 3; ++i) {
                uint32_t addr = qb_u +
                    (uint32_t)(((i * 16 + (lane & 15)) * 72 + ks * 16 + (lane >> 4) * 8) * 2);
                asm volatile("ldmatrix.sync.aligned.m8n8.x4.shared.b16 {%0,%1,%2,%3}, [%4];"
                    : "=r"(a[i][0]), "=r"(a[i][1]), "=r"(a[i][2]), "=r"(a[i][3]) : "r"(addr));
            }
#pragma unroll
            for (int j = 0; j < 3; ++j) {
                int nr = w * 24 + j * 8 + (lane & 7);
                uint32_t addr = xb_u +
                    (uint32_t)((nr * 72 + ks * 16 + ((lane >> 3) & 1) * 8) * 2);
                asm volatile("ldmatrix.sync.aligned.m8n8.x2.shared.b16 {%0,%1}, [%2];"
                    : "=r"(b[j][0]), "=r"(b[j][1]) : "r"(addr));
            }
#pragma unroll
            for (int i = 0; i < 3; ++i)
#pragma unroll
                for (int j = 0; j < 3; ++j)
                    asm volatile(
                        "mma.sync.aligned.m16n8k16.row.col.f32.bf16.bf16.f32 "
                        "{%0,%1,%2,%3}, {%4,%5,%6,%7}, {%8,%9}, {%0,%1,%2,%3};"
                        : "+f"(acc[i][j][0]), "+f"(acc[i][j][1]),
                          "+f"(acc[i][j][2]), "+f"(acc[i][j][3])
                        : "r"(a[i][0]), "r"(a[i][1]), "r"(a[i][2]), "r"(a[i][3]),
                          "r"(b[j][0]), "r"(b[j][1]));
        }
    }

    // write scores to scm fp32
    {
        int gid = lane >> 2, t4 = lane & 3;
#pragma unroll
        for (int i = 0; i < 3; ++i) {
#pragma unroll
            for (int j = 0; j < 3; ++j) {
                int c0 = w * 24 + j * 8 + t4 * 2;
                int r0 = i * 16 + gid;
                int r1 = r0 + 8;
                if (c0 + 1 < 41) {
                    if (r0 < 41) *(float2*)(scm + r0 * 44 + c0) =
                        make_float2(acc[i][j][0] * SCALE_F, acc[i][j][1] * SCALE_F);
                    if (r1 < 41) *(float2*)(scm + r1 * 44 + c0) =
                        make_float2(acc[i][j][2] * SCALE_F, acc[i][j][3] * SCALE_F);
                } else if (c0 < 41) {
                    if (r0 < 41) scm[r0 * 44 + c0] = acc[i][j][0] * SCALE_F;
                    if (r1 < 41) scm[r1 * 44 + c0] = acc[i][j][2] * SCALE_F;
                }
            }
        }
    }
    __syncthreads();

    // softmax: one row per thread; UNNORMALIZED exp -> fp16 P; 1/sum -> sinv
    half* Pb = (half*)qb;
    if (l < 41) {
        const float4* pr4 = (const float4*)(scm + l * 44);
        float mx = scm[l * 44 + 40];
#pragma unroll
        for (int j = 0; j < 10; ++j) {
            float4 v = pr4[j];
            mx = fmaxf(mx, fmaxf(fmaxf(v.x, v.y), fmaxf(v.z, v.w)));
        }
        float sum = __expf(scm[l * 44 + 40] - mx);
        uint32_t* Pr = (uint32_t*)(Pb + l * 56);
#pragma unroll
        for (int j = 0; j < 10; ++j) {
            float4 v = pr4[j];
            float e0 = __expf(v.x - mx), e1 = __expf(v.y - mx);
            float e2 = __expf(v.z - mx), e3 = __expf(v.w - mx);
            sum += (e0 + e1) + (e2 + e3);
            half2 h01 = __floats2half2_rn(e0, e1);
            half2 h23 = __floats2half2_rn(e2, e3);
            Pr[j * 2 + 0] = *(uint32_t*)&h01;
            Pr[j * 2 + 1] = *(uint32_t*)&h23;
        }
        half2 h40 = __floats2half2_rn(__expf(scm[l * 44 + 40] - mx), 0.f);
        Pr[20] = *(uint32_t*)&h40;
#pragma unroll
        for (int j = 21; j < 28; ++j) Pr[j] = 0u;
        sinv[g][l] = 1.f / sum;
    }
    __syncthreads();

    // epilogue mma: out = (expP @ xv) * sinv[t]; warp0 m-tiles {0,1}, warp1 {2}
    {
        int nMt = (w == 0) ? 2 : 1;
        int mBase = (w == 0) ? 0 : 2;
        float ea[2][2][4];
#pragma unroll
        for (int i = 0; i < 2; ++i)
#pragma unroll
            for (int j = 0; j < 2; ++j)
#pragma unroll
                for (int e = 0; e < 4; ++e) ea[i][j][e] = 0.f;
#pragma unroll
        for (int ks = 0; ks < 3; ++ks) {
            uint32_t bf[2][2];
#pragma unroll
            for (int j = 0; j < 2; ++j) {
                uint32_t addr = xvT_u +
                    (uint32_t)(((j * 8 + (lane & 7)) * 56 + ks * 16 + ((lane >> 3) & 1) * 8) * 2);
                asm volatile("ldmatrix.sync.aligned.m8n8.x2.shared.b16 {%0,%1}, [%2];"
                    : "=r"(bf[j][0]), "=r"(bf[j][1]) : "r"(addr));
            }
#pragma unroll
            for (int im = 0; im < 2; ++im) {
                if (im >= nMt) break;
                int mt = mBase + im;
                uint32_t af[4];
                uint32_t addr = qb_u +
                    (uint32_t)(((mt * 16 + (lane & 15)) * 56 + ks * 16 + (lane >> 4) * 8) * 2);
                asm volatile("ldmatrix.sync.aligned.m8n8.x4.shared.b16 {%0,%1,%2,%3}, [%4];"
                    : "=r"(af[0]), "=r"(af[1]), "=r"(af[2]), "=r"(af[3]) : "r"(addr));
#pragma unroll
                for (int j = 0; j < 2; ++j)
                    asm volatile(
                        "mma.sync.aligned.m16n8k16.row.col.f32.f16.f16.f32 "
                        "{%0,%1,%2,%3}, {%4,%5,%6,%7}, {%8,%9}, {%0,%1,%2,%3};"
                        : "+f"(ea[im][j][0]), "+f"(ea[im][j][1]),
                          "+f"(ea[im][j][2]), "+f"(ea[im][j][3])
                        : "r"(af[0]), "r"(af[1]), "r"(af[2]), "r"(af[3]),
                          "r"(bf[j][0]), "r"(bf[j][1]));
            }
        }
        int gid = lane >> 2;
#pragma unroll
        for (int im = 0; im < 2; ++im) {
            if (im >= nMt) break;
            int mt = mBase + im;
#pragma unroll
            for (int j = 0; j < 2; ++j) {
                int c0 = j * 8 + (lane & 3) * 2;
#pragma unroll
                for (int hf = 0; hf < 2; ++hf) {
                    int t = mt * 16 + gid + hf * 8;
                    if (t < 41) {
                        float si = sinv[g][t];
                        float v0 = ea[im][j][hf * 2 + 0] * si;
                        float v1 = ea[im][j][hf * 2 + 1] * si;
                        size_t o = ((size_t)n * 41 + t) * 256 + h * 16 + c0;
                        __nv_bfloat162 pp = __floats2bfloat162_rn(v0, v1);
                        *(uint32_t*)(g_valb + o) = *(uint32_t*)&pp;
                    }
                }
            }
        }
    }
}

// -------- kernel 5: word attention per sequence (val read as bf16) --------
__global__ void __launch_bounds__(256) word_kernel(const float* __restrict__ qw) {
    __shared__ float sqw[200];
    __shared__ float sl[41];
    int n = blockIdx.x;
    int tid = threadIdx.x;
    if (tid < 200) sqw[tid] = qw[tid];
    __syncthreads();
    int warp = tid >> 5, lane = tid & 31;
    for (int t = warp; t < 41; t += 8) {
        const float* kr = g_kbuf + ((size_t)n * 41 + t) * 200;
        float s = 0.f;
        for (int e = lane; e < 200; e += 32) s = fmaf(kr[e], sqw[e], s);
#pragma unroll
        for (int o = 16; o; o >>= 1) s += __shfl_xor_sync(0xffffffffu, s, o);
        if (lane == 0) sl[t] = s * SCALE_F;
    }
    __syncthreads();
    if (tid < 32) {
        float v0 = (tid < 41) ? sl[tid] : -1e30f;
        float v1 = (tid + 32 < 41) ? sl[tid + 32] : -1e30f;
        float m = fmaxf(v0, v1);
#pragma unroll
        for (int o = 16; o; o >>= 1) m = fmaxf(m, __shfl_xor_sync(0xffffffffu, m, o));
        float e0 = (tid < 41) ? expf(v0 - m) : 0.f;
        float e1 = (tid + 32 < 41) ? expf(v1 - m) : 0.f;
        float s = e0 + e1;
#pragma unroll
        for (int o = 16; o; o >>= 1) s += __shfl_xor_sync(0xffffffffu, s, o);
        float inv = 1.f / s;
        if (tid < 41) sl[tid] = e0 * inv;
        if (tid + 32 < 41) sl[tid + 32] = e1 * inv;
    }
    __syncthreads();
    float acc = 0.f;
    const __nv_bfloat16* vr = g_valb + (size_t)n * 41 * 256 + tid;
#pragma unroll 8
    for (int t = 0; t < 41; ++t)
        acc = fmaf(sl[t], __bfloat162float(vr[(size_t)t * 256]), acc);
    g_rep[(size_t)n * 256 + tid] = acc;
}

// -------- kernel 6: mean over HIS, rank score, log-softmax over CDD --------
__global__ void __launch_bounds__(256) final_kernel(const float* __restrict__ Wl,
                                                    const float* __restrict__ blp,
                                                    float* __restrict__ out) {
    __shared__ float red[8];
    __shared__ float sc[5];
    int b = blockIdx.x;
    int tid = threadIdx.x;
    float wl = Wl[tid];
    for (int c = 0; c < 5; ++c) {
        const float* rp = g_rep + ((size_t)(b * 5 + c) * 50) * 256 + tid;
        float s = 0.f;
        for (int h = 0; h < 50; ++h) s += rp[(size_t)h * 256];
        s *= wl;
#pragma unroll
        for (int o = 16; o; o >>= 1) s += __shfl_xor_sync(0xffffffffu, s, o);
        if ((tid & 31) == 0) red[tid >> 5] = s;
        __syncthreads();
        if (tid < 8) {
            float v = red[tid];
#pragma unroll
            for (int o = 4; o; o >>= 1) v += __shfl_xor_sync(0xffu, v, o, 8);
            if (tid == 0) sc[c] = v * (1.f / 50.f) + blp[0];
        }
        __syncthreads();
    }
    if (tid == 0) {
        float m = sc[0];
        for (int c = 1; c < 5; ++c) m = fmaxf(m, sc[c]);
        float s = 0.f;
        for (int c = 0; c < 5; ++c) s += expf(sc[c] - m);
        float ls = logf(s);
        for (int c = 0; c < 5; ++c) out[b * 5 + c] = sc[c] - m - ls;
    }
}

// -------- host launcher --------
extern "C" void kernel_launch(void* const* d_in, const int* in_sizes, int n_in,
                              void* d_out, int out_size) {
    const int* cand = (const int*)d_in[0];
    const int* clk = (const int*)d_in[1];
    const float* emb = (const float*)d_in[2];
    const float* conv_w = (const float*)d_in[3];
    const float* conv_b = (const float*)d_in[4];
    const float* Wq = (const float*)d_in[5];
    const float* bq = (const float*)d_in[6];
    const float* Wv = (const float*)d_in[7];
    const float* bv = (const float*)d_in[8];
    const float* Wk = (const float*)d_in[9];
    const float* bk = (const float*)d_in[10];
    const float* qw = (const float*)d_in[11];
    const float* Wl = (const float*)d_in[12];
    const float* bl = (const float*)d_in[13];
    float* out = (float*)d_out;

    cudaFuncSetAttribute(attn_kernel, cudaFuncAttributeMaxDynamicSharedMemorySize,
                         ATTN_SMEM_BYTES);

    static const __nv_bfloat16* h_xub = nullptr;
    static const __nv_bfloat16* h_WcatTb = nullptr;
    static const __nv_bfloat16* h_WkTb = nullptr;
    static const __nv_bfloat16* h_valb = nullptr;
    static const float* h_bcat = nullptr;
    if (!h_xub) {
        void* p;
        cudaGetSymbolAddress(&p, g_xub);    h_xub = (const __nv_bfloat16*)p;
        cudaGetSymbolAddress(&p, g_WcatTb); h_WcatTb = (const __nv_bfloat16*)p;
        cudaGetSymbolAddress(&p, g_WkTb);   h_WkTb = (const __nv_bfloat16*)p;
        cudaGetSymbolAddress(&p, g_valb);   h_valb = (const __nv_bfloat16*)p;
        cudaGetSymbolAddress(&p, g_bcat);   h_bcat = (const float*)p;
    }

    prep_kernel<<<4352, 256>>>(Wq, bq, Wv, bv, Wk, conv_w);
    conv_mma_kernel<<<dim3(2, 169), 256>>>(cand, clk, emb, conv_b);
    gemm_mma_kernel<0><<<dim3(34, (NUROWS + 127) / 128), 256>>>(h_xub, h_WcatTb, h_bcat,
                                                                NUROWS, 4352);
    attn_kernel<<<dim3(4, NSEQ), 256, ATTN_SMEM_BYTES>>>();
    gemm_mma_kernel<1><<<dim3(2, (MVAL + 127) / 128), 256>>>(h_valb, h_WkTb, bk,
                                                             MVAL, NQD);
    word_kernel<<<NSEQ, 256>>>(qw);
    final_kernel<<<NB, 256>>>(Wl, bl, out);
}

// round 13
// speedup vs baseline: 7.2716x; 1.3015x over previous
#include <cuda_runtime.h>
#include <cuda_bf16.h>
#include <cuda_fp16.h>
#include <math.h>
#include <stdint.h>

#define NB 16
#define NCDD 5
#define NHIS 50
#define NS 20
#define NT 41
#define NE 300
#define NF 256
#define NH 16
#define NDV 16
#define NQD 200
#define NSEQ 4000
#define NUROWS 21600
#define MID_BASE 17600
#define MVAL 164000
#define SCALE_F 0.057735026918962576f
#define CONV_K 928

#define CP_ASYNC16(dst, src) \
    asm volatile("cp.async.cg.shared.global [%0], [%1], 16;" :: "r"(dst), "l"(src))
#define CP_COMMIT() asm volatile("cp.async.commit_group;" ::: "memory")
#define CP_WAIT0() asm volatile("cp.async.wait_group 0;" ::: "memory")

// -------- static device scratch (no allocations) --------
__device__ __nv_bfloat16 g_xub[NUROWS * NF];
__device__ __nv_bfloat16 g_WcatTb[4352 * 256];
__device__ float g_bcat[4352];
__device__ __nv_bfloat16 g_WkTb[200 * 256];
__device__ __nv_bfloat16 g_cwb[256 * CONV_K];
__device__ __nv_bfloat16 g_qb[(size_t)NUROWS * 4096];
__device__ float g_xv[(size_t)NUROWS * 256];
__device__ __nv_bfloat16 g_valb[(size_t)MVAL * NF];
__device__ float g_spart[(size_t)MVAL * 8];     // 8 deterministic partials of k.q_words per row
__device__ float g_rep[(size_t)NSEQ * NF];

// -------- kernel 0: pack transposed bf16 weights + bias --------
__global__ void prep_kernel(const float* __restrict__ Wq, const float* __restrict__ bq,
                            const float* __restrict__ Wv, const float* __restrict__ bv,
                            const float* __restrict__ Wk, const float* __restrict__ cw) {
    int idx = blockIdx.x * 256 + threadIdx.x;
    if (idx < 4352 * 256) {
        int nn = idx >> 8, k = idx & 255;
        float w;
        if (nn < 4096) {
            int h = nn >> 8, g = nn & 255;
            w = Wq[(h * 256 + k) * 256 + g];
        } else {
            int jj = nn - 4096;
            int h = jj >> 4, d = jj & 15;
            w = Wv[(h * 256 + k) * 16 + d];
        }
        g_WcatTb[idx] = __float2bfloat16(w);
    }
    if (idx < 200 * 256) {
        int nn = idx >> 8, k = idx & 255;
        g_WkTb[idx] = __float2bfloat16(Wk[k * 200 + nn]);
    }
    if (idx < 256 * CONV_K) {
        int f = idx / CONV_K, k = idx - f * CONV_K;
        g_cwb[idx] = __float2bfloat16(k < 900 ? cw[k * 256 + f] : 0.f);
    }
    if (idx < 4352) {
        if (idx < 4096) {
            int h = idx >> 8, g = idx & 255;
            g_bcat[idx] = bq[h * 256 + g];
        } else {
            g_bcat[idx] = bv[idx - 4096]; // bv folds through softmax (rows sum to 1)
        }
    }
}

// -------- kernel 1: conv as bf16 mma GEMM over im2col rows --------
__global__ void __launch_bounds__(256, 2) conv_mma_kernel(const int* __restrict__ cand,
                                                          const int* __restrict__ clk,
                                                          const float* __restrict__ emb,
                                                          const float* __restrict__ cb) {
    __shared__ __nv_bfloat16 As[128 * 40];
    __shared__ __nv_bfloat16 Bs[128 * 40];
    __shared__ int st[128][3];
    int tid = threadIdx.x;
    int w = tid >> 5, lane = tid & 31;
    int wm = w >> 2, wn = w & 3;
    int m0 = blockIdx.y * 128;
    int n0 = blockIdx.x * 128;

    if (tid < 128) {
        int row = m0 + tid;
        int t0 = -1, t1 = -1, t2 = -1;
        if (row < NUROWS) {
            if (row < 1600) {
                int bc = row / 20, t = row - bc * 20;
                const int* ct = cand + bc * 20;
                t0 = (t - 1 >= 0) ? ct[t - 1] : -1;
                t1 = ct[t];
                t2 = (t + 1 < 20) ? ct[t + 1] : 1;
            } else if (row < MID_BASE) {
                int r2 = row - 1600;
                int bh = r2 / 20, tt = r2 - bh * 20;
                const int* ht = clk + bh * 20;
                t0 = (tt == 0) ? 1 : ht[tt - 1];
                t1 = ht[tt];
                t2 = (tt + 1 < 20) ? ht[tt + 1] : -1;
            } else {
                int nn = row - MID_BASE;
                int b = nn / 250, rr = nn - b * 250;
                int c = rr / 50, hh = rr - c * 50;
                t0 = cand[(b * 5 + c) * 20 + 19];
                t1 = 1;
                t2 = clk[(b * 50 + hh) * 20 + 0];
            }
        }
        st[tid][0] = t0; st[tid][1] = t1; st[tid][2] = t2;
    }

    uint32_t As_u = (uint32_t)__cvta_generic_to_shared(As);
    uint32_t Bs_u = (uint32_t)__cvta_generic_to_shared(Bs);

    float acc[4][4][4];
#pragma unroll
    for (int i = 0; i < 4; ++i)
#pragma unroll
        for (int j = 0; j < 4; ++j)
#pragma unroll
            for (int e = 0; e < 4; ++e) acc[i][j][e] = 0.f;

    for (int kc = 0; kc < CONV_K; kc += 32) {
        __syncthreads();
#pragma unroll
        for (int j = 0; j < 4; ++j) {
            int i = tid + j * 256;
            int r = i >> 3, q = i & 7;
            int k0 = kc + q * 4;
            uint2 u = make_uint2(0, 0);
            if (k0 < 900) {
                int tap = k0 / 300;
                int e0 = k0 - tap * 300;
                int tok = st[r][tap];
                if (tok >= 0) {
                    float4 v = *(const float4*)(emb + (size_t)tok * 300 + e0);
                    __nv_bfloat162 p0 = __floats2bfloat162_rn(v.x, v.y);
                    __nv_bfloat162 p1 = __floats2bfloat162_rn(v.z, v.w);
                    u.x = *(uint32_t*)&p0;
                    u.y = *(uint32_t*)&p1;
                }
            }
            *(uint2*)(As + r * 40 + q * 4) = u;
        }
#pragma unroll
        for (int j = 0; j < 2; ++j) {
            int i = tid + j * 256;
            int r = i >> 2, kq = i & 3;
            *(uint4*)(Bs + r * 40 + kq * 8) =
                *(const uint4*)(g_cwb + (size_t)(n0 + r) * CONV_K + kc + kq * 8);
        }
        __syncthreads();
#pragma unroll
        for (int ks = 0; ks < 2; ++ks) {
            uint32_t a[4][4], b[4][2];
#pragma unroll
            for (int i = 0; i < 4; ++i) {
                uint32_t addr = As_u +
                    (uint32_t)(((wm * 64 + i * 16 + (lane & 15)) * 40 + ks * 16 + (lane >> 4) * 8) * 2);
                asm volatile("ldmatrix.sync.aligned.m8n8.x4.shared.b16 {%0,%1,%2,%3}, [%4];"
                    : "=r"(a[i][0]), "=r"(a[i][1]), "=r"(a[i][2]), "=r"(a[i][3]) : "r"(addr));
            }
#pragma unroll
            for (int j = 0; j < 4; ++j) {
                int nr = wn * 32 + j * 8 + (lane & 7);
                uint32_t addr = Bs_u +
                    (uint32_t)((nr * 40 + ks * 16 + ((lane >> 3) & 1) * 8) * 2);
                asm volatile("ldmatrix.sync.aligned.m8n8.x2.shared.b16 {%0,%1}, [%2];"
                    : "=r"(b[j][0]), "=r"(b[j][1]) : "r"(addr));
            }
#pragma unroll
            for (int i = 0; i < 4; ++i)
#pragma unroll
                for (int j = 0; j < 4; ++j)
                    asm volatile(
                        "mma.sync.aligned.m16n8k16.row.col.f32.bf16.bf16.f32 "
                        "{%0,%1,%2,%3}, {%4,%5,%6,%7}, {%8,%9}, {%0,%1,%2,%3};"
                        : "+f"(acc[i][j][0]), "+f"(acc[i][j][1]),
                          "+f"(acc[i][j][2]), "+f"(acc[i][j][3])
                        : "r"(a[i][0]), "r"(a[i][1]), "r"(a[i][2]), "r"(a[i][3]),
                          "r"(b[j][0]), "r"(b[j][1]));
        }
    }

    int gid = lane >> 2;
#pragma unroll
    for (int i = 0; i < 4; ++i) {
#pragma unroll
        for (int j = 0; j < 4; ++j) {
            int c0 = n0 + wn * 32 + j * 8 + (lane & 3) * 2;
            float b0 = cb[c0], b1 = cb[c0 + 1];
#pragma unroll
            for (int hf = 0; hf < 2; ++hf) {
                int m = m0 + wm * 64 + i * 16 + gid + hf * 8;
                if (m >= NUROWS) continue;
                float v0 = fmaxf(acc[i][j][hf * 2 + 0] + b0, 0.f);
                float v1 = fmaxf(acc[i][j][hf * 2 + 1] + b1, 0.f);
                __nv_bfloat162 p = __floats2bfloat162_rn(v0, v1);
                *(uint32_t*)(g_xub + (size_t)m * 256 + c0) = *(uint32_t*)&p;
            }
        }
    }
}

// -------- bf16 tensor-core GEMM, K=256, register-prefetch double buffered --------
// MODE 0: n<4096 -> g_qb bf16; n>=4096 -> g_xv fp32.
// MODE 1: fused word-k: s-partials = sum_c tanh(v+bk)*qw[c] -> g_spart (no kbuf).
template <int MODE>
__global__ void __launch_bounds__(256, 2) gemm_mma_kernel(const __nv_bfloat16* __restrict__ Ag,
                                                          const __nv_bfloat16* __restrict__ Bt,
                                                          const float* __restrict__ bias,
                                                          const float* __restrict__ qw,
                                                          int M, int N) {
    __shared__ __nv_bfloat16 As[128 * 56];
    __shared__ __nv_bfloat16 Bs[128 * 56];
    __shared__ float qws[200];
    int tid = threadIdx.x;
    int w = tid >> 5, lane = tid & 31;
    int wm = w >> 2, wn = w & 3;
    int m0 = blockIdx.y * 128;
    int n0 = blockIdx.x * 128;

    if (MODE == 1 && tid < 200) qws[tid] = qw[tid];

    uint32_t As_u = (uint32_t)__cvta_generic_to_shared(As);
    uint32_t Bs_u = (uint32_t)__cvta_generic_to_shared(Bs);

    float acc[4][4][4];
#pragma unroll
    for (int i = 0; i < 4; ++i)
#pragma unroll
        for (int j = 0; j < 4; ++j)
#pragma unroll
            for (int e = 0; e < 4; ++e) acc[i][j][e] = 0.f;

    uint4 pre[4];
#pragma unroll
    for (int j = 0; j < 4; ++j) {
        int i = tid + j * 256;
        int r = (i >> 2) & 127;
        int kq = i & 3;
        uint4 v = make_uint4(0, 0, 0, 0);
        if (i < 512) {
            int m = m0 + r;
            if (m < M) v = *(const uint4*)(Ag + (size_t)m * 256 + kq * 8);
        } else {
            int nn = n0 + r;
            if (nn < N) v = *(const uint4*)(Bt + (size_t)nn * 256 + kq * 8);
        }
        pre[j] = v;
    }

    for (int kc = 0; kc < 256; kc += 32) {
        __syncthreads();
#pragma unroll
        for (int j = 0; j < 4; ++j) {
            int i = tid + j * 256;
            int r = (i >> 2) & 127;
            int kq = i & 3;
            if (i < 512) *(uint4*)(As + r * 56 + kq * 8) = pre[j];
            else         *(uint4*)(Bs + r * 56 + kq * 8) = pre[j];
        }
        __syncthreads();
        if (kc + 32 < 256) {
            int kn = kc + 32;
#pragma unroll
            for (int j = 0; j < 4; ++j) {
                int i = tid + j * 256;
                int r = (i >> 2) & 127;
                int kq = i & 3;
                uint4 v = make_uint4(0, 0, 0, 0);
                if (i < 512) {
                    int m = m0 + r;
                    if (m < M) v = *(const uint4*)(Ag + (size_t)m * 256 + kn + kq * 8);
                } else {
                    int nn = n0 + r;
                    if (nn < N) v = *(const uint4*)(Bt + (size_t)nn * 256 + kn + kq * 8);
                }
                pre[j] = v;
            }
        }
#pragma unroll
        for (int ks = 0; ks < 2; ++ks) {
            uint32_t a[4][4], b[4][2];
#pragma unroll
            for (int i = 0; i < 4; ++i) {
                uint32_t addr = As_u +
                    (uint32_t)(((wm * 64 + i * 16 + (lane & 15)) * 56 + ks * 16 + (lane >> 4) * 8) * 2);
                asm volatile("ldmatrix.sync.aligned.m8n8.x4.shared.b16 {%0,%1,%2,%3}, [%4];"
                    : "=r"(a[i][0]), "=r"(a[i][1]), "=r"(a[i][2]), "=r"(a[i][3]) : "r"(addr));
            }
#pragma unroll
            for (int j = 0; j < 4; ++j) {
                int nr = wn * 32 + j * 8 + (lane & 7);
                uint32_t addr = Bs_u +
                    (uint32_t)((nr * 56 + ks * 16 + ((lane >> 3) & 1) * 8) * 2);
                asm volatile("ldmatrix.sync.aligned.m8n8.x2.shared.b16 {%0,%1}, [%2];"
                    : "=r"(b[j][0]), "=r"(b[j][1]) : "r"(addr));
            }
#pragma unroll
            for (int i = 0; i < 4; ++i)
#pragma unroll
                for (int j = 0; j < 4; ++j)
                    asm volatile(
                        "mma.sync.aligned.m16n8k16.row.col.f32.bf16.bf16.f32 "
                        "{%0,%1,%2,%3}, {%4,%5,%6,%7}, {%8,%9}, {%0,%1,%2,%3};"
                        : "+f"(acc[i][j][0]), "+f"(acc[i][j][1]),
                          "+f"(acc[i][j][2]), "+f"(acc[i][j][3])
                        : "r"(a[i][0]), "r"(a[i][1]), "r"(a[i][2]), "r"(a[i][3]),
                          "r"(b[j][0]), "r"(b[j][1]));
        }
    }

    int gid = lane >> 2;
    if (MODE == 0) {
#pragma unroll
        for (int i = 0; i < 4; ++i) {
#pragma unroll
            for (int j = 0; j < 4; ++j) {
                int c0 = n0 + wn * 32 + j * 8 + (lane & 3) * 2;
                float b0 = bias[c0], b1 = bias[c0 + 1];
#pragma unroll
                for (int hf = 0; hf < 2; ++hf) {
                    int m = m0 + wm * 64 + i * 16 + gid + hf * 8;
                    if (m >= M) continue;
                    float v0 = acc[i][j][hf * 2 + 0] + b0;
                    float v1 = acc[i][j][hf * 2 + 1] + b1;
                    if (c0 < 4096) {
                        __nv_bfloat162 p = __floats2bfloat162_rn(v0, v1);
                        *(uint32_t*)(g_qb + (size_t)m * 4096 + c0) = *(uint32_t*)&p;
                    } else {
                        *(float2*)(g_xv + (size_t)m * 256 + (c0 - 4096)) =
                            make_float2(v0, v1);
                    }
                }
            }
        }
    } else {
        int t4 = lane & 3;
#pragma unroll
        for (int i = 0; i < 4; ++i) {
#pragma unroll
            for (int hf = 0; hf < 2; ++hf) {
                int m = m0 + wm * 64 + i * 16 + gid + hf * 8;
                float part = 0.f;
#pragma unroll
                for (int j = 0; j < 4; ++j) {
                    int c0 = n0 + wn * 32 + j * 8 + t4 * 2;
                    if (c0 < N)
                        part += tanhf(acc[i][j][hf * 2 + 0] + bias[c0]) * qws[c0];
                    if (c0 + 1 < N)
                        part += tanhf(acc[i][j][hf * 2 + 1] + bias[c0 + 1]) * qws[c0 + 1];
                }
                part += __shfl_xor_sync(0xffffffffu, part, 1);
                part += __shfl_xor_sync(0xffffffffu, part, 2);
                if (t4 == 0 && m < M)
                    g_spart[(size_t)m * 8 + (n0 >> 7) * 4 + wn] = part;
            }
        }
    }
}

// -------- kernel 3: attention; cp.async staging, fp16 scores, fp16 mma epilogue --------
// smem: xb 5904 | qbA 4x5904=23616 | scmA 4x(41x48 half)=15744 | xvTA 4x1792=7168 = 52432
#define ATTN_SMEM_BYTES 52432

__global__ void __launch_bounds__(256, 3) attn_kernel() {
    extern __shared__ char smc[];
    __nv_bfloat16* xb = (__nv_bfloat16*)smc;
    __nv_bfloat16* qbA = (__nv_bfloat16*)(smc + 5904);
    half* scA = (half*)(smc + 29520);
    half* xvTA = (half*)(smc + 45264);
    __shared__ int rows[41];
    __shared__ float sinv[4][48];

    int n = blockIdx.y;
    int hb = blockIdx.x;
    int tid = threadIdx.x;
    int g = tid >> 6;
    int l = tid & 63;
    int w = l >> 5;
    int lane = l & 31;
    int h = hb * 4 + g;

    __nv_bfloat16* qb = qbA + g * 2952;      // 5904 B / 2
    half* scm = scA + g * 1968;              // 3936 B / 2, row pitch 48 halves
    half* xvT = xvTA + g * 896;

    uint32_t xb_u = (uint32_t)__cvta_generic_to_shared(xb);
    uint32_t qb_u = (uint32_t)__cvta_generic_to_shared(qb);
    uint32_t xvT_u = (uint32_t)__cvta_generic_to_shared(xvT);

    if (tid < 41) {
        int b = n / 250, rr = n - b * 250;
        int c = rr / 50, hh = rr - c * 50;
        int t = tid, r;
        if (t < 20)       r = (b * 5 + c) * 20 + t;
        else if (t == 20) r = MID_BASE + n;
        else              r = 1600 + (b * 50 + hh) * 20 + (t - 21);
        rows[t] = r;
    }
    __syncthreads();

    // stage xv transposed fp16 [d][s]; zero pad s in [41,56)
    for (int i = l; i < 240; i += 64) {
        int d = i / 15, s = 41 + i % 15;
        xvT[d * 56 + s] = __float2half(0.f);
    }
    for (int i = l; i < 164; i += 64) {
        int s = i >> 2, dq = (i & 3) * 4;
        float4 v = *(const float4*)(g_xv + (size_t)rows[s] * 256 + h * 16 + dq);
        xvT[(dq + 0) * 56 + s] = __float2half(v.x);
        xvT[(dq + 1) * 56 + s] = __float2half(v.y);
        xvT[(dq + 2) * 56 + s] = __float2half(v.z);
        xvT[(dq + 3) * 56 + s] = __float2half(v.w);
    }

    float acc[3][3][4];
#pragma unroll
    for (int i = 0; i < 3; ++i)
#pragma unroll
        for (int j = 0; j < 3; ++j)
#pragma unroll
            for (int e = 0; e < 4; ++e) acc[i][j][e] = 0.f;

    for (int kc = 0; kc < 256; kc += 64) {
        __syncthreads();
        // stage x chunk (whole block) via cp.async
        for (int i = tid; i < 328; i += 256) {
            int t = i >> 3, kq = i & 7;
            CP_ASYNC16(xb_u + (uint32_t)(t * 144 + kq * 16),
                       g_xub + (size_t)rows[t] * 256 + kc + kq * 8);
        }
        // stage q chunk (per group) via cp.async
        for (int i = l; i < 328; i += 64) {
            int t = i >> 3, kq = i & 7;
            CP_ASYNC16(qb_u + (uint32_t)(t * 144 + kq * 16),
                       g_qb + (size_t)rows[t] * 4096 + h * 256 + kc + kq * 8);
        }
        CP_COMMIT();
        CP_WAIT0();
        __syncthreads();
#pragma unroll
        for (int ks = 0; ks < 4; ++ks) {
            uint32_t a[3][4], b[3][2];
#pragma unroll
            for (int i = 0; i < 3; ++i) {
                uint32_t addr = qb_u +
                    (uint32_t)(((i * 16 + (lane & 15)) * 72 + ks * 16 + (lane >> 4) * 8) * 2);
                asm volatile("ldmatrix.sync.aligned.m8n8.x4.shared.b16 {%0,%1,%2,%3}, [%4];"
                    : "=r"(a[i][0]), "=r"(a[i][1]), "=r"(a[i][2]), "=r"(a[i][3]) : "r"(addr));
            }
#pragma unroll
            for (int j = 0; j < 3; ++j) {
                int nr = w * 24 + j * 8 + (lane & 7);
                uint32_t addr = xb_u +
                    (uint32_t)((nr * 72 + ks * 16 + ((lane >> 3) & 1) * 8) * 2);
                asm volatile("ldmatrix.sync.aligned.m8n8.x2.shared.b16 {%0,%1}, [%2];"
                    : "=r"(b[j][0]), "=r"(b[j][1]) : "r"(addr));
            }
#pragma unroll
            for (int i = 0; i < 3; ++i)
#pragma unroll
                for (int j = 0; j < 3; ++j)
                    asm volatile(
                        "mma.sync.aligned.m16n8k16.row.col.f32.bf16.bf16.f32 "
                        "{%0,%1,%2,%3}, {%4,%5,%6,%7}, {%8,%9}, {%0,%1,%2,%3};"
                        : "+f"(acc[i][j][0]), "+f"(acc[i][j][1]),
                          "+f"(acc[i][j][2]), "+f"(acc[i][j][3])
                        : "r"(a[i][0]), "r"(a[i][1]), "r"(a[i][2]), "r"(a[i][3]),
                          "r"(b[j][0]), "r"(b[j][1]));
        }
    }

    // write scores to scm fp16 (pitch 48 halves)
    {
        int gid = lane >> 2, t4 = lane & 3;
#pragma unroll
        for (int i = 0; i < 3; ++i) {
#pragma unroll
            for (int j = 0; j < 3; ++j) {
                int c0 = w * 24 + j * 8 + t4 * 2;
                int r0 = i * 16 + gid;
                int r1 = r0 + 8;
                if (c0 + 1 < 41) {
                    if (r0 < 41) *(half2*)(scm + r0 * 48 + c0) =
                        __floats2half2_rn(acc[i][j][0] * SCALE_F, acc[i][j][1] * SCALE_F);
                    if (r1 < 41) *(half2*)(scm + r1 * 48 + c0) =
                        __floats2half2_rn(acc[i][j][2] * SCALE_F, acc[i][j][3] * SCALE_F);
                } else if (c0 < 41) {
                    if (r0 < 41) scm[r0 * 48 + c0] = __float2half(acc[i][j][0] * SCALE_F);
                    if (r1 < 41) scm[r1 * 48 + c0] = __float2half(acc[i][j][2] * SCALE_F);
                }
            }
        }
    }
    __syncthreads();

    // softmax: one row per thread; UNNORMALIZED exp -> fp16 P in qb region; 1/sum -> sinv
    half* Pb = (half*)qb;
    if (l < 41) {
        const uint4* pr4 = (const uint4*)(scm + l * 48);
        float s40 = __half2float(scm[l * 48 + 40]);
        float mx = s40;
#pragma unroll
        for (int j = 0; j < 5; ++j) {
            uint4 u = pr4[j];
            const half2* hp = (const half2*)&u;
#pragma unroll
            for (int e = 0; e < 4; ++e) {
                float2 f = __half22float2(hp[e]);
                mx = fmaxf(mx, fmaxf(f.x, f.y));
            }
        }
        float sum = 0.f;
        uint32_t* Pr = (uint32_t*)(Pb + l * 56);
#pragma unroll
        for (int j = 0; j < 5; ++j) {
            uint4 u = pr4[j];
            const half2* hp = (const half2*)&u;
#pragma unroll
            for (int e = 0; e < 4; ++e) {
                float2 f = __half22float2(hp[e]);
                float e0 = __expf(f.x - mx), e1 = __expf(f.y - mx);
                sum += e0 + e1;
                half2 hh = __floats2half2_rn(e0, e1);
                Pr[j * 4 + e] = *(uint32_t*)&hh;
            }
        }
        float e40 = __expf(s40 - mx);
        sum += e40;
        half2 h40 = __floats2half2_rn(e40, 0.f);
        Pr[20] = *(uint32_t*)&h40;
#pragma unroll
        for (int j = 21; j < 28; ++j) Pr[j] = 0u;
        sinv[g][l] = 1.f / sum;
    }
    __syncthreads();

    // epilogue mma: out = (expP @ xv) * sinv[t]; warp0 m-tiles {0,1}, warp1 {2}
    {
        int nMt = (w == 0) ? 2 : 1;
        int mBase = (w == 0) ? 0 : 2;
        float ea[2][2][4];
#pragma unroll
        for (int i = 0; i < 2; ++i)
#pragma unroll
            for (int j = 0; j < 2; ++j)
#pragma unroll
                for (int e = 0; e < 4; ++e) ea[i][j][e] = 0.f;
#pragma unroll
        for (int ks = 0; ks < 3; ++ks) {
            uint32_t bf[2][2];
#pragma unroll
            for (int j = 0; j < 2; ++j) {
                uint32_t addr = xvT_u +
                    (uint32_t)(((j * 8 + (lane & 7)) * 56 + ks * 16 + ((lane >> 3) & 1) * 8) * 2);
                asm volatile("ldmatrix.sync.aligned.m8n8.x2.shared.b16 {%0,%1}, [%2];"
                    : "=r"(bf[j][0]), "=r"(bf[j][1]) : "r"(addr));
            }
#pragma unroll
            for (int im = 0; im < 2; ++im) {
                if (im >= nMt) break;
                int mt = mBase + im;
                uint32_t af[4];
                uint32_t addr = qb_u +
                    (uint32_t)(((mt * 16 + (lane & 15)) * 56 + ks * 16 + (lane >> 4) * 8) * 2);
                asm volatile("ldmatrix.sync.aligned.m8n8.x4.shared.b16 {%0,%1,%2,%3}, [%4];"
                    : "=r"(af[0]), "=r"(af[1]), "=r"(af[2]), "=r"(af[3]) : "r"(addr));
#pragma unroll
                for (int j = 0; j < 2; ++j)
                    asm volatile(
                        "mma.sync.aligned.m16n8k16.row.col.f32.f16.f16.f32 "
                        "{%0,%1,%2,%3}, {%4,%5,%6,%7}, {%8,%9}, {%0,%1,%2,%3};"
                        : "+f"(ea[im][j][0]), "+f"(ea[im][j][1]),
                          "+f"(ea[im][j][2]), "+f"(ea[im][j][3])
                        : "r"(af[0]), "r"(af[1]), "r"(af[2]), "r"(af[3]),
                          "r"(bf[j][0]), "r"(bf[j][1]));
            }
        }
        int gid = lane >> 2;
#pragma unroll
        for (int im = 0; im < 2; ++im) {
            if (im >= nMt) break;
            int mt = mBase + im;
#pragma unroll
            for (int j = 0; j < 2; ++j) {
                int c0 = j * 8 + (lane & 3) * 2;
#pragma unroll
                for (int hf = 0; hf < 2; ++hf) {
                    int t = mt * 16 + gid + hf * 8;
                    if (t < 41) {
                        float si = sinv[g][t];
                        float v0 = ea[im][j][hf * 2 + 0] * si;
                        float v1 = ea[im][j][hf * 2 + 1] * si;
                        size_t o = ((size_t)n * 41 + t) * 256 + h * 16 + c0;
                        __nv_bfloat162 pp = __floats2bfloat162_rn(v0, v1);
                        *(uint32_t*)(g_valb + o) = *(uint32_t*)&pp;
                    }
                }
            }
        }
    }
}

// -------- kernel 5: word attention per sequence (s from g_spart, val bf16) --------
__global__ void __launch_bounds__(256) word_kernel() {
    __shared__ float sl[41];
    int n = blockIdx.x;
    int tid = threadIdx.x;
    if (tid < 41) {
        const float4* sp = (const float4*)(g_spart + (size_t)(n * 41 + tid) * 8);
        float4 a = sp[0], b = sp[1];
        sl[tid] = ((a.x + a.y) + (a.z + a.w) + (b.x + b.y) + (b.z + b.w)) * SCALE_F;
    }
    __syncthreads();
    if (tid < 32) {
        float v0 = (tid < 41) ? sl[tid] : -1e30f;
        float v1 = (tid + 32 < 41) ? sl[tid + 32] : -1e30f;
        float m = fmaxf(v0, v1);
#pragma unroll
        for (int o = 16; o; o >>= 1) m = fmaxf(m, __shfl_xor_sync(0xffffffffu, m, o));
        float e0 = (tid < 41) ? expf(v0 - m) : 0.f;
        float e1 = (tid + 32 < 41) ? expf(v1 - m) : 0.f;
        float s = e0 + e1;
#pragma unroll
        for (int o = 16; o; o >>= 1) s += __shfl_xor_sync(0xffffffffu, s, o);
        float inv = 1.f / s;
        if (tid < 41) sl[tid] = e0 * inv;
        if (tid + 32 < 41) sl[tid + 32] = e1 * inv;
    }
    __syncthreads();
    float acc = 0.f;
    const __nv_bfloat16* vr = g_valb + (size_t)n * 41 * 256 + tid;
#pragma unroll 8
    for (int t = 0; t < 41; ++t)
        acc = fmaf(sl[t], __bfloat162float(vr[(size_t)t * 256]), acc);
    g_rep[(size_t)n * 256 + tid] = acc;
}

// -------- kernel 6: mean over HIS, rank score, log-softmax over CDD --------
__global__ void __launch_bounds__(256) final_kernel(const float* __restrict__ Wl,
                                                    const float* __restrict__ blp,
                                                    float* __restrict__ out) {
    __shared__ float red[8];
    __shared__ float sc[5];
    int b = blockIdx.x;
    int tid = threadIdx.x;
    float wl = Wl[tid];
    for (int c = 0; c < 5; ++c) {
        const float* rp = g_rep + ((size_t)(b * 5 + c) * 50) * 256 + tid;
        float s = 0.f;
        for (int h = 0; h < 50; ++h) s += rp[(size_t)h * 256];
        s *= wl;
#pragma unroll
        for (int o = 16; o; o >>= 1) s += __shfl_xor_sync(0xffffffffu, s, o);
        if ((tid & 31) == 0) red[tid >> 5] = s;
        __syncthreads();
        if (tid < 8) {
            float v = red[tid];
#pragma unroll
            for (int o = 4; o; o >>= 1) v += __shfl_xor_sync(0xffu, v, o, 8);
            if (tid == 0) sc[c] = v * (1.f / 50.f) + blp[0];
        }
        __syncthreads();
    }
    if (tid == 0) {
        float m = sc[0];
        for (int c = 1; c < 5; ++c) m = fmaxf(m, sc[c]);
        float s = 0.f;
        for (int c = 0; c < 5; ++c) s += expf(sc[c] - m);
        float ls = logf(s);
        for (int c = 0; c < 5; ++c) out[b * 5 + c] = sc[c] - m - ls;
    }
}

// -------- host launcher --------
extern "C" void kernel_launch(void* const* d_in, const int* in_sizes, int n_in,
                              void* d_out, int out_size) {
    const int* cand = (const int*)d_in[0];
    const int* clk = (const int*)d_in[1];
    const float* emb = (const float*)d_in[2];
    const float* conv_w = (const float*)d_in[3];
    const float* conv_b = (const float*)d_in[4];
    const float* Wq = (const float*)d_in[5];
    const float* bq = (const float*)d_in[6];
    const float* Wv = (const float*)d_in[7];
    const float* bv = (const float*)d_in[8];
    const float* Wk = (const float*)d_in[9];
    const float* bk = (const float*)d_in[10];
    const float* qw = (const float*)d_in[11];
    const float* Wl = (const float*)d_in[12];
    const float* bl = (const float*)d_in[13];
    float* out = (float*)d_out;

    cudaFuncSetAttribute(attn_kernel, cudaFuncAttributeMaxDynamicSharedMemorySize,
                         ATTN_SMEM_BYTES);

    static const __nv_bfloat16* h_xub = nullptr;
    static const __nv_bfloat16* h_WcatTb = nullptr;
    static const __nv_bfloat16* h_WkTb = nullptr;
    static const __nv_bfloat16* h_valb = nullptr;
    static const float* h_bcat = nullptr;
    if (!h_xub) {
        void* p;
        cudaGetSymbolAddress(&p, g_xub);    h_xub = (const __nv_bfloat16*)p;
        cudaGetSymbolAddress(&p, g_WcatTb); h_WcatTb = (const __nv_bfloat16*)p;
        cudaGetSymbolAddress(&p, g_WkTb);   h_WkTb = (const __nv_bfloat16*)p;
        cudaGetSymbolAddress(&p, g_valb);   h_valb = (const __nv_bfloat16*)p;
        cudaGetSymbolAddress(&p, g_bcat);   h_bcat = (const float*)p;
    }

    prep_kernel<<<4352, 256>>>(Wq, bq, Wv, bv, Wk, conv_w);
    conv_mma_kernel<<<dim3(2, 169), 256>>>(cand, clk, emb, conv_b);
    gemm_mma_kernel<0><<<dim3(34, (NUROWS + 127) / 128), 256>>>(h_xub, h_WcatTb, h_bcat,
                                                                nullptr, NUROWS, 4352);
    attn_kernel<<<dim3(4, NSEQ), 256, ATTN_SMEM_BYTES>>>();
    gemm_mma_kernel<1><<<dim3(2, (MVAL + 127) / 128), 256>>>(h_valb, h_WkTb, bk,
                                                             qw, MVAL, NQD);
    word_kernel<<<NSEQ, 256>>>();
    final_kernel<<<NB, 256>>>(Wl, bl, out);
}

// round 14
// speedup vs baseline: 7.4928x; 1.0304x over previous
#include <cuda_runtime.h>
#include <cuda_bf16.h>
#include <cuda_fp16.h>
#include <math.h>
#include <stdint.h>

#define NB 16
#define NCDD 5
#define NHIS 50
#define NS 20
#define NT 41
#define NE 300
#define NF 256
#define NH 16
#define NDV 16
#define NQD 200
#define NSEQ 4000
#define NUROWS 21600
#define MID_BASE 17600
#define MVAL 164000
#define SCALE_F 0.057735026918962576f
#define CONV_K 928

#define CP_ASYNC16(dst, src) \
    asm volatile("cp.async.cg.shared.global [%0], [%1], 16;" :: "r"(dst), "l"(src))
#define CP_COMMIT() asm volatile("cp.async.commit_group;" ::: "memory")
#define CP_WAIT0() asm volatile("cp.async.wait_group 0;" ::: "memory")

// -------- static device scratch (no allocations) --------
__device__ __nv_bfloat16 g_xub[NUROWS * NF];
__device__ __nv_bfloat16 g_WcatTb[4352 * 256];
__device__ float g_bcat[4352];
__device__ __nv_bfloat16 g_WkTb[200 * 256];
__device__ __nv_bfloat16 g_cwb[256 * CONV_K];
__device__ __nv_bfloat16 g_qb[(size_t)NUROWS * 4096];
__device__ float g_xv[(size_t)NUROWS * 256];
__device__ __nv_bfloat16 g_valb[(size_t)MVAL * NF];
__device__ float g_spart[(size_t)MVAL * 8];
__device__ float g_rep[(size_t)NSEQ * NF];

// -------- kernel 0: pack transposed bf16 weights + bias --------
__global__ void prep_kernel(const float* __restrict__ Wq, const float* __restrict__ bq,
                            const float* __restrict__ Wv, const float* __restrict__ bv,
                            const float* __restrict__ Wk, const float* __restrict__ cw) {
    int idx = blockIdx.x * 256 + threadIdx.x;
    if (idx < 4352 * 256) {
        int nn = idx >> 8, k = idx & 255;
        float w;
        if (nn < 4096) {
            int h = nn >> 8, g = nn & 255;
            w = Wq[(h * 256 + k) * 256 + g];
        } else {
            int jj = nn - 4096;
            int h = jj >> 4, d = jj & 15;
            w = Wv[(h * 256 + k) * 16 + d];
        }
        g_WcatTb[idx] = __float2bfloat16(w);
    }
    if (idx < 200 * 256) {
        int nn = idx >> 8, k = idx & 255;
        g_WkTb[idx] = __float2bfloat16(Wk[k * 200 + nn]);
    }
    if (idx < 256 * CONV_K) {
        int f = idx / CONV_K, k = idx - f * CONV_K;
        g_cwb[idx] = __float2bfloat16(k < 900 ? cw[k * 256 + f] : 0.f);
    }
    if (idx < 4352) {
        if (idx < 4096) {
            int h = idx >> 8, g = idx & 255;
            g_bcat[idx] = bq[h * 256 + g];
        } else {
            g_bcat[idx] = bv[idx - 4096]; // bv folds through softmax (rows sum to 1)
        }
    }
}

// -------- kernel 1: conv as bf16 mma GEMM over im2col rows --------
__global__ void __launch_bounds__(256, 2) conv_mma_kernel(const int* __restrict__ cand,
                                                          const int* __restrict__ clk,
                                                          const float* __restrict__ emb,
                                                          const float* __restrict__ cb) {
    __shared__ __nv_bfloat16 As[128 * 40];
    __shared__ __nv_bfloat16 Bs[128 * 40];
    __shared__ int st[128][3];
    int tid = threadIdx.x;
    int w = tid >> 5, lane = tid & 31;
    int wm = w >> 2, wn = w & 3;
    int m0 = blockIdx.y * 128;
    int n0 = blockIdx.x * 128;

    if (tid < 128) {
        int row = m0 + tid;
        int t0 = -1, t1 = -1, t2 = -1;
        if (row < NUROWS) {
            if (row < 1600) {
                int bc = row / 20, t = row - bc * 20;
                const int* ct = cand + bc * 20;
                t0 = (t - 1 >= 0) ? ct[t - 1] : -1;
                t1 = ct[t];
                t2 = (t + 1 < 20) ? ct[t + 1] : 1;
            } else if (row < MID_BASE) {
                int r2 = row - 1600;
                int bh = r2 / 20, tt = r2 - bh * 20;
                const int* ht = clk + bh * 20;
                t0 = (tt == 0) ? 1 : ht[tt - 1];
                t1 = ht[tt];
                t2 = (tt + 1 < 20) ? ht[tt + 1] : -1;
            } else {
                int nn = row - MID_BASE;
                int b = nn / 250, rr = nn - b * 250;
                int c = rr / 50, hh = rr - c * 50;
                t0 = cand[(b * 5 + c) * 20 + 19];
                t1 = 1;
                t2 = clk[(b * 50 + hh) * 20 + 0];
            }
        }
        st[tid][0] = t0; st[tid][1] = t1; st[tid][2] = t2;
    }

    uint32_t As_u = (uint32_t)__cvta_generic_to_shared(As);
    uint32_t Bs_u = (uint32_t)__cvta_generic_to_shared(Bs);

    float acc[4][4][4];
#pragma unroll
    for (int i = 0; i < 4; ++i)
#pragma unroll
        for (int j = 0; j < 4; ++j)
#pragma unroll
            for (int e = 0; e < 4; ++e) acc[i][j][e] = 0.f;

    for (int kc = 0; kc < CONV_K; kc += 32) {
        __syncthreads();
#pragma unroll
        for (int j = 0; j < 4; ++j) {
            int i = tid + j * 256;
            int r = i >> 3, q = i & 7;
            int k0 = kc + q * 4;
            uint2 u = make_uint2(0, 0);
            if (k0 < 900) {
                int tap = k0 / 300;
                int e0 = k0 - tap * 300;
                int tok = st[r][tap];
                if (tok >= 0) {
                    float4 v = *(const float4*)(emb + (size_t)tok * 300 + e0);
                    __nv_bfloat162 p0 = __floats2bfloat162_rn(v.x, v.y);
                    __nv_bfloat162 p1 = __floats2bfloat162_rn(v.z, v.w);
                    u.x = *(uint32_t*)&p0;
                    u.y = *(uint32_t*)&p1;
                }
            }
            *(uint2*)(As + r * 40 + q * 4) = u;
        }
#pragma unroll
        for (int j = 0; j < 2; ++j) {
            int i = tid + j * 256;
            int r = i >> 2, kq = i & 3;
            *(uint4*)(Bs + r * 40 + kq * 8) =
                *(const uint4*)(g_cwb + (size_t)(n0 + r) * CONV_K + kc + kq * 8);
        }
        __syncthreads();
#pragma unroll
        for (int ks = 0; ks < 2; ++ks) {
            uint32_t a[4][4], b[4][2];
#pragma unroll
            for (int i = 0; i < 4; ++i) {
                uint32_t addr = As_u +
                    (uint32_t)(((wm * 64 + i * 16 + (lane & 15)) * 40 + ks * 16 + (lane >> 4) * 8) * 2);
                asm volatile("ldmatrix.sync.aligned.m8n8.x4.shared.b16 {%0,%1,%2,%3}, [%4];"
                    : "=r"(a[i][0]), "=r"(a[i][1]), "=r"(a[i][2]), "=r"(a[i][3]) : "r"(addr));
            }
#pragma unroll
            for (int j = 0; j < 4; ++j) {
                int nr = wn * 32 + j * 8 + (lane & 7);
                uint32_t addr = Bs_u +
                    (uint32_t)((nr * 40 + ks * 16 + ((lane >> 3) & 1) * 8) * 2);
                asm volatile("ldmatrix.sync.aligned.m8n8.x2.shared.b16 {%0,%1}, [%2];"
                    : "=r"(b[j][0]), "=r"(b[j][1]) : "r"(addr));
            }
#pragma unroll
            for (int i = 0; i < 4; ++i)
#pragma unroll
                for (int j = 0; j < 4; ++j)
                    asm volatile(
                        "mma.sync.aligned.m16n8k16.row.col.f32.bf16.bf16.f32 "
                        "{%0,%1,%2,%3}, {%4,%5,%6,%7}, {%8,%9}, {%0,%1,%2,%3};"
                        : "+f"(acc[i][j][0]), "+f"(acc[i][j][1]),
                          "+f"(acc[i][j][2]), "+f"(acc[i][j][3])
                        : "r"(a[i][0]), "r"(a[i][1]), "r"(a[i][2]), "r"(a[i][3]),
                          "r"(b[j][0]), "r"(b[j][1]));
        }
    }

    int gid = lane >> 2;
#pragma unroll
    for (int i = 0; i < 4; ++i) {
#pragma unroll
        for (int j = 0; j < 4; ++j) {
            int c0 = n0 + wn * 32 + j * 8 + (lane & 3) * 2;
            float b0 = cb[c0], b1 = cb[c0 + 1];
#pragma unroll
            for (int hf = 0; hf < 2; ++hf) {
                int m = m0 + wm * 64 + i * 16 + gid + hf * 8;
                if (m >= NUROWS) continue;
                float v0 = fmaxf(acc[i][j][hf * 2 + 0] + b0, 0.f);
                float v1 = fmaxf(acc[i][j][hf * 2 + 1] + b1, 0.f);
                __nv_bfloat162 p = __floats2bfloat162_rn(v0, v1);
                *(uint32_t*)(g_xub + (size_t)m * 256 + c0) = *(uint32_t*)&p;
            }
        }
    }
}

// -------- bf16 tensor-core GEMM, K=256, register-prefetch double buffered --------
// MODE 0: n<4096 -> g_qb bf16; n>=4096 -> g_xv fp32.
// MODE 1: fused word-k partials -> g_spart.
template <int MODE>
__global__ void __launch_bounds__(256, 2) gemm_mma_kernel(const __nv_bfloat16* __restrict__ Ag,
                                                          const __nv_bfloat16* __restrict__ Bt,
                                                          const float* __restrict__ bias,
                                                          const float* __restrict__ qw,
                                                          int M, int N) {
    __shared__ __nv_bfloat16 As[128 * 56];
    __shared__ __nv_bfloat16 Bs[128 * 56];
    __shared__ float qws[200];
    int tid = threadIdx.x;
    int w = tid >> 5, lane = tid & 31;
    int wm = w >> 2, wn = w & 3;
    int m0 = blockIdx.y * 128;
    int n0 = blockIdx.x * 128;

    if (MODE == 1 && tid < 200) qws[tid] = qw[tid];

    uint32_t As_u = (uint32_t)__cvta_generic_to_shared(As);
    uint32_t Bs_u = (uint32_t)__cvta_generic_to_shared(Bs);

    float acc[4][4][4];
#pragma unroll
    for (int i = 0; i < 4; ++i)
#pragma unroll
        for (int j = 0; j < 4; ++j)
#pragma unroll
            for (int e = 0; e < 4; ++e) acc[i][j][e] = 0.f;

    uint4 pre[4];
#pragma unroll
    for (int j = 0; j < 4; ++j) {
        int i = tid + j * 256;
        int r = (i >> 2) & 127;
        int kq = i & 3;
        uint4 v = make_uint4(0, 0, 0, 0);
        if (i < 512) {
            int m = m0 + r;
            if (m < M) v = *(const uint4*)(Ag + (size_t)m * 256 + kq * 8);
        } else {
            int nn = n0 + r;
            if (nn < N) v = *(const uint4*)(Bt + (size_t)nn * 256 + kq * 8);
        }
        pre[j] = v;
    }

    for (int kc = 0; kc < 256; kc += 32) {
        __syncthreads();
#pragma unroll
        for (int j = 0; j < 4; ++j) {
            int i = tid + j * 256;
            int r = (i >> 2) & 127;
            int kq = i & 3;
            if (i < 512) *(uint4*)(As + r * 56 + kq * 8) = pre[j];
            else         *(uint4*)(Bs + r * 56 + kq * 8) = pre[j];
        }
        __syncthreads();
        if (kc + 32 < 256) {
            int kn = kc + 32;
#pragma unroll
            for (int j = 0; j < 4; ++j) {
                int i = tid + j * 256;
                int r = (i >> 2) & 127;
                int kq = i & 3;
                uint4 v = make_uint4(0, 0, 0, 0);
                if (i < 512) {
                    int m = m0 + r;
                    if (m < M) v = *(const uint4*)(Ag + (size_t)m * 256 + kn + kq * 8);
                } else {
                    int nn = n0 + r;
                    if (nn < N) v = *(const uint4*)(Bt + (size_t)nn * 256 + kn + kq * 8);
                }
                pre[j] = v;
            }
        }
#pragma unroll
        for (int ks = 0; ks < 2; ++ks) {
            uint32_t a[4][4], b[4][2];
#pragma unroll
            for (int i = 0; i < 4; ++i) {
                uint32_t addr = As_u +
                    (uint32_t)(((wm * 64 + i * 16 + (lane & 15)) * 56 + ks * 16 + (lane >> 4) * 8) * 2);
                asm volatile("ldmatrix.sync.aligned.m8n8.x4.shared.b16 {%0,%1,%2,%3}, [%4];"
                    : "=r"(a[i][0]), "=r"(a[i][1]), "=r"(a[i][2]), "=r"(a[i][3]) : "r"(addr));
            }
#pragma unroll
            for (int j = 0; j < 4; ++j) {
                int nr = wn * 32 + j * 8 + (lane & 7);
                uint32_t addr = Bs_u +
                    (uint32_t)((nr * 56 + ks * 16 + ((lane >> 3) & 1) * 8) * 2);
                asm volatile("ldmatrix.sync.aligned.m8n8.x2.shared.b16 {%0,%1}, [%2];"
                    : "=r"(b[j][0]), "=r"(b[j][1]) : "r"(addr));
            }
#pragma unroll
            for (int i = 0; i < 4; ++i)
#pragma unroll
                for (int j = 0; j < 4; ++j)
                    asm volatile(
                        "mma.sync.aligned.m16n8k16.row.col.f32.bf16.bf16.f32 "
                        "{%0,%1,%2,%3}, {%4,%5,%6,%7}, {%8,%9}, {%0,%1,%2,%3};"
                        : "+f"(acc[i][j][0]), "+f"(acc[i][j][1]),
                          "+f"(acc[i][j][2]), "+f"(acc[i][j][3])
                        : "r"(a[i][0]), "r"(a[i][1]), "r"(a[i][2]), "r"(a[i][3]),
                          "r"(b[j][0]), "r"(b[j][1]));
        }
    }

    int gid = lane >> 2;
    if (MODE == 0) {
#pragma unroll
        for (int i = 0; i < 4; ++i) {
#pragma unroll
            for (int j = 0; j < 4; ++j) {
                int c0 = n0 + wn * 32 + j * 8 + (lane & 3) * 2;
                float b0 = bias[c0], b1 = bias[c0 + 1];
#pragma unroll
                for (int hf = 0; hf < 2; ++hf) {
                    int m = m0 + wm * 64 + i * 16 + gid + hf * 8;
                    if (m >= M) continue;
                    float v0 = acc[i][j][hf * 2 + 0] + b0;
                    float v1 = acc[i][j][hf * 2 + 1] + b1;
                    if (c0 < 4096) {
                        __nv_bfloat162 p = __floats2bfloat162_rn(v0, v1);
                        *(uint32_t*)(g_qb + (size_t)m * 4096 + c0) = *(uint32_t*)&p;
                    } else {
                        *(float2*)(g_xv + (size_t)m * 256 + (c0 - 4096)) =
                            make_float2(v0, v1);
                    }
                }
            }
        }
    } else {
        int t4 = lane & 3;
#pragma unroll
        for (int i = 0; i < 4; ++i) {
#pragma unroll
            for (int hf = 0; hf < 2; ++hf) {
                int m = m0 + wm * 64 + i * 16 + gid + hf * 8;
                float part = 0.f;
#pragma unroll
                for (int j = 0; j < 4; ++j) {
                    int c0 = n0 + wn * 32 + j * 8 + t4 * 2;
                    if (c0 < N)
                        part += tanhf(acc[i][j][hf * 2 + 0] + bias[c0]) * qws[c0];
                    if (c0 + 1 < N)
                        part += tanhf(acc[i][j][hf * 2 + 1] + bias[c0 + 1]) * qws[c0 + 1];
                }
                part += __shfl_xor_sync(0xffffffffu, part, 1);
                part += __shfl_xor_sync(0xffffffffu, part, 2);
                if (t4 == 0 && m < M)
                    g_spart[(size_t)m * 8 + (n0 >> 7) * 4 + wn] = part;
            }
        }
    }
}

// -------- kernel 3: attention; 1 warp = 1 full head, register softmax, P in regs --------
// smem: xb 48*72*2=6912 | qbA 8x6912=55296 | xvTA 8x1792=14336  => 76544 B, 2 CTAs/SM
#define ATTN_SMEM_BYTES 76544

__global__ void __launch_bounds__(256, 2) attn_kernel() {
    extern __shared__ char smc[];
    __nv_bfloat16* xb = (__nv_bfloat16*)smc;
    __nv_bfloat16* qbA = (__nv_bfloat16*)(smc + 6912);
    half* xvTA = (half*)(smc + 6912 + 55296);
    __shared__ int rows[41];

    int n = blockIdx.y;
    int hb = blockIdx.x;
    int tid = threadIdx.x;
    int w = tid >> 5;
    int lane = tid & 31;
    int h = hb * 8 + w;
    int t4 = lane & 3;
    int gid = lane >> 2;

    __nv_bfloat16* qb = qbA + w * 3456;
    half* xvT = xvTA + w * 896;

    uint32_t xb_u = (uint32_t)__cvta_generic_to_shared(xb);
    uint32_t qb_u = (uint32_t)__cvta_generic_to_shared(qb);
    uint32_t xvT_u = (uint32_t)__cvta_generic_to_shared(xvT);

    if (tid < 41) {
        int b = n / 250, rr = n - b * 250;
        int c = rr / 50, hh = rr - c * 50;
        int t = tid, r;
        if (t < 20)       r = (b * 5 + c) * 20 + t;
        else if (t == 20) r = MID_BASE + n;
        else              r = 1600 + (b * 50 + hh) * 20 + (t - 21);
        rows[t] = r;
    }
    __syncthreads();

    // per-warp xvT [d][s] fp16, s padded zero in [41,56)
    for (int i = lane; i < 240; i += 32) {
        int d = i / 15, s = 41 + i % 15;
        xvT[d * 56 + s] = __float2half(0.f);
    }
    for (int i = lane; i < 164; i += 32) {
        int s = i >> 2, dq = (i & 3) * 4;
        float4 v = *(const float4*)(g_xv + (size_t)rows[s] * 256 + h * 16 + dq);
        xvT[(dq + 0) * 56 + s] = __float2half(v.x);
        xvT[(dq + 1) * 56 + s] = __float2half(v.y);
        xvT[(dq + 2) * 56 + s] = __float2half(v.z);
        xvT[(dq + 3) * 56 + s] = __float2half(v.w);
    }

    float acc[3][6][4];
#pragma unroll
    for (int i = 0; i < 3; ++i)
#pragma unroll
        for (int j = 0; j < 6; ++j)
#pragma unroll
            for (int e = 0; e < 4; ++e) acc[i][j][e] = 0.f;

    for (int kc = 0; kc < 256; kc += 64) {
        __syncthreads();
        // x chunk: staged by whole block
        for (int i = tid; i < 328; i += 256) {
            int t = i >> 3, kq = i & 7;
            CP_ASYNC16(xb_u + (uint32_t)(t * 144 + kq * 16),
                       g_xub + (size_t)rows[t] * 256 + kc + kq * 8);
        }
        // q chunk: per warp (own head)
        for (int i = lane; i < 328; i += 32) {
            int t = i >> 3, kq = i & 7;
            CP_ASYNC16(qb_u + (uint32_t)(t * 144 + kq * 16),
                       g_qb + (size_t)rows[t] * 4096 + h * 256 + kc + kq * 8);
        }
        CP_COMMIT();
        CP_WAIT0();
        __syncthreads();
#pragma unroll
        for (int ks = 0; ks < 4; ++ks) {
            uint32_t a[3][4], b[3][4];
#pragma unroll
            for (int i = 0; i < 3; ++i) {
                uint32_t addr = qb_u +
                    (uint32_t)(((i * 16 + (lane & 15)) * 72 + ks * 16 + (lane >> 4) * 8) * 2);
                asm volatile("ldmatrix.sync.aligned.m8n8.x4.shared.b16 {%0,%1,%2,%3}, [%4];"
                    : "=r"(a[i][0]), "=r"(a[i][1]), "=r"(a[i][2]), "=r"(a[i][3]) : "r"(addr));
            }
#pragma unroll
            for (int jj = 0; jj < 3; ++jj) {
                // x4 pair: n-tiles 2jj, 2jj+1
                int nr = jj * 16 + ((lane >> 4) << 3) + (lane & 7);
                int ko = ks * 16 + ((lane >> 3) & 1) * 8;
                uint32_t addr = xb_u + (uint32_t)((nr * 72 + ko) * 2);
                asm volatile("ldmatrix.sync.aligned.m8n8.x4.shared.b16 {%0,%1,%2,%3}, [%4];"
                    : "=r"(b[jj][0]), "=r"(b[jj][1]), "=r"(b[jj][2]), "=r"(b[jj][3]) : "r"(addr));
            }
#pragma unroll
            for (int i = 0; i < 3; ++i)
#pragma unroll
                for (int jj = 0; jj < 3; ++jj) {
                    asm volatile(
                        "mma.sync.aligned.m16n8k16.row.col.f32.bf16.bf16.f32 "
                        "{%0,%1,%2,%3}, {%4,%5,%6,%7}, {%8,%9}, {%0,%1,%2,%3};"
                        : "+f"(acc[i][2 * jj][0]), "+f"(acc[i][2 * jj][1]),
                          "+f"(acc[i][2 * jj][2]), "+f"(acc[i][2 * jj][3])
                        : "r"(a[i][0]), "r"(a[i][1]), "r"(a[i][2]), "r"(a[i][3]),
                          "r"(b[jj][0]), "r"(b[jj][1]));
                    asm volatile(
                        "mma.sync.aligned.m16n8k16.row.col.f32.bf16.bf16.f32 "
                        "{%0,%1,%2,%3}, {%4,%5,%6,%7}, {%8,%9}, {%0,%1,%2,%3};"
                        : "+f"(acc[i][2 * jj + 1][0]), "+f"(acc[i][2 * jj + 1][1]),
                          "+f"(acc[i][2 * jj + 1][2]), "+f"(acc[i][2 * jj + 1][3])
                        : "r"(a[i][0]), "r"(a[i][1]), "r"(a[i][2]), "r"(a[i][3]),
                          "r"(b[jj][2]), "r"(b[jj][3]));
                }
        }
    }

    // register softmax: rows owned per lane quad; reduce over t4 lanes (xor 1,2)
    float sinv0[3], sinv1[3];
#pragma unroll
    for (int i = 0; i < 3; ++i) {
        float mx0 = -1e30f, mx1 = -1e30f;
#pragma unroll
        for (int j = 0; j < 6; ++j) {
            int c0 = j * 8 + t4 * 2;
            if (c0 < 41) { mx0 = fmaxf(mx0, acc[i][j][0]); mx1 = fmaxf(mx1, acc[i][j][2]); }
            if (c0 + 1 < 41) { mx0 = fmaxf(mx0, acc[i][j][1]); mx1 = fmaxf(mx1, acc[i][j][3]); }
        }
        mx0 = fmaxf(mx0, __shfl_xor_sync(0xffffffffu, mx0, 1));
        mx0 = fmaxf(mx0, __shfl_xor_sync(0xffffffffu, mx0, 2));
        mx1 = fmaxf(mx1, __shfl_xor_sync(0xffffffffu, mx1, 1));
        mx1 = fmaxf(mx1, __shfl_xor_sync(0xffffffffu, mx1, 2));
        float s0 = 0.f, s1 = 0.f;
#pragma unroll
        for (int j = 0; j < 6; ++j) {
            int c0 = j * 8 + t4 * 2;
            float e0 = (c0 < 41) ? __expf((acc[i][j][0] - mx0) * SCALE_F) : 0.f;
            float e1 = (c0 + 1 < 41) ? __expf((acc[i][j][1] - mx0) * SCALE_F) : 0.f;
            float e2 = (c0 < 41) ? __expf((acc[i][j][2] - mx1) * SCALE_F) : 0.f;
            float e3 = (c0 + 1 < 41) ? __expf((acc[i][j][3] - mx1) * SCALE_F) : 0.f;
            acc[i][j][0] = e0; acc[i][j][1] = e1; acc[i][j][2] = e2; acc[i][j][3] = e3;
            s0 += e0 + e1; s1 += e2 + e3;
        }
        s0 += __shfl_xor_sync(0xffffffffu, s0, 1);
        s0 += __shfl_xor_sync(0xffffffffu, s0, 2);
        s1 += __shfl_xor_sync(0xffffffffu, s1, 1);
        s1 += __shfl_xor_sync(0xffffffffu, s1, 2);
        sinv0[i] = 1.f / s0;
        sinv1[i] = 1.f / s1;
    }

    // pack P acc -> fp16 A-fragments (acc of n-tile pair (2kt,2kt+1) == A-frag of k-tile kt)
    uint32_t pf[3][3][4];
#pragma unroll
    for (int i = 0; i < 3; ++i)
#pragma unroll
        for (int kt = 0; kt < 3; ++kt) {
            half2 q0 = __floats2half2_rn(acc[i][2 * kt][0], acc[i][2 * kt][1]);
            half2 q1 = __floats2half2_rn(acc[i][2 * kt][2], acc[i][2 * kt][3]);
            half2 q2 = __floats2half2_rn(acc[i][2 * kt + 1][0], acc[i][2 * kt + 1][1]);
            half2 q3 = __floats2half2_rn(acc[i][2 * kt + 1][2], acc[i][2 * kt + 1][3]);
            pf[i][kt][0] = *(uint32_t*)&q0;
            pf[i][kt][1] = *(uint32_t*)&q1;
            pf[i][kt][2] = *(uint32_t*)&q2;
            pf[i][kt][3] = *(uint32_t*)&q3;
        }

    __syncwarp();  // xvT STS (cross-lane) -> LDSM ordering

    // epilogue: out[48x16] = P @ xv ; A from pf, B from xvT
    float oa[3][2][4];
#pragma unroll
    for (int i = 0; i < 3; ++i)
#pragma unroll
        for (int j = 0; j < 2; ++j)
#pragma unroll
            for (int e = 0; e < 4; ++e) oa[i][j][e] = 0.f;
#pragma unroll
    for (int kt = 0; kt < 3; ++kt) {
        uint32_t bf[4];
        int nr = ((lane >> 4) << 3) + (lane & 7);
        int ko = kt * 16 + ((lane >> 3) & 1) * 8;
        uint32_t addr = xvT_u + (uint32_t)((nr * 56 + ko) * 2);
        asm volatile("ldmatrix.sync.aligned.m8n8.x4.shared.b16 {%0,%1,%2,%3}, [%4];"
            : "=r"(bf[0]), "=r"(bf[1]), "=r"(bf[2]), "=r"(bf[3]) : "r"(addr));
#pragma unroll
        for (int i = 0; i < 3; ++i) {
            asm volatile(
                "mma.sync.aligned.m16n8k16.row.col.f32.f16.f16.f32 "
                "{%0,%1,%2,%3}, {%4,%5,%6,%7}, {%8,%9}, {%0,%1,%2,%3};"
                : "+f"(oa[i][0][0]), "+f"(oa[i][0][1]), "+f"(oa[i][0][2]), "+f"(oa[i][0][3])
                : "r"(pf[i][kt][0]), "r"(pf[i][kt][1]), "r"(pf[i][kt][2]), "r"(pf[i][kt][3]),
                  "r"(bf[0]), "r"(bf[1]));
            asm volatile(
                "mma.sync.aligned.m16n8k16.row.col.f32.f16.f16.f32 "
                "{%0,%1,%2,%3}, {%4,%5,%6,%7}, {%8,%9}, {%0,%1,%2,%3};"
                : "+f"(oa[i][1][0]), "+f"(oa[i][1][1]), "+f"(oa[i][1][2]), "+f"(oa[i][1][3])
                : "r"(pf[i][kt][0]), "r"(pf[i][kt][1]), "r"(pf[i][kt][2]), "r"(pf[i][kt][3]),
                  "r"(bf[2]), "r"(bf[3]));
        }
    }
#pragma unroll
    for (int i = 0; i < 3; ++i) {
#pragma unroll
        for (int j = 0; j < 2; ++j) {
            int c0 = j * 8 + t4 * 2;
            int tA = i * 16 + gid;
            if (tA < 41) {
                float v0 = oa[i][j][0] * sinv0[i];
                float v1 = oa[i][j][1] * sinv0[i];
                __nv_bfloat162 pp = __floats2bfloat162_rn(v0, v1);
                *(uint32_t*)(g_valb + ((size_t)n * 41 + tA) * 256 + h * 16 + c0) =
                    *(uint32_t*)&pp;
            }
            int tB = tA + 8;
            if (tB < 41) {
                float v0 = oa[i][j][2] * sinv1[i];
                float v1 = oa[i][j][3] * sinv1[i];
                __nv_bfloat162 pp = __floats2bfloat162_rn(v0, v1);
                *(uint32_t*)(g_valb + ((size_t)n * 41 + tB) * 256 + h * 16 + c0) =
                    *(uint32_t*)&pp;
            }
        }
    }
}

// -------- kernel 5: word attention per sequence (s from g_spart, val bf16) --------
__global__ void __launch_bounds__(256) word_kernel() {
    __shared__ float sl[41];
    int n = blockIdx.x;
    int tid = threadIdx.x;
    if (tid < 41) {
        const float4* sp = (const float4*)(g_spart + (size_t)(n * 41 + tid) * 8);
        float4 a = sp[0], b = sp[1];
        sl[tid] = ((a.x + a.y) + (a.z + a.w) + (b.x + b.y) + (b.z + b.w)) * SCALE_F;
    }
    __syncthreads();
    if (tid < 32) {
        float v0 = (tid < 41) ? sl[tid] : -1e30f;
        float v1 = (tid + 32 < 41) ? sl[tid + 32] : -1e30f;
        float m = fmaxf(v0, v1);
#pragma unroll
        for (int o = 16; o; o >>= 1) m = fmaxf(m, __shfl_xor_sync(0xffffffffu, m, o));
        float e0 = (tid < 41) ? expf(v0 - m) : 0.f;
        float e1 = (tid + 32 < 41) ? expf(v1 - m) : 0.f;
        float s = e0 + e1;
#pragma unroll
        for (int o = 16; o; o >>= 1) s += __shfl_xor_sync(0xffffffffu, s, o);
        float inv = 1.f / s;
        if (tid < 41) sl[tid] = e0 * inv;
        if (tid + 32 < 41) sl[tid + 32] = e1 * inv;
    }
    __syncthreads();
    float acc = 0.f;
    const __nv_bfloat16* vr = g_valb + (size_t)n * 41 * 256 + tid;
#pragma unroll 8
    for (int t = 0; t < 41; ++t)
        acc = fmaf(sl[t], __bfloat162float(vr[(size_t)t * 256]), acc);
    g_rep[(size_t)n * 256 + tid] = acc;
}

// -------- kernel 6: mean over HIS, rank score, log-softmax over CDD --------
__global__ void __launch_bounds__(256) final_kernel(const float* __restrict__ Wl,
                                                    const float* __restrict__ blp,
                                                    float* __restrict__ out) {
    __shared__ float red[8];
    __shared__ float sc[5];
    int b = blockIdx.x;
    int tid = threadIdx.x;
    float wl = Wl[tid];
    for (int c = 0; c < 5; ++c) {
        const float* rp = g_rep + ((size_t)(b * 5 + c) * 50) * 256 + tid;
        float s = 0.f;
        for (int h = 0; h < 50; ++h) s += rp[(size_t)h * 256];
        s *= wl;
#pragma unroll
        for (int o = 16; o; o >>= 1) s += __shfl_xor_sync(0xffffffffu, s, o);
        if ((tid & 31) == 0) red[tid >> 5] = s;
        __syncthreads();
        if (tid < 8) {
            float v = red[tid];
#pragma unroll
            for (int o = 4; o; o >>= 1) v += __shfl_xor_sync(0xffu, v, o, 8);
            if (tid == 0) sc[c] = v * (1.f / 50.f) + blp[0];
        }
        __syncthreads();
    }
    if (tid == 0) {
        float m = sc[0];
        for (int c = 1; c < 5; ++c) m = fmaxf(m, sc[c]);
        float s = 0.f;
        for (int c = 0; c < 5; ++c) s += expf(sc[c] - m);
        float ls = logf(s);
        for (int c = 0; c < 5; ++c) out[b * 5 + c] = sc[c] - m - ls;
    }
}

// -------- host launcher --------
extern "C" void kernel_launch(void* const* d_in, const int* in_sizes, int n_in,
                              void* d_out, int out_size) {
    const int* cand = (const int*)d_in[0];
    const int* clk = (const int*)d_in[1];
    const float* emb = (const float*)d_in[2];
    const float* conv_w = (const float*)d_in[3];
    const float* conv_b = (const float*)d_in[4];
    const float* Wq = (const float*)d_in[5];
    const float* bq = (const float*)d_in[6];
    const float* Wv = (const float*)d_in[7];
    const float* bv = (const float*)d_in[8];
    const float* Wk = (const float*)d_in[9];
    const float* bk = (const float*)d_in[10];
    const float* qw = (const float*)d_in[11];
    const float* Wl = (const float*)d_in[12];
    const float* bl = (const float*)d_in[13];
    float* out = (float*)d_out;

    cudaFuncSetAttribute(attn_kernel, cudaFuncAttributeMaxDynamicSharedMemorySize,
                         ATTN_SMEM_BYTES);

    static const __nv_bfloat16* h_xub = nullptr;
    static const __nv_bfloat16* h_WcatTb = nullptr;
    static const __nv_bfloat16* h_WkTb = nullptr;
    static const __nv_bfloat16* h_valb = nullptr;
    static const float* h_bcat = nullptr;
    if (!h_xub) {
        void* p;
        cudaGetSymbolAddress(&p, g_xub);    h_xub = (const __nv_bfloat16*)p;
        cudaGetSymbolAddress(&p, g_WcatTb); h_WcatTb = (const __nv_bfloat16*)p;
        cudaGetSymbolAddress(&p, g_WkTb);   h_WkTb = (const __nv_bfloat16*)p;
        cudaGetSymbolAddress(&p, g_valb);   h_valb = (const __nv_bfloat16*)p;
        cudaGetSymbolAddress(&p, g_bcat);   h_bcat = (const float*)p;
    }

    prep_kernel<<<4352, 256>>>(Wq, bq, Wv, bv, Wk, conv_w);
    conv_mma_kernel<<<dim3(2, 169), 256>>>(cand, clk, emb, conv_b);
    gemm_mma_kernel<0><<<dim3(34, (NUROWS + 127) / 128), 256>>>(h_xub, h_WcatTb, h_bcat,
                                                                nullptr, NUROWS, 4352);
    attn_kernel<<<dim3(2, NSEQ), 256, ATTN_SMEM_BYTES>>>();
    gemm_mma_kernel<1><<<dim3(2, (MVAL + 127) / 128), 256>>>(h_valb, h_WkTb, bk,
                                                             qw, MVAL, NQD);
    word_kernel<<<NSEQ, 256>>>();
    final_kernel<<<NB, 256>>>(Wl, bl, out);
}

// round 15
// speedup vs baseline: 8.0375x; 1.0727x over previous
#include <cuda_runtime.h>
#include <cuda_bf16.h>
#include <cuda_fp16.h>
#include <math.h>
#include <stdint.h>

#define NB 16
#define NCDD 5
#define NHIS 50
#define NS 20
#define NT 41
#define NE 300
#define NF 256
#define NH 16
#define NDV 16
#define NQD 200
#define NSEQ 4000
#define NUROWS 21600
#define MID_BASE 17600
#define MVAL 164000
#define SCALE_F 0.057735026918962576f
#define CONV_K 928

#define CP_ASYNC16(dst, src) \
    asm volatile("cp.async.cg.shared.global [%0], [%1], 16;" :: "r"(dst), "l"(src))
#define CP_COMMIT() asm volatile("cp.async.commit_group;" ::: "memory")
#define CP_WAIT0() asm volatile("cp.async.wait_group 0;" ::: "memory")

// -------- static device scratch (no allocations) --------
__device__ half g_xub[NUROWS * NF];
__device__ half g_WcatTb[4352 * 256];
__device__ float g_bcat[4352];
__device__ half g_WkTb[200 * 256];
__device__ half g_cwb[256 * CONV_K];
__device__ half g_qb[(size_t)NUROWS * 4096];
__device__ float g_xv[(size_t)NUROWS * 256];
__device__ half g_valb[(size_t)MVAL * NF];
__device__ float g_spart[(size_t)MVAL * 8];
__device__ float g_rep[(size_t)NSEQ * NF];

// -------- kernel 0: pack transposed fp16 weights + bias --------
__global__ void prep_kernel(const float* __restrict__ Wq, const float* __restrict__ bq,
                            const float* __restrict__ Wv, const float* __restrict__ bv,
                            const float* __restrict__ Wk, const float* __restrict__ cw) {
    int idx = blockIdx.x * 256 + threadIdx.x;
    if (idx < 4352 * 256) {
        int nn = idx >> 8, k = idx & 255;
        float w;
        if (nn < 4096) {
            int h = nn >> 8, g = nn & 255;
            w = Wq[(h * 256 + k) * 256 + g];
        } else {
            int jj = nn - 4096;
            int h = jj >> 4, d = jj & 15;
            w = Wv[(h * 256 + k) * 16 + d];
        }
        g_WcatTb[idx] = __float2half(w);
    }
    if (idx < 200 * 256) {
        int nn = idx >> 8, k = idx & 255;
        g_WkTb[idx] = __float2half(Wk[k * 200 + nn]);
    }
    if (idx < 256 * CONV_K) {
        int f = idx / CONV_K, k = idx - f * CONV_K;
        g_cwb[idx] = __float2half(k < 900 ? cw[k * 256 + f] : 0.f);
    }
    if (idx < 4352) {
        if (idx < 4096) {
            int h = idx >> 8, g = idx & 255;
            g_bcat[idx] = bq[h * 256 + g];
        } else {
            g_bcat[idx] = bv[idx - 4096]; // bv folds through softmax (rows sum to 1)
        }
    }
}

// -------- kernel 1: conv as fp16 mma GEMM over im2col rows --------
__global__ void __launch_bounds__(256, 2) conv_mma_kernel(const int* __restrict__ cand,
                                                          const int* __restrict__ clk,
                                                          const float* __restrict__ emb,
                                                          const float* __restrict__ cb) {
    __shared__ half As[128 * 40];
    __shared__ half Bs[128 * 40];
    __shared__ int st[128][3];
    int tid = threadIdx.x;
    int w = tid >> 5, lane = tid & 31;
    int wm = w >> 2, wn = w & 3;
    int m0 = blockIdx.y * 128;
    int n0 = blockIdx.x * 128;

    if (tid < 128) {
        int row = m0 + tid;
        int t0 = -1, t1 = -1, t2 = -1;
        if (row < NUROWS) {
            if (row < 1600) {
                int bc = row / 20, t = row - bc * 20;
                const int* ct = cand + bc * 20;
                t0 = (t - 1 >= 0) ? ct[t - 1] : -1;
                t1 = ct[t];
                t2 = (t + 1 < 20) ? ct[t + 1] : 1;
            } else if (row < MID_BASE) {
                int r2 = row - 1600;
                int bh = r2 / 20, tt = r2 - bh * 20;
                const int* ht = clk + bh * 20;
                t0 = (tt == 0) ? 1 : ht[tt - 1];
                t1 = ht[tt];
                t2 = (tt + 1 < 20) ? ht[tt + 1] : -1;
            } else {
                int nn = row - MID_BASE;
                int b = nn / 250, rr = nn - b * 250;
                int c = rr / 50, hh = rr - c * 50;
                t0 = cand[(b * 5 + c) * 20 + 19];
                t1 = 1;
                t2 = clk[(b * 50 + hh) * 20 + 0];
            }
        }
        st[tid][0] = t0; st[tid][1] = t1; st[tid][2] = t2;
    }

    uint32_t As_u = (uint32_t)__cvta_generic_to_shared(As);
    uint32_t Bs_u = (uint32_t)__cvta_generic_to_shared(Bs);

    float acc[4][4][4];
#pragma unroll
    for (int i = 0; i < 4; ++i)
#pragma unroll
        for (int j = 0; j < 4; ++j)
#pragma unroll
            for (int e = 0; e < 4; ++e) acc[i][j][e] = 0.f;

    for (int kc = 0; kc < CONV_K; kc += 32) {
        __syncthreads();
#pragma unroll
        for (int j = 0; j < 4; ++j) {
            int i = tid + j * 256;
            int r = i >> 3, q = i & 7;
            int k0 = kc + q * 4;
            uint2 u = make_uint2(0, 0);
            if (k0 < 900) {
                int tap = k0 / 300;
                int e0 = k0 - tap * 300;
                int tok = st[r][tap];
                if (tok >= 0) {
                    float4 v = *(const float4*)(emb + (size_t)tok * 300 + e0);
                    __half2 p0 = __floats2half2_rn(v.x, v.y);
                    __half2 p1 = __floats2half2_rn(v.z, v.w);
                    u.x = *(uint32_t*)&p0;
                    u.y = *(uint32_t*)&p1;
                }
            }
            *(uint2*)(As + r * 40 + q * 4) = u;
        }
#pragma unroll
        for (int j = 0; j < 2; ++j) {
            int i = tid + j * 256;
            int r = i >> 2, kq = i & 3;
            *(uint4*)(Bs + r * 40 + kq * 8) =
                *(const uint4*)(g_cwb + (size_t)(n0 + r) * CONV_K + kc + kq * 8);
        }
        __syncthreads();
#pragma unroll
        for (int ks = 0; ks < 2; ++ks) {
            uint32_t a[4][4], b[4][2];
#pragma unroll
            for (int i = 0; i < 4; ++i) {
                uint32_t addr = As_u +
                    (uint32_t)(((wm * 64 + i * 16 + (lane & 15)) * 40 + ks * 16 + (lane >> 4) * 8) * 2);
                asm volatile("ldmatrix.sync.aligned.m8n8.x4.shared.b16 {%0,%1,%2,%3}, [%4];"
                    : "=r"(a[i][0]), "=r"(a[i][1]), "=r"(a[i][2]), "=r"(a[i][3]) : "r"(addr));
            }
#pragma unroll
            for (int j = 0; j < 4; ++j) {
                int nr = wn * 32 + j * 8 + (lane & 7);
                uint32_t addr = Bs_u +
                    (uint32_t)((nr * 40 + ks * 16 + ((lane >> 3) & 1) * 8) * 2);
                asm volatile("ldmatrix.sync.aligned.m8n8.x2.shared.b16 {%0,%1}, [%2];"
                    : "=r"(b[j][0]), "=r"(b[j][1]) : "r"(addr));
            }
#pragma unroll
            for (int i = 0; i < 4; ++i)
#pragma unroll
                for (int j = 0; j < 4; ++j)
                    asm volatile(
                        "mma.sync.aligned.m16n8k16.row.col.f32.f16.f16.f32 "
                        "{%0,%1,%2,%3}, {%4,%5,%6,%7}, {%8,%9}, {%0,%1,%2,%3};"
                        : "+f"(acc[i][j][0]), "+f"(acc[i][j][1]),
                          "+f"(acc[i][j][2]), "+f"(acc[i][j][3])
                        : "r"(a[i][0]), "r"(a[i][1]), "r"(a[i][2]), "r"(a[i][3]),
                          "r"(b[j][0]), "r"(b[j][1]));
        }
    }

    int gid = lane >> 2;
#pragma unroll
    for (int i = 0; i < 4; ++i) {
#pragma unroll
        for (int j = 0; j < 4; ++j) {
            int c0 = n0 + wn * 32 + j * 8 + (lane & 3) * 2;
            float b0 = cb[c0], b1 = cb[c0 + 1];
#pragma unroll
            for (int hf = 0; hf < 2; ++hf) {
                int m = m0 + wm * 64 + i * 16 + gid + hf * 8;
                if (m >= NUROWS) continue;
                float v0 = fmaxf(acc[i][j][hf * 2 + 0] + b0, 0.f);
                float v1 = fmaxf(acc[i][j][hf * 2 + 1] + b1, 0.f);
                __half2 p = __floats2half2_rn(v0, v1);
                *(uint32_t*)(g_xub + (size_t)m * 256 + c0) = *(uint32_t*)&p;
            }
        }
    }
}

// -------- fp16 tensor-core GEMM, K=256, register-prefetch double buffered --------
// MODE 0: n<4096 -> g_qb fp16; n>=4096 -> g_xv fp32.
// MODE 1: fused word-k partials -> g_spart.
template <int MODE>
__global__ void __launch_bounds__(256, 2) gemm_mma_kernel(const half* __restrict__ Ag,
                                                          const half* __restrict__ Bt,
                                                          const float* __restrict__ bias,
                                                          const float* __restrict__ qw,
                                                          int M, int N) {
    __shared__ half As[128 * 56];
    __shared__ half Bs[128 * 56];
    __shared__ float qws[200];
    int tid = threadIdx.x;
    int w = tid >> 5, lane = tid & 31;
    int wm = w >> 2, wn = w & 3;
    int m0 = blockIdx.y * 128;
    int n0 = blockIdx.x * 128;

    if (MODE == 1 && tid < 200) qws[tid] = qw[tid];

    uint32_t As_u = (uint32_t)__cvta_generic_to_shared(As);
    uint32_t Bs_u = (uint32_t)__cvta_generic_to_shared(Bs);

    float acc[4][4][4];
#pragma unroll
    for (int i = 0; i < 4; ++i)
#pragma unroll
        for (int j = 0; j < 4; ++j)
#pragma unroll
            for (int e = 0; e < 4; ++e) acc[i][j][e] = 0.f;

    uint4 pre[4];
#pragma unroll
    for (int j = 0; j < 4; ++j) {
        int i = tid + j * 256;
        int r = (i >> 2) & 127;
        int kq = i & 3;
        uint4 v = make_uint4(0, 0, 0, 0);
        if (i < 512) {
            int m = m0 + r;
            if (m < M) v = *(const uint4*)(Ag + (size_t)m * 256 + kq * 8);
        } else {
            int nn = n0 + r;
            if (nn < N) v = *(const uint4*)(Bt + (size_t)nn * 256 + kq * 8);
        }
        pre[j] = v;
    }

    for (int kc = 0; kc < 256; kc += 32) {
        __syncthreads();
#pragma unroll
        for (int j = 0; j < 4; ++j) {
            int i = tid + j * 256;
            int r = (i >> 2) & 127;
            int kq = i & 3;
            if (i < 512) *(uint4*)(As + r * 56 + kq * 8) = pre[j];
            else         *(uint4*)(Bs + r * 56 + kq * 8) = pre[j];
        }
        __syncthreads();
        if (kc + 32 < 256) {
            int kn = kc + 32;
#pragma unroll
            for (int j = 0; j < 4; ++j) {
                int i = tid + j * 256;
                int r = (i >> 2) & 127;
                int kq = i & 3;
                uint4 v = make_uint4(0, 0, 0, 0);
                if (i < 512) {
                    int m = m0 + r;
                    if (m < M) v = *(const uint4*)(Ag + (size_t)m * 256 + kn + kq * 8);
                } else {
                    int nn = n0 + r;
                    if (nn < N) v = *(const uint4*)(Bt + (size_t)nn * 256 + kn + kq * 8);
                }
                pre[j] = v;
            }
        }
#pragma unroll
        for (int ks = 0; ks < 2; ++ks) {
            uint32_t a[4][4], b[4][2];
#pragma unroll
            for (int i = 0; i < 4; ++i) {
                uint32_t addr = As_u +
                    (uint32_t)(((wm * 64 + i * 16 + (lane & 15)) * 56 + ks * 16 + (lane >> 4) * 8) * 2);
                asm volatile("ldmatrix.sync.aligned.m8n8.x4.shared.b16 {%0,%1,%2,%3}, [%4];"
                    : "=r"(a[i][0]), "=r"(a[i][1]), "=r"(a[i][2]), "=r"(a[i][3]) : "r"(addr));
            }
#pragma unroll
            for (int j = 0; j < 4; ++j) {
                int nr = wn * 32 + j * 8 + (lane & 7);
                uint32_t addr = Bs_u +
                    (uint32_t)((nr * 56 + ks * 16 + ((lane >> 3) & 1) * 8) * 2);
                asm volatile("ldmatrix.sync.aligned.m8n8.x2.shared.b16 {%0,%1}, [%2];"
                    : "=r"(b[j][0]), "=r"(b[j][1]) : "r"(addr));
            }
#pragma unroll
            for (int i = 0; i < 4; ++i)
#pragma unroll
                for (int j = 0; j < 4; ++j)
                    asm volatile(
                        "mma.sync.aligned.m16n8k16.row.col.f32.f16.f16.f32 "
                        "{%0,%1,%2,%3}, {%4,%5,%6,%7}, {%8,%9}, {%0,%1,%2,%3};"
                        : "+f"(acc[i][j][0]), "+f"(acc[i][j][1]),
                          "+f"(acc[i][j][2]), "+f"(acc[i][j][3])
                        : "r"(a[i][0]), "r"(a[i][1]), "r"(a[i][2]), "r"(a[i][3]),
                          "r"(b[j][0]), "r"(b[j][1]));
        }
    }

    int gid = lane >> 2;
    if (MODE == 0) {
#pragma unroll
        for (int i = 0; i < 4; ++i) {
#pragma unroll
            for (int j = 0; j < 4; ++j) {
                int c0 = n0 + wn * 32 + j * 8 + (lane & 3) * 2;
                float b0 = bias[c0], b1 = bias[c0 + 1];
#pragma unroll
                for (int hf = 0; hf < 2; ++hf) {
                    int m = m0 + wm * 64 + i * 16 + gid + hf * 8;
                    if (m >= M) continue;
                    float v0 = acc[i][j][hf * 2 + 0] + b0;
                    float v1 = acc[i][j][hf * 2 + 1] + b1;
                    if (c0 < 4096) {
                        __half2 p = __floats2half2_rn(v0, v1);
                        *(uint32_t*)(g_qb + (size_t)m * 4096 + c0) = *(uint32_t*)&p;
                    } else {
                        *(float2*)(g_xv + (size_t)m * 256 + (c0 - 4096)) =
                            make_float2(v0, v1);
                    }
                }
            }
        }
    } else {
        int t4 = lane & 3;
#pragma unroll
        for (int i = 0; i < 4; ++i) {
#pragma unroll
            for (int hf = 0; hf < 2; ++hf) {
                int m = m0 + wm * 64 + i * 16 + gid + hf * 8;
                float part = 0.f;
#pragma unroll
                for (int j = 0; j < 4; ++j) {
                    int c0 = n0 + wn * 32 + j * 8 + t4 * 2;
                    if (c0 < N)
                        part += tanhf(acc[i][j][hf * 2 + 0] + bias[c0]) * qws[c0];
                    if (c0 + 1 < N)
                        part += tanhf(acc[i][j][hf * 2 + 1] + bias[c0 + 1]) * qws[c0 + 1];
                }
                part += __shfl_xor_sync(0xffffffffu, part, 1);
                part += __shfl_xor_sync(0xffffffffu, part, 2);
                if (t4 == 0 && m < M)
                    g_spart[(size_t)m * 8 + (n0 >> 7) * 4 + wn] = part;
            }
        }
    }
}

// -------- kernel 3: attention; 1 warp = 1 head, fp16-acc scores, in-place softmax --------
// smem: xb 48*72*2=6912 | qbA 8x6912=55296 | xvTA 8x1792=14336  => 76544 B
#define ATTN_SMEM_BYTES 76544

__global__ void __launch_bounds__(256, 3) attn_kernel() {
    extern __shared__ char smc[];
    half* xb = (half*)smc;
    half* qbA = (half*)(smc + 6912);
    half* xvTA = (half*)(smc + 6912 + 55296);
    __shared__ int rows[41];

    int n = blockIdx.y;
    int hb = blockIdx.x;
    int tid = threadIdx.x;
    int w = tid >> 5;
    int lane = tid & 31;
    int h = hb * 8 + w;
    int t4 = lane & 3;
    int gid = lane >> 2;

    half* qb = qbA + w * 3456;
    half* xvT = xvTA + w * 896;

    uint32_t xb_u = (uint32_t)__cvta_generic_to_shared(xb);
    uint32_t qb_u = (uint32_t)__cvta_generic_to_shared(qb);
    uint32_t xvT_u = (uint32_t)__cvta_generic_to_shared(xvT);

    if (tid < 41) {
        int b = n / 250, rr = n - b * 250;
        int c = rr / 50, hh = rr - c * 50;
        int t = tid, r;
        if (t < 20)       r = (b * 5 + c) * 20 + t;
        else if (t == 20) r = MID_BASE + n;
        else              r = 1600 + (b * 50 + hh) * 20 + (t - 21);
        rows[t] = r;
    }
    __syncthreads();

    // per-warp xvT [d][s] fp16, s padded zero in [41,56)
    for (int i = lane; i < 240; i += 32) {
        int d = i / 15, s = 41 + i % 15;
        xvT[d * 56 + s] = __float2half(0.f);
    }
    for (int i = lane; i < 164; i += 32) {
        int s = i >> 2, dq = (i & 3) * 4;
        float4 v = *(const float4*)(g_xv + (size_t)rows[s] * 256 + h * 16 + dq);
        xvT[(dq + 0) * 56 + s] = __float2half(v.x);
        xvT[(dq + 1) * 56 + s] = __float2half(v.y);
        xvT[(dq + 2) * 56 + s] = __float2half(v.z);
        xvT[(dq + 3) * 56 + s] = __float2half(v.w);
    }

    // fp16 accumulators: acc[i][j][0] = rows gid {c0,c1}; [1] = rows gid+8
    uint32_t acc[3][6][2];
#pragma unroll
    for (int i = 0; i < 3; ++i)
#pragma unroll
        for (int j = 0; j < 6; ++j) { acc[i][j][0] = 0u; acc[i][j][1] = 0u; }

    for (int kc = 0; kc < 256; kc += 64) {
        __syncthreads();
        for (int i = tid; i < 328; i += 256) {
            int t = i >> 3, kq = i & 7;
            CP_ASYNC16(xb_u + (uint32_t)(t * 144 + kq * 16),
                       g_xub + (size_t)rows[t] * 256 + kc + kq * 8);
        }
        for (int i = lane; i < 328; i += 32) {
            int t = i >> 3, kq = i & 7;
            CP_ASYNC16(qb_u + (uint32_t)(t * 144 + kq * 16),
                       g_qb + (size_t)rows[t] * 4096 + h * 256 + kc + kq * 8);
        }
        CP_COMMIT();
        CP_WAIT0();
        __syncthreads();
#pragma unroll
        for (int ks = 0; ks < 4; ++ks) {
            uint32_t a[3][4], b[3][4];
#pragma unroll
            for (int i = 0; i < 3; ++i) {
                uint32_t addr = qb_u +
                    (uint32_t)(((i * 16 + (lane & 15)) * 72 + ks * 16 + (lane >> 4) * 8) * 2);
                asm volatile("ldmatrix.sync.aligned.m8n8.x4.shared.b16 {%0,%1,%2,%3}, [%4];"
                    : "=r"(a[i][0]), "=r"(a[i][1]), "=r"(a[i][2]), "=r"(a[i][3]) : "r"(addr));
            }
#pragma unroll
            for (int jj = 0; jj < 3; ++jj) {
                int nr = jj * 16 + ((lane >> 4) << 3) + (lane & 7);
                int ko = ks * 16 + ((lane >> 3) & 1) * 8;
                uint32_t addr = xb_u + (uint32_t)((nr * 72 + ko) * 2);
                asm volatile("ldmatrix.sync.aligned.m8n8.x4.shared.b16 {%0,%1,%2,%3}, [%4];"
                    : "=r"(b[jj][0]), "=r"(b[jj][1]), "=r"(b[jj][2]), "=r"(b[jj][3]) : "r"(addr));
            }
#pragma unroll
            for (int i = 0; i < 3; ++i)
#pragma unroll
                for (int jj = 0; jj < 3; ++jj) {
                    asm volatile(
                        "mma.sync.aligned.m16n8k16.row.col.f16.f16.f16.f16 "
                        "{%0,%1}, {%2,%3,%4,%5}, {%6,%7}, {%0,%1};"
                        : "+r"(acc[i][2 * jj][0]), "+r"(acc[i][2 * jj][1])
                        : "r"(a[i][0]), "r"(a[i][1]), "r"(a[i][2]), "r"(a[i][3]),
                          "r"(b[jj][0]), "r"(b[jj][1]));
                    asm volatile(
                        "mma.sync.aligned.m16n8k16.row.col.f16.f16.f16.f16 "
                        "{%0,%1}, {%2,%3,%4,%5}, {%6,%7}, {%0,%1};"
                        : "+r"(acc[i][2 * jj + 1][0]), "+r"(acc[i][2 * jj + 1][1])
                        : "r"(a[i][0]), "r"(a[i][1]), "r"(a[i][2]), "r"(a[i][3]),
                          "r"(b[jj][2]), "r"(b[jj][3]));
                }
        }
    }

    // register softmax (rows gid / gid+8 per tile); exp applied IN-PLACE (acc -> fp16 P)
    float sinv0[3], sinv1[3];
#pragma unroll
    for (int i = 0; i < 3; ++i) {
        float mx0 = -1e30f, mx1 = -1e30f;
#pragma unroll
        for (int j = 0; j < 6; ++j) {
            int c0 = j * 8 + t4 * 2;
            float2 f0 = __half22float2(*(__half2*)&acc[i][j][0]);
            float2 f1 = __half22float2(*(__half2*)&acc[i][j][1]);
            if (c0 < 41) { mx0 = fmaxf(mx0, f0.x); mx1 = fmaxf(mx1, f1.x); }
            if (c0 + 1 < 41) { mx0 = fmaxf(mx0, f0.y); mx1 = fmaxf(mx1, f1.y); }
        }
        mx0 = fmaxf(mx0, __shfl_xor_sync(0xffffffffu, mx0, 1));
        mx0 = fmaxf(mx0, __shfl_xor_sync(0xffffffffu, mx0, 2));
        mx1 = fmaxf(mx1, __shfl_xor_sync(0xffffffffu, mx1, 1));
        mx1 = fmaxf(mx1, __shfl_xor_sync(0xffffffffu, mx1, 2));
        float s0 = 0.f, s1 = 0.f;
#pragma unroll
        for (int j = 0; j < 6; ++j) {
            int c0 = j * 8 + t4 * 2;
            float2 f0 = __half22float2(*(__half2*)&acc[i][j][0]);
            float2 f1 = __half22float2(*(__half2*)&acc[i][j][1]);
            float e00 = (c0 < 41) ? __expf((f0.x - mx0) * SCALE_F) : 0.f;
            float e01 = (c0 + 1 < 41) ? __expf((f0.y - mx0) * SCALE_F) : 0.f;
            float e10 = (c0 < 41) ? __expf((f1.x - mx1) * SCALE_F) : 0.f;
            float e11 = (c0 + 1 < 41) ? __expf((f1.y - mx1) * SCALE_F) : 0.f;
            s0 += e00 + e01; s1 += e10 + e11;
            __half2 h0 = __floats2half2_rn(e00, e01);
            __half2 h1 = __floats2half2_rn(e10, e11);
            acc[i][j][0] = *(uint32_t*)&h0;
            acc[i][j][1] = *(uint32_t*)&h1;
        }
        s0 += __shfl_xor_sync(0xffffffffu, s0, 1);
        s0 += __shfl_xor_sync(0xffffffffu, s0, 2);
        s1 += __shfl_xor_sync(0xffffffffu, s1, 1);
        s1 += __shfl_xor_sync(0xffffffffu, s1, 2);
        sinv0[i] = 1.f / s0;
        sinv1[i] = 1.f / s1;
    }

    __syncwarp();  // xvT STS (cross-lane) -> LDSM ordering

    // epilogue: out[48x16] = P @ xv ; A-frag k-tile kt = {acc[2kt][0],acc[2kt][1],acc[2kt+1][0],acc[2kt+1][1]}
    float oa[3][2][4];
#pragma unroll
    for (int i = 0; i < 3; ++i)
#pragma unroll
        for (int j = 0; j < 2; ++j)
#pragma unroll
            for (int e = 0; e < 4; ++e) oa[i][j][e] = 0.f;
#pragma unroll
    for (int kt = 0; kt < 3; ++kt) {
        uint32_t bf[4];
        int nr = ((lane >> 4) << 3) + (lane & 7);
        int ko = kt * 16 + ((lane >> 3) & 1) * 8;
        uint32_t addr = xvT_u + (uint32_t)((nr * 56 + ko) * 2);
        asm volatile("ldmatrix.sync.aligned.m8n8.x4.shared.b16 {%0,%1,%2,%3}, [%4];"
            : "=r"(bf[0]), "=r"(bf[1]), "=r"(bf[2]), "=r"(bf[3]) : "r"(addr));
#pragma unroll
        for (int i = 0; i < 3; ++i) {
            asm volatile(
                "mma.sync.aligned.m16n8k16.row.col.f32.f16.f16.f32 "
                "{%0,%1,%2,%3}, {%4,%5,%6,%7}, {%8,%9}, {%0,%1,%2,%3};"
                : "+f"(oa[i][0][0]), "+f"(oa[i][0][1]), "+f"(oa[i][0][2]), "+f"(oa[i][0][3])
                : "r"(acc[i][2 * kt][0]), "r"(acc[i][2 * kt][1]),
                  "r"(acc[i][2 * kt + 1][0]), "r"(acc[i][2 * kt + 1][1]),
                  "r"(bf[0]), "r"(bf[1]));
            asm volatile(
                "mma.sync.aligned.m16n8k16.row.col.f32.f16.f16.f32 "
                "{%0,%1,%2,%3}, {%4,%5,%6,%7}, {%8,%9}, {%0,%1,%2,%3};"
                : "+f"(oa[i][1][0]), "+f"(oa[i][1][1]), "+f"(oa[i][1][2]), "+f"(oa[i][1][3])
                : "r"(acc[i][2 * kt][0]), "r"(acc[i][2 * kt][1]),
                  "r"(acc[i][2 * kt + 1][0]), "r"(acc[i][2 * kt + 1][1]),
                  "r"(bf[2]), "r"(bf[3]));
        }
    }
#pragma unroll
    for (int i = 0; i < 3; ++i) {
#pragma unroll
        for (int j = 0; j < 2; ++j) {
            int c0 = j * 8 + t4 * 2;
            int tA = i * 16 + gid;
            if (tA < 41) {
                float v0 = oa[i][j][0] * sinv0[i];
                float v1 = oa[i][j][1] * sinv0[i];
                __half2 pp = __floats2half2_rn(v0, v1);
                *(uint32_t*)(g_valb + ((size_t)n * 41 + tA) * 256 + h * 16 + c0) =
                    *(uint32_t*)&pp;
            }
            int tB = tA + 8;
            if (tB < 41) {
                float v0 = oa[i][j][2] * sinv1[i];
                float v1 = oa[i][j][3] * sinv1[i];
                __half2 pp = __floats2half2_rn(v0, v1);
                *(uint32_t*)(g_valb + ((size_t)n * 41 + tB) * 256 + h * 16 + c0) =
                    *(uint32_t*)&pp;
            }
        }
    }
}

// -------- kernel 5: word attention per sequence (s from g_spart, val fp16) --------
__global__ void __launch_bounds__(256) word_kernel() {
    __shared__ float sl[41];
    int n = blockIdx.x;
    int tid = threadIdx.x;
    if (tid < 41) {
        const float4* sp = (const float4*)(g_spart + (size_t)(n * 41 + tid) * 8);
        float4 a = sp[0], b = sp[1];
        sl[tid] = ((a.x + a.y) + (a.z + a.w) + (b.x + b.y) + (b.z + b.w)) * SCALE_F;
    }
    __syncthreads();
    if (tid < 32) {
        float v0 = (tid < 41) ? sl[tid] : -1e30f;
        float v1 = (tid + 32 < 41) ? sl[tid + 32] : -1e30f;
        float m = fmaxf(v0, v1);
#pragma unroll
        for (int o = 16; o; o >>= 1) m = fmaxf(m, __shfl_xor_sync(0xffffffffu, m, o));
        float e0 = (tid < 41) ? expf(v0 - m) : 0.f;
        float e1 = (tid + 32 < 41) ? expf(v1 - m) : 0.f;
        float s = e0 + e1;
#pragma unroll
        for (int o = 16; o; o >>= 1) s += __shfl_xor_sync(0xffffffffu, s, o);
        float inv = 1.f / s;
        if (tid < 41) sl[tid] = e0 * inv;
        if (tid + 32 < 41) sl[tid + 32] = e1 * inv;
    }
    __syncthreads();
    float acc = 0.f;
    const half* vr = g_valb + (size_t)n * 41 * 256 + tid;
#pragma unroll 8
    for (int t = 0; t < 41; ++t)
        acc = fmaf(sl[t], __half2float(vr[(size_t)t * 256]), acc);
    g_rep[(size_t)n * 256 + tid] = acc;
}

// -------- kernel 6: mean over HIS, rank score, log-softmax over CDD --------
__global__ void __launch_bounds__(256) final_kernel(const float* __restrict__ Wl,
                                                    const float* __restrict__ blp,
                                                    float* __restrict__ out) {
    __shared__ float red[8];
    __shared__ float sc[5];
    int b = blockIdx.x;
    int tid = threadIdx.x;
    float wl = Wl[tid];
    for (int c = 0; c < 5; ++c) {
        const float* rp = g_rep + ((size_t)(b * 5 + c) * 50) * 256 + tid;
        float s = 0.f;
        for (int h = 0; h < 50; ++h) s += rp[(size_t)h * 256];
        s *= wl;
#pragma unroll
        for (int o = 16; o; o >>= 1) s += __shfl_xor_sync(0xffffffffu, s, o);
        if ((tid & 31) == 0) red[tid >> 5] = s;
        __syncthreads();
        if (tid < 8) {
            float v = red[tid];
#pragma unroll
            for (int o = 4; o; o >>= 1) v += __shfl_xor_sync(0xffu, v, o, 8);
            if (tid == 0) sc[c] = v * (1.f / 50.f) + blp[0];
        }
        __syncthreads();
    }
    if (tid == 0) {
        float m = sc[0];
        for (int c = 1; c < 5; ++c) m = fmaxf(m, sc[c]);
        float s = 0.f;
        for (int c = 0; c < 5; ++c) s += expf(sc[c] - m);
        float ls = logf(s);
        for (int c = 0; c < 5; ++c) out[b * 5 + c] = sc[c] - m - ls;
    }
}

// -------- host launcher --------
extern "C" void kernel_launch(void* const* d_in, const int* in_sizes, int n_in,
                              void* d_out, int out_size) {
    const int* cand = (const int*)d_in[0];
    const int* clk = (const int*)d_in[1];
    const float* emb = (const float*)d_in[2];
    const float* conv_w = (const float*)d_in[3];
    const float* conv_b = (const float*)d_in[4];
    const float* Wq = (const float*)d_in[5];
    const float* bq = (const float*)d_in[6];
    const float* Wv = (const float*)d_in[7];
    const float* bv = (const float*)d_in[8];
    const float* Wk = (const float*)d_in[9];
    const float* bk = (const float*)d_in[10];
    const float* qw = (const float*)d_in[11];
    const float* Wl = (const float*)d_in[12];
    const float* bl = (const float*)d_in[13];
    float* out = (float*)d_out;

    cudaFuncSetAttribute(attn_kernel, cudaFuncAttributeMaxDynamicSharedMemorySize,
                         ATTN_SMEM_BYTES);

    static const half* h_xub = nullptr;
    static const half* h_WcatTb = nullptr;
    static const half* h_WkTb = nullptr;
    static const half* h_valb = nullptr;
    static const float* h_bcat = nullptr;
    if (!h_xub) {
        void* p;
        cudaGetSymbolAddress(&p, g_xub);    h_xub = (const half*)p;
        cudaGetSymbolAddress(&p, g_WcatTb); h_WcatTb = (const half*)p;
        cudaGetSymbolAddress(&p, g_WkTb);   h_WkTb = (const half*)p;
        cudaGetSymbolAddress(&p, g_valb);   h_valb = (const half*)p;
        cudaGetSymbolAddress(&p, g_bcat);   h_bcat = (const float*)p;
    }

    prep_kernel<<<4352, 256>>>(Wq, bq, Wv, bv, Wk, conv_w);
    conv_mma_kernel<<<dim3(2, 169), 256>>>(cand, clk, emb, conv_b);
    gemm_mma_kernel<0><<<dim3(34, (NUROWS + 127) / 128), 256>>>(h_xub, h_WcatTb, h_bcat,
                                                                nullptr, NUROWS, 4352);
    attn_kernel<<<dim3(2, NSEQ), 256, ATTN_SMEM_BYTES>>>();
    gemm_mma_kernel<1><<<dim3(2, (MVAL + 127) / 128), 256>>>(h_valb, h_WkTb, bk,
                                                             qw, MVAL, NQD);
    word_kernel<<<NSEQ, 256>>>();
    final_kernel<<<NB, 256>>>(Wl, bl, out);
}